// round 4
// baseline (speedup 1.0000x reference)
#include <cuda_runtime.h>
#include <math.h>

// Fixed problem shapes
#define NNODES 50000
#define D0 3000
#define D1 256
#define D2 128
#define D3 64

// Static scratch (allocation-free rule). Device-code access only.
__device__ float s_bufA[NNODES * D1];   // 51.2 MB
__device__ float s_bufB[NNODES * D1];   // 51.2 MB
__device__ float s_bufC[NNODES * D2];   // 25.6 MB
__device__ int   s_deg[NNODES];
__device__ float s_dis[NNODES];
__device__ int   s_is64;                // 1 if edge_index is int64, 0 if int32

// Compile-time scratch selector.
template <int ID>
__device__ __forceinline__ float* scratch() {
    if constexpr (ID == 0) return s_bufA;
    else if constexpr (ID == 1) return s_bufB;
    else return s_bufC;
}

// Edge index accessor, dtype-adaptive.
__device__ __forceinline__ int edge_at(const void* ei, long long idx, int is64) {
    if (is64) return (int)((const long long*)ei)[idx];
    return ((const int*)ei)[idx];
}

// ---------------------------------------------------------------------------
// Dtype detection: int64 little-endian values < 2^31 have zero odd int32
// words; int32 node-id data has random nonzero odd words.
// ---------------------------------------------------------------------------
__global__ void k_detect_dtype(const int* __restrict__ ei_words, int nwords)
{
    __shared__ int found_nonzero;
    if (threadIdx.x == 0) found_nonzero = 0;
    __syncthreads();
    for (int w = 1 + 2 * threadIdx.x; w < nwords; w += 2 * blockDim.x) {
        if (ei_words[w] != 0) { found_nonzero = 1; break; }
    }
    __syncthreads();
    if (threadIdx.x == 0) s_is64 = found_nonzero ? 0 : 1;
}

// ---------------------------------------------------------------------------
// Degree / normalization
// ---------------------------------------------------------------------------
__global__ void k_deg_zero(int n) {
    int i = blockIdx.x * blockDim.x + threadIdx.x;
    if (i < n) s_deg[i] = 0;
}

__global__ void k_deg_count(const void* __restrict__ ei, int E) {
    int e = blockIdx.x * blockDim.x + threadIdx.x;
    if (e < E) {
        int is64 = s_is64;
        int d = edge_at(ei, (long long)E + e, is64);   // dst row
        if ((unsigned)d < (unsigned)NNODES) atomicAdd(&s_deg[d], 1);
    }
}

__global__ void k_dis(int n) {
    int i = blockIdx.x * blockDim.x + threadIdx.x;
    if (i < n) s_dis[i] = rsqrtf((float)s_deg[i] + 1.0f);
}

// ---------------------------------------------------------------------------
// FP32 SIMT GEMM: C[M,N] = A[M,K] @ B[K,N].
// 128x128 tile, BK=8, 256 threads, 8x8 per thread. AID=-1 -> external A.
// ---------------------------------------------------------------------------
#define TM 128
#define TN 128
#define TKK 8

template <int AID, int CID>
__global__ __launch_bounds__(256) void k_gemm(
    const float* __restrict__ Aext, const float* __restrict__ B,
    int M, int N, int K)
{
    const float* A;
    if constexpr (AID < 0) A = Aext; else A = scratch<AID>();
    float* C = scratch<CID>();

    __shared__ float As[TKK][TM];
    __shared__ float Bs[TKK][TN];

    const int tid = threadIdx.x;
    const int m0 = blockIdx.y * TM;
    const int n0 = blockIdx.x * TN;
    const int ty = tid >> 4;
    const int tx = tid & 15;

    const int a_row = tid >> 1;
    const int a_k   = (tid & 1) * 4;
    const int b_k   = tid >> 5;
    const int b_n   = (tid & 31) * 4;

    float acc[8][8];
#pragma unroll
    for (int i = 0; i < 8; i++)
#pragma unroll
        for (int j = 0; j < 8; j++) acc[i][j] = 0.0f;

    for (int k0 = 0; k0 < K; k0 += TKK) {
        float4 av = make_float4(0.f, 0.f, 0.f, 0.f);
        int gm = m0 + a_row;
        if (gm < M)
            av = *reinterpret_cast<const float4*>(A + (size_t)gm * K + (k0 + a_k));
        As[a_k + 0][a_row] = av.x;
        As[a_k + 1][a_row] = av.y;
        As[a_k + 2][a_row] = av.z;
        As[a_k + 3][a_row] = av.w;

        float4 bv = make_float4(0.f, 0.f, 0.f, 0.f);
        int gn = n0 + b_n;
        if (gn < N)
            bv = *reinterpret_cast<const float4*>(B + (size_t)(k0 + b_k) * N + gn);
        *reinterpret_cast<float4*>(&Bs[b_k][b_n]) = bv;

        __syncthreads();

#pragma unroll
        for (int k = 0; k < TKK; k++) {
            float a[8], b[8];
#pragma unroll
            for (int i = 0; i < 8; i++) a[i] = As[k][ty * 8 + i];
#pragma unroll
            for (int j = 0; j < 8; j++) b[j] = Bs[k][tx * 8 + j];
#pragma unroll
            for (int i = 0; i < 8; i++)
#pragma unroll
                for (int j = 0; j < 8; j++)
                    acc[i][j] = fmaf(a[i], b[j], acc[i][j]);
        }
        __syncthreads();
    }

#pragma unroll
    for (int i = 0; i < 8; i++) {
        int gm = m0 + ty * 8 + i;
        if (gm < M) {
#pragma unroll
            for (int j = 0; j < 8; j += 4) {
                int gn = n0 + tx * 8 + j;
                if (gn < N) {
                    *reinterpret_cast<float4*>(C + (size_t)gm * N + gn) =
                        make_float4(acc[i][j], acc[i][j+1], acc[i][j+2], acc[i][j+3]);
                }
            }
        }
    }
}

// ---------------------------------------------------------------------------
// agg = (dis^2) * h   (self-loop term), vectorized float4
// ---------------------------------------------------------------------------
template <int HID, int GID>
__global__ void k_selfloop(int n, int F)
{
    const float* h = scratch<HID>();
    float* agg = scratch<GID>();
    int per = F >> 2;
    int idx = blockIdx.x * blockDim.x + threadIdx.x;
    if (idx >= n * per) return;
    int i = idx / per;
    float d = s_dis[i];
    float c = d * d;
    float4 v = *reinterpret_cast<const float4*>(h + (size_t)idx * 4);
    v.x *= c; v.y *= c; v.z *= c; v.w *= c;
    *reinterpret_cast<float4*>(agg + (size_t)idx * 4) = v;
}

// ---------------------------------------------------------------------------
// agg[dst] += h[src] * dis[src] * dis[dst]  over edges, float4 chunks
// ---------------------------------------------------------------------------
template <int HID, int GID>
__global__ void k_scatter(const void* __restrict__ ei, int E, int F)
{
    const float* h = scratch<HID>();
    float* agg = scratch<GID>();
    int per = F >> 2;
    long long idx = (long long)blockIdx.x * blockDim.x + threadIdx.x;
    if (idx >= (long long)E * per) return;
    int e  = (int)(idx / per);
    int fo = (int)(idx % per) * 4;
    int is64 = s_is64;
    int s = edge_at(ei, e, is64);
    int d = edge_at(ei, (long long)E + e, is64);
    if ((unsigned)s >= (unsigned)NNODES || (unsigned)d >= (unsigned)NNODES) return;
    float c = s_dis[s] * s_dis[d];
    float4 v = *reinterpret_cast<const float4*>(h + (size_t)s * F + fo);
    float* p = agg + (size_t)d * F + fo;
    atomicAdd(p + 0, v.x * c);
    atomicAdd(p + 1, v.y * c);
    atomicAdd(p + 2, v.z * c);
    atomicAdd(p + 3, v.w * c);
}

// ---------------------------------------------------------------------------
// agg += bias; optional relu
// ---------------------------------------------------------------------------
template <int GID, bool RELU>
__global__ void k_bias(const float* __restrict__ b, int n, int F)
{
    float* agg = scratch<GID>();
    int idx = blockIdx.x * blockDim.x + threadIdx.x;
    if (idx >= n * F) return;
    float v = agg[idx] + b[idx % F];
    if constexpr (RELU) v = fmaxf(v, 0.0f);
    agg[idx] = v;
}

// ---------------------------------------------------------------------------
// Head: out[i] = sigmoid(x3[i].Wl + bl); copy x3 -> out[n:]. One warp/node.
// ---------------------------------------------------------------------------
template <int XID>
__global__ void k_head(const float* __restrict__ Wl,
                       const float* __restrict__ bl,
                       float* __restrict__ out, int n, long long out_cap)
{
    const float* x3 = scratch<XID>();
    int gt = blockIdx.x * blockDim.x + threadIdx.x;
    int node = gt >> 5;
    int lane = gt & 31;
    if (node >= n) return;
    float v0 = x3[(size_t)node * 64 + lane];
    float v1 = x3[(size_t)node * 64 + 32 + lane];
    long long o0 = (long long)n + (long long)node * 64 + lane;
    if (o0 < out_cap)      out[o0]      = v0;
    if (o0 + 32 < out_cap) out[o0 + 32] = v1;
    float ss = v0 * Wl[lane] + v1 * Wl[32 + lane];
#pragma unroll
    for (int o = 16; o; o >>= 1) ss += __shfl_xor_sync(0xFFFFFFFFu, ss, o);
    if (lane == 0 && node < out_cap)
        out[node] = 1.0f / (1.0f + expf(-(ss + bl[0])));
}

// ---------------------------------------------------------------------------
static inline int cdiv(long long a, long long b) { return (int)((a + b - 1) / b); }

extern "C" void kernel_launch(void* const* d_in, const int* in_sizes, int n_in,
                              void* d_out, int out_size)
{
    const float* x   = (const float*)d_in[0];
    const void*  ei  = d_in[1];               // int32 or int64, detected on device
    const float* W1  = (const float*)d_in[2];
    const float* b1  = (const float*)d_in[3];
    const float* W2  = (const float*)d_in[4];
    const float* b2  = (const float*)d_in[5];
    const float* W3  = (const float*)d_in[6];
    const float* b3  = (const float*)d_in[7];
    const float* Wl  = (const float*)d_in[8];
    const float* bl  = (const float*)d_in[9];
    float* out = (float*)d_out;

    const int n = in_sizes[0] / D0;    // 50000
    const int E = in_sizes[1] / 2;     // 1600000

    // 0. detect edge dtype (scan stays within smaller int32 interpretation)
    int scan_words = (2 * E < 4096) ? 2 * E : 4096;
    k_detect_dtype<<<1, 256>>>((const int*)ei, scan_words);

    // 1. degrees + normalization
    k_deg_zero<<<cdiv(n, 256), 256>>>(n);
    k_deg_count<<<cdiv(E, 256), 256>>>(ei, E);
    k_dis<<<cdiv(n, 256), 256>>>(n);

    // ---- Layer 1: h1 = x @ W1 -> A ; agg(self+scatter) -> B ; +b1, relu ----
    k_gemm<-1, 0><<<dim3(cdiv(D1, TN), cdiv(n, TM)), 256>>>(x, W1, n, D1, D0);
    k_selfloop<0, 1><<<cdiv((long long)n * (D1 / 4), 256), 256>>>(n, D1);
    k_scatter<0, 1><<<cdiv((long long)E * (D1 / 4), 256), 256>>>(ei, E, D1);
    k_bias<1, true><<<cdiv((long long)n * D1, 256), 256>>>(b1, n, D1);

    // ---- Layer 2: h2 = B @ W2 -> C ; agg -> A ; +b2 ----
    k_gemm<1, 2><<<dim3(cdiv(D2, TN), cdiv(n, TM)), 256>>>(nullptr, W2, n, D2, D1);
    k_selfloop<2, 0><<<cdiv((long long)n * (D2 / 4), 256), 256>>>(n, D2);
    k_scatter<2, 0><<<cdiv((long long)E * (D2 / 4), 256), 256>>>(ei, E, D2);
    k_bias<0, false><<<cdiv((long long)n * D2, 256), 256>>>(b2, n, D2);

    // ---- Layer 3: h3 = A @ W3 -> B ; agg -> C (= x3) ; +b3 ----
    k_gemm<0, 1><<<dim3(cdiv(D3, TN), cdiv(n, TM)), 256>>>(nullptr, W3, n, D3, D2);
    k_selfloop<1, 2><<<cdiv((long long)n * (D3 / 4), 256), 256>>>(n, D3);
    k_scatter<1, 2><<<cdiv((long long)E * (D3 / 4), 256), 256>>>(ei, E, D3);
    k_bias<2, false><<<cdiv((long long)n * D3, 256), 256>>>(b3, n, D3);

    // ---- Head ----
    k_head<2><<<cdiv((long long)n * 32, 256), 256>>>(Wl, bl, out, n, (long long)out_size);
}

// round 5
// speedup vs baseline: 1.3014x; 1.3014x over previous
#include <cuda_runtime.h>
#include <cuda_bf16.h>
#include <math.h>

// Fixed problem shapes
#define NNODES 50000
#define D0 3000
#define D1 256
#define D2 128
#define D3 64

// Static scratch (allocation-free rule). Device-code access only.
__device__ __align__(16) float s_bufA[NNODES * D1];   // 51.2 MB
__device__ __align__(16) float s_bufB[NNODES * D1];   // 51.2 MB
__device__ __align__(16) float s_bufC[NNODES * D2];   // 25.6 MB
__device__ int   s_deg[NNODES];
__device__ float s_dis[NNODES];
__device__ int   s_is64;                // 1 if edge_index is int64, 0 if int32

template <int ID>
__device__ __forceinline__ float* scratch() {
    if constexpr (ID == 0) return s_bufA;
    else if constexpr (ID == 1) return s_bufB;
    else return s_bufC;
}

__device__ __forceinline__ int edge_at(const void* ei, long long idx, int is64) {
    if (is64) return (int)((const long long*)ei)[idx];
    return ((const int*)ei)[idx];
}

// ---------------------------------------------------------------------------
// Edge dtype detection (int64 values < 2^31 have all-zero odd int32 words)
// ---------------------------------------------------------------------------
__global__ void k_detect_dtype(const int* __restrict__ ei_words, int nwords)
{
    __shared__ int found_nonzero;
    if (threadIdx.x == 0) found_nonzero = 0;
    __syncthreads();
    for (int w = 1 + 2 * threadIdx.x; w < nwords; w += 2 * blockDim.x) {
        if (ei_words[w] != 0) { found_nonzero = 1; break; }
    }
    __syncthreads();
    if (threadIdx.x == 0) s_is64 = found_nonzero ? 0 : 1;
}

// ---------------------------------------------------------------------------
// Degree / normalization
// ---------------------------------------------------------------------------
__global__ void k_deg_zero(int n) {
    int i = blockIdx.x * blockDim.x + threadIdx.x;
    if (i < n) s_deg[i] = 0;
}

__global__ void k_deg_count(const void* __restrict__ ei, int E) {
    int e = blockIdx.x * blockDim.x + threadIdx.x;
    if (e < E) {
        int is64 = s_is64;
        int d = edge_at(ei, (long long)E + e, is64);
        if ((unsigned)d < (unsigned)NNODES) atomicAdd(&s_deg[d], 1);
    }
}

__global__ void k_dis(int n) {
    int i = blockIdx.x * blockDim.x + threadIdx.x;
    if (i < n) s_dis[i] = rsqrtf((float)s_deg[i] + 1.0f);
}

// ---------------------------------------------------------------------------
// Tensor-core GEMM with split-bf16 (hi/lo) precision compensation.
// C[M,N] = A[M,K] @ W[K,N], fp32 in/out, fp32 accumulate.
// CTA tile 128 x BN, BK=32. Warp tile 64x32. mma.sync.m16n8k16 bf16.
// ---------------------------------------------------------------------------
#define BM 128
#define BK 32
#define BKP 34   // padded SMEM row stride (bf16 elems)

__device__ __forceinline__ void mma16816(float* c, const unsigned* a, const unsigned* b) {
    asm volatile(
        "mma.sync.aligned.m16n8k16.row.col.f32.bf16.bf16.f32 "
        "{%0,%1,%2,%3}, {%4,%5,%6,%7}, {%8,%9}, {%0,%1,%2,%3};\n"
        : "+f"(c[0]), "+f"(c[1]), "+f"(c[2]), "+f"(c[3])
        : "r"(a[0]), "r"(a[1]), "r"(a[2]), "r"(a[3]), "r"(b[0]), "r"(b[1]));
}

template <int AID, int BN, int CID, int T>
__global__ __launch_bounds__(T) void k_gemm_tc(
    const float* __restrict__ Aext, const float* __restrict__ W,
    int M, int N, int K)
{
    const float* A;
    if constexpr (AID < 0) A = Aext; else A = scratch<AID>();
    float* C = scratch<CID>();

    __shared__ __nv_bfloat16 Ah[BM][BKP], Al[BM][BKP];
    __shared__ __nv_bfloat16 Bh[BN][BKP], Bl[BN][BKP];

    const int tid = threadIdx.x;
    const int m0 = blockIdx.y * BM;
    const int n0 = blockIdx.x * BN;

    constexpr int NW_N = BN / 32;           // warp cols
    const int w = tid >> 5, lane = tid & 31;
    const int wm = w / NW_N, wn = w % NW_N; // warp row (0..1), warp col
    const int quad = lane >> 2, ql = lane & 3;

    constexpr int AF4 = (BM * BK / 4) / T;  // float4 per thread for A
    constexpr int WF4 = (BK * BN / 4) / T;  // float4 per thread for W
    constexpr int WF4PR = BN / 4;           // float4 per W row

    float4 aReg[AF4], wReg[WF4];
    float acc[4][4][4];
#pragma unroll
    for (int mt = 0; mt < 4; mt++)
#pragma unroll
        for (int nt = 0; nt < 4; nt++)
#pragma unroll
            for (int i = 0; i < 4; i++) acc[mt][nt][i] = 0.0f;

    const int nch = (K + BK - 1) / BK;

    auto loadA = [&](int k0) {
#pragma unroll
        for (int i = 0; i < AF4; i++) {
            int idx = tid + i * T;
            int r = idx >> 3, c4 = (idx & 7) * 4;
            int gm = m0 + r, gk = k0 + c4;
            float4 v = make_float4(0.f, 0.f, 0.f, 0.f);
            if (gm < M) {
                const float* base = A + (size_t)gm * K;
                if (gk + 3 < K) v = *reinterpret_cast<const float4*>(base + gk);
                else {
                    if (gk + 0 < K) v.x = base[gk + 0];
                    if (gk + 1 < K) v.y = base[gk + 1];
                    if (gk + 2 < K) v.z = base[gk + 2];
                    if (gk + 3 < K) v.w = base[gk + 3];
                }
            }
            aReg[i] = v;
        }
    };

    auto loadW = [&](int k0) {
#pragma unroll
        for (int i = 0; i < WF4; i++) {
            int idx = tid + i * T;
            int k = idx / WF4PR, c4 = (idx % WF4PR) * 4;
            int gk = k0 + k;
            float4 v = make_float4(0.f, 0.f, 0.f, 0.f);
            if (gk < K)
                v = *reinterpret_cast<const float4*>(W + (size_t)gk * N + n0 + c4);
            wReg[i] = v;
        }
    };

    auto stage = [&]() {
#pragma unroll
        for (int i = 0; i < AF4; i++) {
            int idx = tid + i * T;
            int r = idx >> 3, c = (idx & 7) * 4;
            float vv[4] = {aReg[i].x, aReg[i].y, aReg[i].z, aReg[i].w};
#pragma unroll
            for (int j = 0; j < 4; j += 2) {
                __nv_bfloat16 h0 = __float2bfloat16(vv[j]);
                __nv_bfloat16 h1 = __float2bfloat16(vv[j + 1]);
                __nv_bfloat16 l0 = __float2bfloat16(vv[j] - __bfloat162float(h0));
                __nv_bfloat16 l1 = __float2bfloat16(vv[j + 1] - __bfloat162float(h1));
                __nv_bfloat162 hp; hp.x = h0; hp.y = h1;
                __nv_bfloat162 lp; lp.x = l0; lp.y = l1;
                *reinterpret_cast<__nv_bfloat162*>(&Ah[r][c + j]) = hp;
                *reinterpret_cast<__nv_bfloat162*>(&Al[r][c + j]) = lp;
            }
        }
#pragma unroll
        for (int i = 0; i < WF4; i++) {
            int idx = tid + i * T;
            int k = idx / WF4PR, c = (idx % WF4PR) * 4;
            float vv[4] = {wReg[i].x, wReg[i].y, wReg[i].z, wReg[i].w};
#pragma unroll
            for (int j = 0; j < 4; j++) {
                __nv_bfloat16 h = __float2bfloat16(vv[j]);
                __nv_bfloat16 l = __float2bfloat16(vv[j] - __bfloat162float(h));
                Bh[c + j][k] = h;   // transposed: [n][k]
                Bl[c + j][k] = l;
            }
        }
    };

    auto compute = [&]() {
#pragma unroll
        for (int ks = 0; ks < BK; ks += 16) {
            unsigned bh[4][2], bl[4][2];
#pragma unroll
            for (int nt = 0; nt < 4; nt++) {
                int nn = wn * 32 + nt * 8 + quad;
                int kk = ks + ql * 2;
                bh[nt][0] = *reinterpret_cast<const unsigned*>(&Bh[nn][kk]);
                bh[nt][1] = *reinterpret_cast<const unsigned*>(&Bh[nn][kk + 8]);
                bl[nt][0] = *reinterpret_cast<const unsigned*>(&Bl[nn][kk]);
                bl[nt][1] = *reinterpret_cast<const unsigned*>(&Bl[nn][kk + 8]);
            }
#pragma unroll
            for (int mt = 0; mt < 4; mt++) {
                int r = wm * 64 + mt * 16 + quad;
                int kk = ks + ql * 2;
                unsigned ah[4], al[4];
                ah[0] = *reinterpret_cast<const unsigned*>(&Ah[r][kk]);
                ah[1] = *reinterpret_cast<const unsigned*>(&Ah[r + 8][kk]);
                ah[2] = *reinterpret_cast<const unsigned*>(&Ah[r][kk + 8]);
                ah[3] = *reinterpret_cast<const unsigned*>(&Ah[r + 8][kk + 8]);
                al[0] = *reinterpret_cast<const unsigned*>(&Al[r][kk]);
                al[1] = *reinterpret_cast<const unsigned*>(&Al[r + 8][kk]);
                al[2] = *reinterpret_cast<const unsigned*>(&Al[r][kk + 8]);
                al[3] = *reinterpret_cast<const unsigned*>(&Al[r + 8][kk + 8]);
#pragma unroll
                for (int nt = 0; nt < 4; nt++) {
                    mma16816(acc[mt][nt], ah, bh[nt]);
                    mma16816(acc[mt][nt], ah, bl[nt]);
                    mma16816(acc[mt][nt], al, bh[nt]);
                }
            }
        }
    };

    loadA(0); loadW(0);
    for (int ch = 0; ch < nch; ch++) {
        __syncthreads();
        stage();
        __syncthreads();
        if (ch + 1 < nch) { loadA((ch + 1) * BK); loadW((ch + 1) * BK); }
        compute();
    }

    // Epilogue
#pragma unroll
    for (int mt = 0; mt < 4; mt++) {
        int r0 = m0 + wm * 64 + mt * 16 + quad;
#pragma unroll
        for (int nt = 0; nt < 4; nt++) {
            int cc = n0 + wn * 32 + nt * 8 + ql * 2;
            float* p = acc[mt][nt];
            if (r0 < M) {
                float2 v0 = make_float2(p[0], p[1]);
                *reinterpret_cast<float2*>(C + (size_t)r0 * N + cc) = v0;
            }
            if (r0 + 8 < M) {
                float2 v1 = make_float2(p[2], p[3]);
                *reinterpret_cast<float2*>(C + (size_t)(r0 + 8) * N + cc) = v1;
            }
        }
    }
}

// ---------------------------------------------------------------------------
// agg = (dis^2) * h   (self-loop term)
// ---------------------------------------------------------------------------
template <int HID, int GID>
__global__ void k_selfloop(int n, int F)
{
    const float* h = scratch<HID>();
    float* agg = scratch<GID>();
    int per = F >> 2;
    int idx = blockIdx.x * blockDim.x + threadIdx.x;
    if (idx >= n * per) return;
    int i = idx / per;
    float d = s_dis[i];
    float c = d * d;
    float4 v = *reinterpret_cast<const float4*>(h + (size_t)idx * 4);
    v.x *= c; v.y *= c; v.z *= c; v.w *= c;
    *reinterpret_cast<float4*>(agg + (size_t)idx * 4) = v;
}

// ---------------------------------------------------------------------------
// agg[dst] += h[src] * dis[src] * dis[dst]
// ---------------------------------------------------------------------------
template <int HID, int GID>
__global__ void k_scatter(const void* __restrict__ ei, int E, int F)
{
    const float* h = scratch<HID>();
    float* agg = scratch<GID>();
    int per = F >> 2;
    long long idx = (long long)blockIdx.x * blockDim.x + threadIdx.x;
    if (idx >= (long long)E * per) return;
    int e  = (int)(idx / per);
    int fo = (int)(idx % per) * 4;
    int is64 = s_is64;
    int s = edge_at(ei, e, is64);
    int d = edge_at(ei, (long long)E + e, is64);
    if ((unsigned)s >= (unsigned)NNODES || (unsigned)d >= (unsigned)NNODES) return;
    float c = s_dis[s] * s_dis[d];
    float4 v = *reinterpret_cast<const float4*>(h + (size_t)s * F + fo);
    float* p = agg + (size_t)d * F + fo;
    atomicAdd(p + 0, v.x * c);
    atomicAdd(p + 1, v.y * c);
    atomicAdd(p + 2, v.z * c);
    atomicAdd(p + 3, v.w * c);
}

// ---------------------------------------------------------------------------
// agg += bias; optional relu
// ---------------------------------------------------------------------------
template <int GID, bool RELU>
__global__ void k_bias(const float* __restrict__ b, int n, int F)
{
    float* agg = scratch<GID>();
    int idx = blockIdx.x * blockDim.x + threadIdx.x;
    if (idx >= n * F) return;
    float v = agg[idx] + b[idx % F];
    if constexpr (RELU) v = fmaxf(v, 0.0f);
    agg[idx] = v;
}

// ---------------------------------------------------------------------------
// Head
// ---------------------------------------------------------------------------
template <int XID>
__global__ void k_head(const float* __restrict__ Wl,
                       const float* __restrict__ bl,
                       float* __restrict__ out, int n, long long out_cap)
{
    const float* x3 = scratch<XID>();
    int gt = blockIdx.x * blockDim.x + threadIdx.x;
    int node = gt >> 5;
    int lane = gt & 31;
    if (node >= n) return;
    float v0 = x3[(size_t)node * 64 + lane];
    float v1 = x3[(size_t)node * 64 + 32 + lane];
    long long o0 = (long long)n + (long long)node * 64 + lane;
    if (o0 < out_cap)      out[o0]      = v0;
    if (o0 + 32 < out_cap) out[o0 + 32] = v1;
    float ss = v0 * Wl[lane] + v1 * Wl[32 + lane];
#pragma unroll
    for (int o = 16; o; o >>= 1) ss += __shfl_xor_sync(0xFFFFFFFFu, ss, o);
    if (lane == 0 && node < out_cap)
        out[node] = 1.0f / (1.0f + expf(-(ss + bl[0])));
}

// ---------------------------------------------------------------------------
static inline int cdiv(long long a, long long b) { return (int)((a + b - 1) / b); }

extern "C" void kernel_launch(void* const* d_in, const int* in_sizes, int n_in,
                              void* d_out, int out_size)
{
    const float* x   = (const float*)d_in[0];
    const void*  ei  = d_in[1];
    const float* W1  = (const float*)d_in[2];
    const float* b1  = (const float*)d_in[3];
    const float* W2  = (const float*)d_in[4];
    const float* b2  = (const float*)d_in[5];
    const float* W3  = (const float*)d_in[6];
    const float* b3  = (const float*)d_in[7];
    const float* Wl  = (const float*)d_in[8];
    const float* bl  = (const float*)d_in[9];
    float* out = (float*)d_out;

    const int n = in_sizes[0] / D0;    // 50000
    const int E = in_sizes[1] / 2;     // 1600000

    int scan_words = (2 * E < 4096) ? 2 * E : 4096;
    k_detect_dtype<<<1, 256>>>((const int*)ei, scan_words);

    k_deg_zero<<<cdiv(n, 256), 256>>>(n);
    k_deg_count<<<cdiv(E, 256), 256>>>(ei, E);
    k_dis<<<cdiv(n, 256), 256>>>(n);

    const int MT = cdiv(n, BM);   // 391

    // ---- Layer 1: h1 = x @ W1 -> A ; agg -> B ; +b1, relu ----
    k_gemm_tc<-1, 128, 0, 256><<<dim3(D1 / 128, MT), 256>>>(x, W1, n, D1, D0);
    k_selfloop<0, 1><<<cdiv((long long)n * (D1 / 4), 256), 256>>>(n, D1);
    k_scatter<0, 1><<<cdiv((long long)E * (D1 / 4), 256), 256>>>(ei, E, D1);
    k_bias<1, true><<<cdiv((long long)n * D1, 256), 256>>>(b1, n, D1);

    // ---- Layer 2: h2 = B @ W2 -> C ; agg -> A ; +b2 ----
    k_gemm_tc<1, 128, 2, 256><<<dim3(D2 / 128, MT), 256>>>(nullptr, W2, n, D2, D1);
    k_selfloop<2, 0><<<cdiv((long long)n * (D2 / 4), 256), 256>>>(n, D2);
    k_scatter<2, 0><<<cdiv((long long)E * (D2 / 4), 256), 256>>>(ei, E, D2);
    k_bias<0, false><<<cdiv((long long)n * D2, 256), 256>>>(b2, n, D2);

    // ---- Layer 3: h3 = A @ W3 -> B ; agg -> C (= x3) ; +b3 ----
    k_gemm_tc<0, 64, 1, 128><<<dim3(D3 / 64, MT), 128>>>(nullptr, W3, n, D3, D2);
    k_selfloop<1, 2><<<cdiv((long long)n * (D3 / 4), 256), 256>>>(n, D3);
    k_scatter<1, 2><<<cdiv((long long)E * (D3 / 4), 256), 256>>>(ei, E, D3);
    k_bias<2, false><<<cdiv((long long)n * D3, 256), 256>>>(b3, n, D3);

    // ---- Head ----
    k_head<2><<<cdiv((long long)n * 32, 256), 256>>>(Wl, bl, out, n, (long long)out_size);
}

// round 6
// speedup vs baseline: 2.4341x; 1.8704x over previous
#include <cuda_runtime.h>
#include <cuda_bf16.h>
#include <math.h>

// Fixed problem shapes
#define NNODES 50000
#define D0 3000
#define D1 256
#define D2 128
#define D3 64
#define ECAP 1600000

// Static scratch (allocation-free rule). Device-code access only.
__device__ __align__(16) float s_bufA[NNODES * D1];   // 51.2 MB
__device__ __align__(16) float s_bufB[NNODES * D1];   // 51.2 MB
__device__ int   s_deg[NNODES];
__device__ float s_dis[NNODES];
__device__ int   s_rowptr[NNODES + 1];
__device__ int   s_cnt[NNODES];
__device__ int   s_csr_src[ECAP];
__device__ float s_csr_w[ECAP];
__device__ int   s_is64;

template <int ID>
__device__ __forceinline__ float* scratch() {
    if constexpr (ID == 0) return s_bufA;
    else return s_bufB;
}

__device__ __forceinline__ int edge_at(const void* ei, long long idx, int is64) {
    if (is64) return (int)((const long long*)ei)[idx];
    return ((const int*)ei)[idx];
}

// ---------------------------------------------------------------------------
// Edge dtype detection (int64 values < 2^31 have all-zero odd int32 words)
// ---------------------------------------------------------------------------
__global__ void k_detect_dtype(const int* __restrict__ ei_words, int nwords)
{
    __shared__ int found_nonzero;
    if (threadIdx.x == 0) found_nonzero = 0;
    __syncthreads();
    for (int w = 1 + 2 * threadIdx.x; w < nwords; w += 2 * blockDim.x) {
        if (ei_words[w] != 0) { found_nonzero = 1; break; }
    }
    __syncthreads();
    if (threadIdx.x == 0) s_is64 = found_nonzero ? 0 : 1;
}

// ---------------------------------------------------------------------------
// Degree / normalization / CSR build
// ---------------------------------------------------------------------------
__global__ void k_deg_zero(int n) {
    int i = blockIdx.x * blockDim.x + threadIdx.x;
    if (i < n) s_deg[i] = 0;
}

__global__ void k_deg_count(const void* __restrict__ ei, int E) {
    int e = blockIdx.x * blockDim.x + threadIdx.x;
    if (e < E) {
        int is64 = s_is64;
        int d = edge_at(ei, (long long)E + e, is64);
        if ((unsigned)d < (unsigned)NNODES) atomicAdd(&s_deg[d], 1);
    }
}

__global__ void k_dis(int n) {
    int i = blockIdx.x * blockDim.x + threadIdx.x;
    if (i < n) s_dis[i] = rsqrtf((float)s_deg[i] + 1.0f);
}

// Single-block exclusive prefix scan of s_deg -> s_rowptr, and s_cnt = rowptr.
__global__ __launch_bounds__(1024) void k_scan(int n)
{
    __shared__ int sh[1024];
    __shared__ int carry_sh;
    if (threadIdx.x == 0) carry_sh = 0;
    __syncthreads();
    for (int base = 0; base < n; base += 1024) {
        int i = base + (int)threadIdx.x;
        int v = (i < n) ? s_deg[i] : 0;
        sh[threadIdx.x] = v;
        __syncthreads();
#pragma unroll
        for (int off = 1; off < 1024; off <<= 1) {
            int t = (threadIdx.x >= off) ? sh[threadIdx.x - off] : 0;
            __syncthreads();
            sh[threadIdx.x] += t;
            __syncthreads();
        }
        int incl = sh[threadIdx.x];
        int excl = incl - v;
        int carry = carry_sh;
        if (i < n) {
            s_rowptr[i] = carry + excl;
            s_cnt[i]    = carry + excl;
        }
        __syncthreads();
        if (threadIdx.x == 1023) carry_sh = carry + incl;
        __syncthreads();
    }
    if (threadIdx.x == 0) s_rowptr[n] = carry_sh;
}

// Fill CSR: slot = cnt[dst]++; store src and weight dis[src]*dis[dst].
__global__ void k_csr_fill(const void* __restrict__ ei, int E)
{
    int e = blockIdx.x * blockDim.x + threadIdx.x;
    if (e >= E) return;
    int is64 = s_is64;
    int s = edge_at(ei, e, is64);
    int d = edge_at(ei, (long long)E + e, is64);
    if ((unsigned)s >= (unsigned)NNODES || (unsigned)d >= (unsigned)NNODES) return;
    int pos = atomicAdd(&s_cnt[d], 1);
    if (pos < ECAP) {
        s_csr_src[pos] = s;
        s_csr_w[pos]   = s_dis[s] * s_dis[d];
    }
}

// ---------------------------------------------------------------------------
// Tensor-core GEMM with split-bf16 (hi/lo) precision compensation.
// ---------------------------------------------------------------------------
#define BM 128
#define BK 32
#define BKP 34

__device__ __forceinline__ void mma16816(float* c, const unsigned* a, const unsigned* b) {
    asm volatile(
        "mma.sync.aligned.m16n8k16.row.col.f32.bf16.bf16.f32 "
        "{%0,%1,%2,%3}, {%4,%5,%6,%7}, {%8,%9}, {%0,%1,%2,%3};\n"
        : "+f"(c[0]), "+f"(c[1]), "+f"(c[2]), "+f"(c[3])
        : "r"(a[0]), "r"(a[1]), "r"(a[2]), "r"(a[3]), "r"(b[0]), "r"(b[1]));
}

template <int AID, int BN, int CID, int T>
__global__ __launch_bounds__(T) void k_gemm_tc(
    const float* __restrict__ Aext, const float* __restrict__ W,
    int M, int N, int K)
{
    const float* A;
    if constexpr (AID < 0) A = Aext; else A = scratch<AID>();
    float* C = scratch<CID>();

    __shared__ __nv_bfloat16 Ah[BM][BKP], Al[BM][BKP];
    __shared__ __nv_bfloat16 Bh[BN][BKP], Bl[BN][BKP];

    const int tid = threadIdx.x;
    const int m0 = blockIdx.y * BM;
    const int n0 = blockIdx.x * BN;

    constexpr int NW_N = BN / 32;
    const int w = tid >> 5, lane = tid & 31;
    const int wm = w / NW_N, wn = w % NW_N;
    const int quad = lane >> 2, ql = lane & 3;

    constexpr int AF4 = (BM * BK / 4) / T;
    constexpr int WF4 = (BK * BN / 4) / T;
    constexpr int WF4PR = BN / 4;

    float4 aReg[AF4], wReg[WF4];
    float acc[4][4][4];
#pragma unroll
    for (int mt = 0; mt < 4; mt++)
#pragma unroll
        for (int nt = 0; nt < 4; nt++)
#pragma unroll
            for (int i = 0; i < 4; i++) acc[mt][nt][i] = 0.0f;

    const int nch = (K + BK - 1) / BK;

    auto loadA = [&](int k0) {
#pragma unroll
        for (int i = 0; i < AF4; i++) {
            int idx = tid + i * T;
            int r = idx >> 3, c4 = (idx & 7) * 4;
            int gm = m0 + r, gk = k0 + c4;
            float4 v = make_float4(0.f, 0.f, 0.f, 0.f);
            if (gm < M) {
                const float* base = A + (size_t)gm * K;
                if (gk + 3 < K) v = *reinterpret_cast<const float4*>(base + gk);
                else {
                    if (gk + 0 < K) v.x = base[gk + 0];
                    if (gk + 1 < K) v.y = base[gk + 1];
                    if (gk + 2 < K) v.z = base[gk + 2];
                    if (gk + 3 < K) v.w = base[gk + 3];
                }
            }
            aReg[i] = v;
        }
    };

    auto loadW = [&](int k0) {
#pragma unroll
        for (int i = 0; i < WF4; i++) {
            int idx = tid + i * T;
            int k = idx / WF4PR, c4 = (idx % WF4PR) * 4;
            int gk = k0 + k;
            float4 v = make_float4(0.f, 0.f, 0.f, 0.f);
            if (gk < K)
                v = *reinterpret_cast<const float4*>(W + (size_t)gk * N + n0 + c4);
            wReg[i] = v;
        }
    };

    auto stage = [&]() {
#pragma unroll
        for (int i = 0; i < AF4; i++) {
            int idx = tid + i * T;
            int r = idx >> 3, c = (idx & 7) * 4;
            float vv[4] = {aReg[i].x, aReg[i].y, aReg[i].z, aReg[i].w};
#pragma unroll
            for (int j = 0; j < 4; j += 2) {
                __nv_bfloat16 h0 = __float2bfloat16(vv[j]);
                __nv_bfloat16 h1 = __float2bfloat16(vv[j + 1]);
                __nv_bfloat16 l0 = __float2bfloat16(vv[j] - __bfloat162float(h0));
                __nv_bfloat16 l1 = __float2bfloat16(vv[j + 1] - __bfloat162float(h1));
                __nv_bfloat162 hp; hp.x = h0; hp.y = h1;
                __nv_bfloat162 lp; lp.x = l0; lp.y = l1;
                *reinterpret_cast<__nv_bfloat162*>(&Ah[r][c + j]) = hp;
                *reinterpret_cast<__nv_bfloat162*>(&Al[r][c + j]) = lp;
            }
        }
#pragma unroll
        for (int i = 0; i < WF4; i++) {
            int idx = tid + i * T;
            int k = idx / WF4PR, c = (idx % WF4PR) * 4;
            float vv[4] = {wReg[i].x, wReg[i].y, wReg[i].z, wReg[i].w};
#pragma unroll
            for (int j = 0; j < 4; j++) {
                __nv_bfloat16 h = __float2bfloat16(vv[j]);
                __nv_bfloat16 l = __float2bfloat16(vv[j] - __bfloat162float(h));
                Bh[c + j][k] = h;
                Bl[c + j][k] = l;
            }
        }
    };

    auto compute = [&]() {
#pragma unroll
        for (int ks = 0; ks < BK; ks += 16) {
            unsigned bh[4][2], bl[4][2];
#pragma unroll
            for (int nt = 0; nt < 4; nt++) {
                int nn = wn * 32 + nt * 8 + quad;
                int kk = ks + ql * 2;
                bh[nt][0] = *reinterpret_cast<const unsigned*>(&Bh[nn][kk]);
                bh[nt][1] = *reinterpret_cast<const unsigned*>(&Bh[nn][kk + 8]);
                bl[nt][0] = *reinterpret_cast<const unsigned*>(&Bl[nn][kk]);
                bl[nt][1] = *reinterpret_cast<const unsigned*>(&Bl[nn][kk + 8]);
            }
#pragma unroll
            for (int mt = 0; mt < 4; mt++) {
                int r = wm * 64 + mt * 16 + quad;
                int kk = ks + ql * 2;
                unsigned ah[4], al[4];
                ah[0] = *reinterpret_cast<const unsigned*>(&Ah[r][kk]);
                ah[1] = *reinterpret_cast<const unsigned*>(&Ah[r + 8][kk]);
                ah[2] = *reinterpret_cast<const unsigned*>(&Ah[r][kk + 8]);
                ah[3] = *reinterpret_cast<const unsigned*>(&Ah[r + 8][kk + 8]);
                al[0] = *reinterpret_cast<const unsigned*>(&Al[r][kk]);
                al[1] = *reinterpret_cast<const unsigned*>(&Al[r + 8][kk]);
                al[2] = *reinterpret_cast<const unsigned*>(&Al[r][kk + 8]);
                al[3] = *reinterpret_cast<const unsigned*>(&Al[r + 8][kk + 8]);
#pragma unroll
                for (int nt = 0; nt < 4; nt++) {
                    mma16816(acc[mt][nt], ah, bh[nt]);
                    mma16816(acc[mt][nt], ah, bl[nt]);
                    mma16816(acc[mt][nt], al, bh[nt]);
                }
            }
        }
    };

    loadA(0); loadW(0);
    for (int ch = 0; ch < nch; ch++) {
        __syncthreads();
        stage();
        __syncthreads();
        if (ch + 1 < nch) { loadA((ch + 1) * BK); loadW((ch + 1) * BK); }
        compute();
    }

#pragma unroll
    for (int mt = 0; mt < 4; mt++) {
        int r0 = m0 + wm * 64 + mt * 16 + quad;
#pragma unroll
        for (int nt = 0; nt < 4; nt++) {
            int cc = n0 + wn * 32 + nt * 8 + ql * 2;
            float* p = acc[mt][nt];
            if (r0 < M) {
                *reinterpret_cast<float2*>(C + (size_t)r0 * N + cc) =
                    make_float2(p[0], p[1]);
            }
            if (r0 + 8 < M) {
                *reinterpret_cast<float2*>(C + (size_t)(r0 + 8) * N + cc) =
                    make_float2(p[2], p[3]);
            }
        }
    }
}

// ---------------------------------------------------------------------------
// Fused CSR aggregation: one warp per dst node.
//   acc = h[node]*dis[node]^2 + sum_e h[csr_src[e]]*csr_w[e] + bias (+relu)
// HEAD variant (F=64) writes x3 to out[n:], computes sigmoid(x3.Wl+bl) -> out[0:n].
// ---------------------------------------------------------------------------
template <int HID, int GID, int F, bool RELU, bool HEAD>
__global__ __launch_bounds__(256) void k_aggregate(
    const float* __restrict__ bias,
    const float* __restrict__ Wl, const float* __restrict__ bl,
    float* __restrict__ out, int n)
{
    const float* h = scratch<HID>();
    constexpr int REP = F / 32;

    int warp_in_block = threadIdx.x >> 5;
    int lane = threadIdx.x & 31;
    int node = blockIdx.x * (blockDim.x >> 5) + warp_in_block;
    if (node >= n) return;

    float d = s_dis[node];
    float dsq = d * d;

    float acc[REP];
#pragma unroll
    for (int r = 0; r < REP; r++)
        acc[r] = h[(size_t)node * F + lane + r * 32] * dsq;

    int beg = s_rowptr[node];
    int end = s_rowptr[node + 1];
    for (int e = beg; e < end; e++) {
        int src = s_csr_src[e];
        float wgt = s_csr_w[e];
        const float* hr = h + (size_t)src * F;
#pragma unroll
        for (int r = 0; r < REP; r++)
            acc[r] = fmaf(hr[lane + r * 32], wgt, acc[r]);
    }

#pragma unroll
    for (int r = 0; r < REP; r++) {
        acc[r] += bias[lane + r * 32];
        if constexpr (RELU) acc[r] = fmaxf(acc[r], 0.0f);
    }

    if constexpr (!HEAD) {
        float* agg = scratch<GID>();
#pragma unroll
        for (int r = 0; r < REP; r++)
            agg[(size_t)node * F + lane + r * 32] = acc[r];
    } else {
        // F == 64 here: acc[0] = x3[lane], acc[1] = x3[lane+32]
        out[(size_t)n + (size_t)node * 64 + lane]      = acc[0];
        out[(size_t)n + (size_t)node * 64 + 32 + lane] = acc[1];
        float ss = acc[0] * Wl[lane] + acc[1] * Wl[32 + lane];
#pragma unroll
        for (int o = 16; o; o >>= 1) ss += __shfl_xor_sync(0xFFFFFFFFu, ss, o);
        if (lane == 0)
            out[node] = 1.0f / (1.0f + expf(-(ss + bl[0])));
    }
}

// ---------------------------------------------------------------------------
static inline int cdiv(long long a, long long b) { return (int)((a + b - 1) / b); }

extern "C" void kernel_launch(void* const* d_in, const int* in_sizes, int n_in,
                              void* d_out, int out_size)
{
    const float* x   = (const float*)d_in[0];
    const void*  ei  = d_in[1];
    const float* W1  = (const float*)d_in[2];
    const float* b1  = (const float*)d_in[3];
    const float* W2  = (const float*)d_in[4];
    const float* b2  = (const float*)d_in[5];
    const float* W3  = (const float*)d_in[6];
    const float* b3  = (const float*)d_in[7];
    const float* Wl  = (const float*)d_in[8];
    const float* bl  = (const float*)d_in[9];
    float* out = (float*)d_out;

    const int n = in_sizes[0] / D0;    // 50000
    const int E = in_sizes[1] / 2;     // 1600000

    int scan_words = (2 * E < 4096) ? 2 * E : 4096;
    k_detect_dtype<<<1, 256>>>((const int*)ei, scan_words);

    // CSR build
    k_deg_zero<<<cdiv(n, 256), 256>>>(n);
    k_deg_count<<<cdiv(E, 256), 256>>>(ei, E);
    k_dis<<<cdiv(n, 256), 256>>>(n);
    k_scan<<<1, 1024>>>(n);
    k_csr_fill<<<cdiv(E, 256), 256>>>(ei, E);

    const int MT = cdiv(n, BM);           // 391
    const int AGG_BLOCKS = cdiv(n, 8);    // 8 warps per block

    // ---- Layer 1: gemm x@W1 -> A ; fused agg+b1+relu -> B ----
    k_gemm_tc<-1, 128, 0, 256><<<dim3(D1 / 128, MT), 256>>>(x, W1, n, D1, D0);
    k_aggregate<0, 1, D1, true, false><<<AGG_BLOCKS, 256>>>(b1, nullptr, nullptr, nullptr, n);

    // ---- Layer 2: gemm B@W2 -> A ; fused agg+b2 -> B ----
    k_gemm_tc<1, 128, 0, 256><<<dim3(D2 / 128, MT), 256>>>(nullptr, W2, n, D2, D1);
    k_aggregate<0, 1, D2, false, false><<<AGG_BLOCKS, 256>>>(b2, nullptr, nullptr, nullptr, n);

    // ---- Layer 3: gemm B@W3 -> A ; fused agg+b3+head -> out ----
    k_gemm_tc<1, 64, 0, 128><<<dim3(D3 / 64, MT), 128>>>(nullptr, W3, n, D3, D2);
    k_aggregate<0, 1, D3, false, true><<<AGG_BLOCKS, 256>>>(b3, Wl, bl, out, n);
}

// round 7
// speedup vs baseline: 2.4631x; 1.0119x over previous
#include <cuda_runtime.h>
#include <cuda_bf16.h>
#include <math.h>

// Fixed problem shapes
#define NNODES 50000
#define D0 3000
#define D1 256
#define D2 128
#define D3 64
#define ECAP 1600000

// Static scratch (allocation-free rule). Device-code access only.
__device__ __align__(16) float s_bufA[NNODES * D1];   // 51.2 MB
__device__ __align__(16) float s_bufB[NNODES * D1];   // 51.2 MB
__device__ int   s_deg[NNODES];
__device__ float s_dis[NNODES];
__device__ int   s_rowptr[NNODES + 1];
__device__ int   s_cnt[NNODES];
__device__ int   s_csr_src[ECAP];
__device__ float s_csr_w[ECAP];
__device__ int   s_is64;

template <int ID>
__device__ __forceinline__ float* scratch() {
    if constexpr (ID == 0) return s_bufA;
    else return s_bufB;
}

__device__ __forceinline__ int edge_at(const void* ei, long long idx, int is64) {
    if (is64) return (int)((const long long*)ei)[idx];
    return ((const int*)ei)[idx];
}

// ---------------------------------------------------------------------------
// Edge dtype detection
// ---------------------------------------------------------------------------
__global__ void k_detect_dtype(const int* __restrict__ ei_words, int nwords)
{
    __shared__ int found_nonzero;
    if (threadIdx.x == 0) found_nonzero = 0;
    __syncthreads();
    for (int w = 1 + 2 * threadIdx.x; w < nwords; w += 2 * blockDim.x) {
        if (ei_words[w] != 0) { found_nonzero = 1; break; }
    }
    __syncthreads();
    if (threadIdx.x == 0) s_is64 = found_nonzero ? 0 : 1;
}

// ---------------------------------------------------------------------------
// Degree / normalization / CSR build
// ---------------------------------------------------------------------------
__global__ void k_deg_zero(int n) {
    int i = blockIdx.x * blockDim.x + threadIdx.x;
    if (i < n) s_deg[i] = 0;
}

__global__ void k_deg_count(const void* __restrict__ ei, int E) {
    int e = blockIdx.x * blockDim.x + threadIdx.x;
    if (e < E) {
        int is64 = s_is64;
        int d = edge_at(ei, (long long)E + e, is64);
        if ((unsigned)d < (unsigned)NNODES) atomicAdd(&s_deg[d], 1);
    }
}

__global__ void k_dis(int n) {
    int i = blockIdx.x * blockDim.x + threadIdx.x;
    if (i < n) s_dis[i] = rsqrtf((float)s_deg[i] + 1.0f);
}

__global__ __launch_bounds__(1024) void k_scan(int n)
{
    __shared__ int sh[1024];
    __shared__ int carry_sh;
    if (threadIdx.x == 0) carry_sh = 0;
    __syncthreads();
    for (int base = 0; base < n; base += 1024) {
        int i = base + (int)threadIdx.x;
        int v = (i < n) ? s_deg[i] : 0;
        sh[threadIdx.x] = v;
        __syncthreads();
#pragma unroll
        for (int off = 1; off < 1024; off <<= 1) {
            int t = (threadIdx.x >= off) ? sh[threadIdx.x - off] : 0;
            __syncthreads();
            sh[threadIdx.x] += t;
            __syncthreads();
        }
        int incl = sh[threadIdx.x];
        int excl = incl - v;
        int carry = carry_sh;
        if (i < n) {
            s_rowptr[i] = carry + excl;
            s_cnt[i]    = carry + excl;
        }
        __syncthreads();
        if (threadIdx.x == 1023) carry_sh = carry + incl;
        __syncthreads();
    }
    if (threadIdx.x == 0) s_rowptr[n] = carry_sh;
}

__global__ void k_csr_fill(const void* __restrict__ ei, int E)
{
    int e = blockIdx.x * blockDim.x + threadIdx.x;
    if (e >= E) return;
    int is64 = s_is64;
    int s = edge_at(ei, e, is64);
    int d = edge_at(ei, (long long)E + e, is64);
    if ((unsigned)s >= (unsigned)NNODES || (unsigned)d >= (unsigned)NNODES) return;
    int pos = atomicAdd(&s_cnt[d], 1);
    if (pos < ECAP) {
        s_csr_src[pos] = s;
        s_csr_w[pos]   = s_dis[s] * s_dis[d];
    }
}

// ---------------------------------------------------------------------------
// mma helper
// ---------------------------------------------------------------------------
__device__ __forceinline__ void mma16816(float* c, const unsigned* a, const unsigned* b) {
    asm volatile(
        "mma.sync.aligned.m16n8k16.row.col.f32.bf16.bf16.f32 "
        "{%0,%1,%2,%3}, {%4,%5,%6,%7}, {%8,%9}, {%0,%1,%2,%3};\n"
        : "+f"(c[0]), "+f"(c[1]), "+f"(c[2]), "+f"(c[3])
        : "r"(a[0]), "r"(a[1]), "r"(a[2]), "r"(a[3]), "r"(b[0]), "r"(b[1]));
}

__device__ __forceinline__ void split_bf16(float v, __nv_bfloat16& h, __nv_bfloat16& l) {
    h = __float2bfloat16(v);
    l = __float2bfloat16(v - __bfloat162float(h));
}

// ---------------------------------------------------------------------------
// Layer-1 GEMM: C[M,256] = A[M,3000] @ W[3000,256].
// BM=128, BN=256 (full N -> A staged once), BK=32, T=512 (16 warps 2x8),
// warp tile 64x32, double-buffered dynamic SMEM, split-bf16 3-pass mma.
// ---------------------------------------------------------------------------
#define BK 32
#define BKP 34
#define L1_ASZ (128 * BKP)
#define L1_BSZ (256 * BKP)
#define L1_SMEM_BYTES ((2 * L1_ASZ + 2 * L1_ASZ + 2 * L1_BSZ + 2 * L1_BSZ) * 2)

__global__ __launch_bounds__(512) void k_gemm_l1(
    const float* __restrict__ A, const float* __restrict__ W, int M)
{
    const int N = 256, K = 3000;
    float* C = s_bufA;

    extern __shared__ __nv_bfloat16 dsm[];
    __nv_bfloat16* Ah = dsm;                    // [2][128][BKP]
    __nv_bfloat16* Al = Ah + 2 * L1_ASZ;
    __nv_bfloat16* Bh = Al + 2 * L1_ASZ;        // [2][256][BKP] (transposed [n][k])
    __nv_bfloat16* Bl = Bh + 2 * L1_BSZ;

    const int tid = threadIdx.x;
    const int m0 = blockIdx.y * 128;
    const int w = tid >> 5, lane = tid & 31;
    const int wm = w >> 3, wn = w & 7;          // 2 x 8 warp grid
    const int quad = lane >> 2, ql = lane & 3;

    float acc[4][4][4];
#pragma unroll
    for (int mt = 0; mt < 4; mt++)
#pragma unroll
        for (int nt = 0; nt < 4; nt++)
#pragma unroll
            for (int i = 0; i < 4; i++) acc[mt][nt][i] = 0.0f;

    const int nch = (K + BK - 1) / BK;   // 94

    auto loadstage = [&](int k0, int buf) {
        // A: 128x32 = 1024 float4, 2 per thread
#pragma unroll
        for (int i = 0; i < 2; i++) {
            int idx = tid + i * 512;
            int r = idx >> 3, c4 = (idx & 7) * 4;
            int gm = m0 + r, gk = k0 + c4;
            float4 v = make_float4(0.f, 0.f, 0.f, 0.f);
            if (gm < M) {
                const float* base = A + (size_t)gm * K;
                if (gk + 3 < K) v = *reinterpret_cast<const float4*>(base + gk);
                else {
                    if (gk + 0 < K) v.x = base[gk + 0];
                    if (gk + 1 < K) v.y = base[gk + 1];
                    if (gk + 2 < K) v.z = base[gk + 2];
                    if (gk + 3 < K) v.w = base[gk + 3];
                }
            }
            float vv[4] = {v.x, v.y, v.z, v.w};
            int off = buf * L1_ASZ + r * BKP + c4;
#pragma unroll
            for (int j = 0; j < 4; j += 2) {
                __nv_bfloat16 h0, l0, h1, l1;
                split_bf16(vv[j], h0, l0);
                split_bf16(vv[j + 1], h1, l1);
                __nv_bfloat162 hp; hp.x = h0; hp.y = h1;
                __nv_bfloat162 lp; lp.x = l0; lp.y = l1;
                *reinterpret_cast<__nv_bfloat162*>(&Ah[off + j]) = hp;
                *reinterpret_cast<__nv_bfloat162*>(&Al[off + j]) = lp;
            }
        }
        // W: 32x256 = 2048 float4, 4 per thread
#pragma unroll
        for (int i = 0; i < 4; i++) {
            int idx = tid + i * 512;
            int k = idx >> 6, c4 = (idx & 63) * 4;
            int gk = k0 + k;
            float4 v = make_float4(0.f, 0.f, 0.f, 0.f);
            if (gk < K)
                v = *reinterpret_cast<const float4*>(W + (size_t)gk * N + c4);
            float vv[4] = {v.x, v.y, v.z, v.w};
#pragma unroll
            for (int j = 0; j < 4; j++) {
                __nv_bfloat16 h, l;
                split_bf16(vv[j], h, l);
                Bh[buf * L1_BSZ + (c4 + j) * BKP + k] = h;
                Bl[buf * L1_BSZ + (c4 + j) * BKP + k] = l;
            }
        }
    };

    auto compute = [&](int buf) {
        const __nv_bfloat16* ah_base = Ah + buf * L1_ASZ;
        const __nv_bfloat16* al_base = Al + buf * L1_ASZ;
        const __nv_bfloat16* bh_base = Bh + buf * L1_BSZ;
        const __nv_bfloat16* bl_base = Bl + buf * L1_BSZ;
#pragma unroll
        for (int ks = 0; ks < BK; ks += 16) {
            unsigned bh[4][2], bl[4][2];
#pragma unroll
            for (int nt = 0; nt < 4; nt++) {
                int nn = wn * 32 + nt * 8 + quad;
                int kk = ks + ql * 2;
                bh[nt][0] = *reinterpret_cast<const unsigned*>(&bh_base[nn * BKP + kk]);
                bh[nt][1] = *reinterpret_cast<const unsigned*>(&bh_base[nn * BKP + kk + 8]);
                bl[nt][0] = *reinterpret_cast<const unsigned*>(&bl_base[nn * BKP + kk]);
                bl[nt][1] = *reinterpret_cast<const unsigned*>(&bl_base[nn * BKP + kk + 8]);
            }
#pragma unroll
            for (int mt = 0; mt < 4; mt++) {
                int r = wm * 64 + mt * 16 + quad;
                int kk = ks + ql * 2;
                unsigned ah[4], al[4];
                ah[0] = *reinterpret_cast<const unsigned*>(&ah_base[r * BKP + kk]);
                ah[1] = *reinterpret_cast<const unsigned*>(&ah_base[(r + 8) * BKP + kk]);
                ah[2] = *reinterpret_cast<const unsigned*>(&ah_base[r * BKP + kk + 8]);
                ah[3] = *reinterpret_cast<const unsigned*>(&ah_base[(r + 8) * BKP + kk + 8]);
                al[0] = *reinterpret_cast<const unsigned*>(&al_base[r * BKP + kk]);
                al[1] = *reinterpret_cast<const unsigned*>(&al_base[(r + 8) * BKP + kk]);
                al[2] = *reinterpret_cast<const unsigned*>(&al_base[r * BKP + kk + 8]);
                al[3] = *reinterpret_cast<const unsigned*>(&al_base[(r + 8) * BKP + kk + 8]);
#pragma unroll
                for (int nt = 0; nt < 4; nt++) {
                    mma16816(acc[mt][nt], ah, bh[nt]);
                    mma16816(acc[mt][nt], ah, bl[nt]);
                    mma16816(acc[mt][nt], al, bh[nt]);
                }
            }
        }
    };

    loadstage(0, 0);
    __syncthreads();
    for (int ch = 0; ch < nch; ch++) {
        if (ch + 1 < nch) loadstage((ch + 1) * BK, (ch + 1) & 1);
        compute(ch & 1);
        __syncthreads();
    }

#pragma unroll
    for (int mt = 0; mt < 4; mt++) {
        int r0 = m0 + wm * 64 + mt * 16 + quad;
#pragma unroll
        for (int nt = 0; nt < 4; nt++) {
            int cc = wn * 32 + nt * 8 + ql * 2;
            float* p = acc[mt][nt];
            if (r0 < M)
                *reinterpret_cast<float2*>(C + (size_t)r0 * N + cc) = make_float2(p[0], p[1]);
            if (r0 + 8 < M)
                *reinterpret_cast<float2*>(C + (size_t)(r0 + 8) * N + cc) = make_float2(p[2], p[3]);
        }
    }
}

// ---------------------------------------------------------------------------
// Generic split-bf16 GEMM (layers 2/3): BM=128, BN in {64,128}, grid.x = 1.
// ---------------------------------------------------------------------------
#define BM 128

template <int AID, int BN, int CID, int T>
__global__ __launch_bounds__(T) void k_gemm_tc(
    const float* __restrict__ W, int M, int N, int K)
{
    const float* A = scratch<AID>();
    float* C = scratch<CID>();

    __shared__ __nv_bfloat16 Ahs[BM][BKP], Als[BM][BKP];
    __shared__ __nv_bfloat16 Bhs[BN][BKP], Bls[BN][BKP];

    const int tid = threadIdx.x;
    const int m0 = blockIdx.y * BM;
    const int n0 = blockIdx.x * BN;

    constexpr int NW_N = BN / 32;
    const int w = tid >> 5, lane = tid & 31;
    const int wm = w / NW_N, wn = w % NW_N;
    const int quad = lane >> 2, ql = lane & 3;

    constexpr int AF4 = (BM * BK / 4) / T;
    constexpr int WF4 = (BK * BN / 4) / T;
    constexpr int WF4PR = BN / 4;

    float4 aReg[AF4], wReg[WF4];
    float acc[4][4][4];
#pragma unroll
    for (int mt = 0; mt < 4; mt++)
#pragma unroll
        for (int nt = 0; nt < 4; nt++)
#pragma unroll
            for (int i = 0; i < 4; i++) acc[mt][nt][i] = 0.0f;

    const int nch = (K + BK - 1) / BK;

    auto loadA = [&](int k0) {
#pragma unroll
        for (int i = 0; i < AF4; i++) {
            int idx = tid + i * T;
            int r = idx >> 3, c4 = (idx & 7) * 4;
            int gm = m0 + r, gk = k0 + c4;
            float4 v = make_float4(0.f, 0.f, 0.f, 0.f);
            if (gm < M && gk + 3 < K)
                v = *reinterpret_cast<const float4*>(A + (size_t)gm * K + gk);
            aReg[i] = v;
        }
    };

    auto loadW = [&](int k0) {
#pragma unroll
        for (int i = 0; i < WF4; i++) {
            int idx = tid + i * T;
            int k = idx / WF4PR, c4 = (idx % WF4PR) * 4;
            int gk = k0 + k;
            float4 v = make_float4(0.f, 0.f, 0.f, 0.f);
            if (gk < K)
                v = *reinterpret_cast<const float4*>(W + (size_t)gk * N + n0 + c4);
            wReg[i] = v;
        }
    };

    auto stage = [&]() {
#pragma unroll
        for (int i = 0; i < AF4; i++) {
            int idx = tid + i * T;
            int r = idx >> 3, c = (idx & 7) * 4;
            float vv[4] = {aReg[i].x, aReg[i].y, aReg[i].z, aReg[i].w};
#pragma unroll
            for (int j = 0; j < 4; j += 2) {
                __nv_bfloat16 h0, l0, h1, l1;
                split_bf16(vv[j], h0, l0);
                split_bf16(vv[j + 1], h1, l1);
                __nv_bfloat162 hp; hp.x = h0; hp.y = h1;
                __nv_bfloat162 lp; lp.x = l0; lp.y = l1;
                *reinterpret_cast<__nv_bfloat162*>(&Ahs[r][c + j]) = hp;
                *reinterpret_cast<__nv_bfloat162*>(&Als[r][c + j]) = lp;
            }
        }
#pragma unroll
        for (int i = 0; i < WF4; i++) {
            int idx = tid + i * T;
            int k = idx / WF4PR, c = (idx % WF4PR) * 4;
            float vv[4] = {wReg[i].x, wReg[i].y, wReg[i].z, wReg[i].w};
#pragma unroll
            for (int j = 0; j < 4; j++) {
                __nv_bfloat16 h, l;
                split_bf16(vv[j], h, l);
                Bhs[c + j][k] = h;
                Bls[c + j][k] = l;
            }
        }
    };

    auto compute = [&]() {
#pragma unroll
        for (int ks = 0; ks < BK; ks += 16) {
            unsigned bh[4][2], bl[4][2];
#pragma unroll
            for (int nt = 0; nt < 4; nt++) {
                int nn = wn * 32 + nt * 8 + quad;
                int kk = ks + ql * 2;
                bh[nt][0] = *reinterpret_cast<const unsigned*>(&Bhs[nn][kk]);
                bh[nt][1] = *reinterpret_cast<const unsigned*>(&Bhs[nn][kk + 8]);
                bl[nt][0] = *reinterpret_cast<const unsigned*>(&Bls[nn][kk]);
                bl[nt][1] = *reinterpret_cast<const unsigned*>(&Bls[nn][kk + 8]);
            }
#pragma unroll
            for (int mt = 0; mt < 4; mt++) {
                int r = wm * 64 + mt * 16 + quad;
                int kk = ks + ql * 2;
                unsigned ah[4], al[4];
                ah[0] = *reinterpret_cast<const unsigned*>(&Ahs[r][kk]);
                ah[1] = *reinterpret_cast<const unsigned*>(&Ahs[r + 8][kk]);
                ah[2] = *reinterpret_cast<const unsigned*>(&Ahs[r][kk + 8]);
                ah[3] = *reinterpret_cast<const unsigned*>(&Ahs[r + 8][kk + 8]);
                al[0] = *reinterpret_cast<const unsigned*>(&Als[r][kk]);
                al[1] = *reinterpret_cast<const unsigned*>(&Als[r + 8][kk]);
                al[2] = *reinterpret_cast<const unsigned*>(&Als[r][kk + 8]);
                al[3] = *reinterpret_cast<const unsigned*>(&Als[r + 8][kk + 8]);
#pragma unroll
                for (int nt = 0; nt < 4; nt++) {
                    mma16816(acc[mt][nt], ah, bh[nt]);
                    mma16816(acc[mt][nt], ah, bl[nt]);
                    mma16816(acc[mt][nt], al, bh[nt]);
                }
            }
        }
    };

    loadA(0); loadW(0);
    for (int ch = 0; ch < nch; ch++) {
        __syncthreads();
        stage();
        __syncthreads();
        if (ch + 1 < nch) { loadA((ch + 1) * BK); loadW((ch + 1) * BK); }
        compute();
    }

#pragma unroll
    for (int mt = 0; mt < 4; mt++) {
        int r0 = m0 + wm * 64 + mt * 16 + quad;
#pragma unroll
        for (int nt = 0; nt < 4; nt++) {
            int cc = n0 + wn * 32 + nt * 8 + ql * 2;
            float* p = acc[mt][nt];
            if (r0 < M)
                *reinterpret_cast<float2*>(C + (size_t)r0 * N + cc) = make_float2(p[0], p[1]);
            if (r0 + 8 < M)
                *reinterpret_cast<float2*>(C + (size_t)(r0 + 8) * N + cc) = make_float2(p[2], p[3]);
        }
    }
}

// ---------------------------------------------------------------------------
// Fused CSR aggregation: one warp per dst node.
// ---------------------------------------------------------------------------
template <int HID, int GID, int F, bool RELU, bool HEAD>
__global__ __launch_bounds__(256) void k_aggregate(
    const float* __restrict__ bias,
    const float* __restrict__ Wl, const float* __restrict__ bl,
    float* __restrict__ out, int n)
{
    const float* h = scratch<HID>();
    constexpr int REP = F / 32;

    int warp_in_block = threadIdx.x >> 5;
    int lane = threadIdx.x & 31;
    int node = blockIdx.x * (blockDim.x >> 5) + warp_in_block;
    if (node >= n) return;

    float d = s_dis[node];
    float dsq = d * d;

    float acc[REP];
#pragma unroll
    for (int r = 0; r < REP; r++)
        acc[r] = h[(size_t)node * F + lane + r * 32] * dsq;

    int beg = s_rowptr[node];
    int end = s_rowptr[node + 1];
    for (int e = beg; e < end; e++) {
        int src = s_csr_src[e];
        float wgt = s_csr_w[e];
        const float* hr = h + (size_t)src * F;
#pragma unroll
        for (int r = 0; r < REP; r++)
            acc[r] = fmaf(hr[lane + r * 32], wgt, acc[r]);
    }

#pragma unroll
    for (int r = 0; r < REP; r++) {
        acc[r] += bias[lane + r * 32];
        if constexpr (RELU) acc[r] = fmaxf(acc[r], 0.0f);
    }

    if constexpr (!HEAD) {
        float* agg = scratch<GID>();
#pragma unroll
        for (int r = 0; r < REP; r++)
            agg[(size_t)node * F + lane + r * 32] = acc[r];
    } else {
        out[(size_t)n + (size_t)node * 64 + lane]      = acc[0];
        out[(size_t)n + (size_t)node * 64 + 32 + lane] = acc[1];
        float ss = acc[0] * Wl[lane] + acc[1] * Wl[32 + lane];
#pragma unroll
        for (int o = 16; o; o >>= 1) ss += __shfl_xor_sync(0xFFFFFFFFu, ss, o);
        if (lane == 0)
            out[node] = 1.0f / (1.0f + expf(-(ss + bl[0])));
    }
}

// ---------------------------------------------------------------------------
static inline int cdiv(long long a, long long b) { return (int)((a + b - 1) / b); }

extern "C" void kernel_launch(void* const* d_in, const int* in_sizes, int n_in,
                              void* d_out, int out_size)
{
    const float* x   = (const float*)d_in[0];
    const void*  ei  = d_in[1];
    const float* W1  = (const float*)d_in[2];
    const float* b1  = (const float*)d_in[3];
    const float* W2  = (const float*)d_in[4];
    const float* b2  = (const float*)d_in[5];
    const float* W3  = (const float*)d_in[6];
    const float* b3  = (const float*)d_in[7];
    const float* Wl  = (const float*)d_in[8];
    const float* bl  = (const float*)d_in[9];
    float* out = (float*)d_out;

    const int n = in_sizes[0] / D0;    // 50000
    const int E = in_sizes[1] / 2;     // 1600000

    cudaFuncSetAttribute(k_gemm_l1, cudaFuncAttributeMaxDynamicSharedMemorySize,
                         L1_SMEM_BYTES);

    int scan_words = (2 * E < 4096) ? 2 * E : 4096;
    k_detect_dtype<<<1, 256>>>((const int*)ei, scan_words);

    // CSR build
    k_deg_zero<<<cdiv(n, 256), 256>>>(n);
    k_deg_count<<<cdiv(E, 256), 256>>>(ei, E);
    k_dis<<<cdiv(n, 256), 256>>>(n);
    k_scan<<<1, 1024>>>(n);
    k_csr_fill<<<cdiv(E, 256), 256>>>(ei, E);

    const int MT = cdiv(n, BM);           // 391
    const int AGG_BLOCKS = cdiv(n, 8);

    // ---- Layer 1: gemm x@W1 -> A ; fused agg+b1+relu -> B ----
    k_gemm_l1<<<dim3(1, MT), 512, L1_SMEM_BYTES>>>(x, W1, n);
    k_aggregate<0, 1, D1, true, false><<<AGG_BLOCKS, 256>>>(b1, nullptr, nullptr, nullptr, n);

    // ---- Layer 2: gemm B@W2 -> A ; fused agg+b2 -> B ----
    k_gemm_tc<1, 128, 0, 256><<<dim3(1, MT), 256>>>(W2, n, D2, D1);
    k_aggregate<0, 1, D2, false, false><<<AGG_BLOCKS, 256>>>(b2, nullptr, nullptr, nullptr, n);

    // ---- Layer 3: gemm B@W3 -> A ; fused agg+b3+head -> out ----
    k_gemm_tc<1, 64, 0, 128><<<dim3(1, MT), 128>>>(W3, n, D3, D2);
    k_aggregate<0, 1, D3, false, true><<<AGG_BLOCKS, 256>>>(b3, Wl, bl, out, n);
}

// round 11
// speedup vs baseline: 2.7584x; 1.1199x over previous
#include <cuda_runtime.h>
#include <cuda_bf16.h>
#include <cuda_fp16.h>
#include <math.h>

// Fixed problem shapes
#define NNODES 50000
#define D0 3000
#define D1 256
#define D2 128
#define D3 64
#define ECAP 1600000

// Static scratch (allocation-free rule). Device-code access only.
__device__ __align__(16) float s_bufA[NNODES * D1];   // 51.2 MB
__device__ __align__(16) float s_bufB[NNODES * D1];   // 51.2 MB
__device__ int   s_deg[NNODES];
__device__ float s_dis[NNODES];
__device__ int   s_rowptr[NNODES + 1];
__device__ int   s_cnt[NNODES];
__device__ int   s_csr_src[ECAP];
__device__ float s_csr_w[ECAP];
__device__ int   s_is64;

template <int ID>
__device__ __forceinline__ float* scratch() {
    if constexpr (ID == 0) return s_bufA;
    else return s_bufB;
}

__device__ __forceinline__ int edge_at(const void* ei, long long idx, int is64) {
    if (is64) return (int)((const long long*)ei)[idx];
    return ((const int*)ei)[idx];
}

__device__ __forceinline__ void split_bf16(float v, __nv_bfloat16& h, __nv_bfloat16& l) {
    h = __float2bfloat16(v);
    l = __float2bfloat16(v - __bfloat162float(h));
}

__device__ __forceinline__ void split_fp16(float v, __half& h, __half& l) {
    h = __float2half_rn(v);
    l = __float2half_rn(v - __half2float(h));
}

// ---------------------------------------------------------------------------
// Edge dtype detection
// ---------------------------------------------------------------------------
__global__ void k_detect_dtype(const int* __restrict__ ei_words, int nwords)
{
    __shared__ int found_nonzero;
    if (threadIdx.x == 0) found_nonzero = 0;
    __syncthreads();
    for (int w = 1 + 2 * threadIdx.x; w < nwords; w += 2 * blockDim.x) {
        if (ei_words[w] != 0) { found_nonzero = 1; break; }
    }
    __syncthreads();
    if (threadIdx.x == 0) s_is64 = found_nonzero ? 0 : 1;
}

// ---------------------------------------------------------------------------
// Degree / normalization / CSR build
// ---------------------------------------------------------------------------
__global__ void k_deg_zero(int n) {
    int i = blockIdx.x * blockDim.x + threadIdx.x;
    if (i < n) s_deg[i] = 0;
}

__global__ void k_deg_count(const void* __restrict__ ei, int E) {
    int e = blockIdx.x * blockDim.x + threadIdx.x;
    if (e < E) {
        int is64 = s_is64;
        int d = edge_at(ei, (long long)E + e, is64);
        if ((unsigned)d < (unsigned)NNODES) atomicAdd(&s_deg[d], 1);
    }
}

__global__ void k_dis(int n) {
    int i = blockIdx.x * blockDim.x + threadIdx.x;
    if (i < n) s_dis[i] = rsqrtf((float)s_deg[i] + 1.0f);
}

__global__ __launch_bounds__(1024) void k_scan(int n)
{
    __shared__ int sh[1024];
    __shared__ int carry_sh;
    if (threadIdx.x == 0) carry_sh = 0;
    __syncthreads();
    for (int base = 0; base < n; base += 1024) {
        int i = base + (int)threadIdx.x;
        int v = (i < n) ? s_deg[i] : 0;
        sh[threadIdx.x] = v;
        __syncthreads();
#pragma unroll
        for (int off = 1; off < 1024; off <<= 1) {
            int t = (threadIdx.x >= off) ? sh[threadIdx.x - off] : 0;
            __syncthreads();
            sh[threadIdx.x] += t;
            __syncthreads();
        }
        int incl = sh[threadIdx.x];
        int excl = incl - v;
        int carry = carry_sh;
        if (i < n) {
            s_rowptr[i] = carry + excl;
            s_cnt[i]    = carry + excl;
        }
        __syncthreads();
        if (threadIdx.x == 1023) carry_sh = carry + incl;
        __syncthreads();
    }
    if (threadIdx.x == 0) s_rowptr[n] = carry_sh;
}

__global__ void k_csr_fill(const void* __restrict__ ei, int E)
{
    int e = blockIdx.x * blockDim.x + threadIdx.x;
    if (e >= E) return;
    int is64 = s_is64;
    int s = edge_at(ei, e, is64);
    int d = edge_at(ei, (long long)E + e, is64);
    if ((unsigned)s >= (unsigned)NNODES || (unsigned)d >= (unsigned)NNODES) return;
    int pos = atomicAdd(&s_cnt[d], 1);
    if (pos < ECAP) {
        s_csr_src[pos] = s;
        s_csr_w[pos]   = s_dis[s] * s_dis[d];
    }
}

// ---------------------------------------------------------------------------
// mma helpers
// ---------------------------------------------------------------------------
__device__ __forceinline__ void mma16816bf(float* c, const unsigned* a, const unsigned* b) {
    asm volatile(
        "mma.sync.aligned.m16n8k16.row.col.f32.bf16.bf16.f32 "
        "{%0,%1,%2,%3}, {%4,%5,%6,%7}, {%8,%9}, {%0,%1,%2,%3};\n"
        : "+f"(c[0]), "+f"(c[1]), "+f"(c[2]), "+f"(c[3])
        : "r"(a[0]), "r"(a[1]), "r"(a[2]), "r"(a[3]), "r"(b[0]), "r"(b[1]));
}

__device__ __forceinline__ void mma16816fp(float* c, const unsigned* a, const unsigned* b) {
    asm volatile(
        "mma.sync.aligned.m16n8k16.row.col.f32.f16.f16.f32 "
        "{%0,%1,%2,%3}, {%4,%5,%6,%7}, {%8,%9}, {%0,%1,%2,%3};\n"
        : "+f"(c[0]), "+f"(c[1]), "+f"(c[2]), "+f"(c[3])
        : "r"(a[0]), "r"(a[1]), "r"(a[2]), "r"(a[3]), "r"(b[0]), "r"(b[1]));
}

// ---------------------------------------------------------------------------
// Layer-1 GEMM: C[M,256] = A[M,3000] @ W[3000,256].  fp16 TWO-pass split:
//   C = ah*bh + ah*bl   (a rounded to fp16; b split hi/lo fp16)
// BM=128, BN=256 (A staged once), BK=32, T=512 (16 warps 2x8),
// warp tile 64x32, double-buffered dynamic SMEM.
// ---------------------------------------------------------------------------
#define BK 32
#define BKP 34   // padded SMEM row stride (fp16/bf16 elems); 34*2=68B, 4B-aligned
#define L1_ASZ (128 * BKP)
#define L1_BSZ (256 * BKP)
#define L1_SMEM_BYTES ((2 * L1_ASZ + 2 * L1_BSZ + 2 * L1_BSZ) * 2)  // 87040

__global__ __launch_bounds__(512) void k_gemm_l1(
    const float* __restrict__ A, const float* __restrict__ W, int M)
{
    const int N = 256, K = 3000;
    float* C = s_bufA;

    extern __shared__ __half dsm_l1[];
    __half* Ah = dsm_l1;                  // [2][128][BKP]   (hi only)
    __half* Bh = Ah + 2 * L1_ASZ;         // [2][256][BKP]   (transposed [n][k])
    __half* Bl = Bh + 2 * L1_BSZ;

    const int tid = threadIdx.x;
    const int m0 = blockIdx.y * 128;
    const int w = tid >> 5, lane = tid & 31;
    const int wm = w >> 3, wn = w & 7;    // 2 x 8 warp grid
    const int quad = lane >> 2, ql = lane & 3;

    float acc[4][4][4];
#pragma unroll
    for (int mt = 0; mt < 4; mt++)
#pragma unroll
        for (int nt = 0; nt < 4; nt++)
#pragma unroll
            for (int i = 0; i < 4; i++) acc[mt][nt][i] = 0.0f;

    const int nch = (K + BK - 1) / BK;   // 94

    auto loadstage = [&](int k0, int buf) {
        // A: 128x32 = 1024 float4, 2 per thread -> fp16 hi only
#pragma unroll
        for (int i = 0; i < 2; i++) {
            int idx = tid + i * 512;
            int r = idx >> 3, c4 = (idx & 7) * 4;
            int gm = m0 + r, gk = k0 + c4;
            float4 v = make_float4(0.f, 0.f, 0.f, 0.f);
            if (gm < M) {
                const float* base = A + (size_t)gm * K;
                if (gk + 3 < K) {
                    v = *reinterpret_cast<const float4*>(base + gk);
                } else {
                    if (gk + 0 < K) v.x = base[gk + 0];
                    if (gk + 1 < K) v.y = base[gk + 1];
                    if (gk + 2 < K) v.z = base[gk + 2];
                    if (gk + 3 < K) v.w = base[gk + 3];
                }
            }
            float vv[4];
            vv[0] = v.x; vv[1] = v.y; vv[2] = v.z; vv[3] = v.w;
            __half* arow = Ah + buf * L1_ASZ + r * BKP + c4;
#pragma unroll
            for (int j = 0; j < 4; j += 2) {
                __half2 hp;
                hp.x = __float2half_rn(vv[j]);
                hp.y = __float2half_rn(vv[j + 1]);
                *reinterpret_cast<__half2*>(arow + j) = hp;
            }
        }
        // W: 32x256 = 2048 float4, 4 per thread -> fp16 hi/lo, transposed [n][k]
#pragma unroll
        for (int i = 0; i < 4; i++) {
            int idx = tid + i * 512;
            int k = idx >> 6, c4 = (idx & 63) * 4;
            int gk = k0 + k;
            float4 v = make_float4(0.f, 0.f, 0.f, 0.f);
            if (gk < K)
                v = *reinterpret_cast<const float4*>(W + (size_t)gk * N + c4);
            float vv[4];
            vv[0] = v.x; vv[1] = v.y; vv[2] = v.z; vv[3] = v.w;
#pragma unroll
            for (int j = 0; j < 4; j++) {
                __half h, l;
                split_fp16(vv[j], h, l);
                Bh[buf * L1_BSZ + (c4 + j) * BKP + k] = h;
                Bl[buf * L1_BSZ + (c4 + j) * BKP + k] = l;
            }
        }
    };

    auto compute = [&](int buf) {
        const __half* ah_base = Ah + buf * L1_ASZ;
        const __half* bh_base = Bh + buf * L1_BSZ;
        const __half* bl_base = Bl + buf * L1_BSZ;
#pragma unroll
        for (int ks = 0; ks < BK; ks += 16) {
            unsigned bh[4][2], bl[4][2];
#pragma unroll
            for (int nt = 0; nt < 4; nt++) {
                int nn = wn * 32 + nt * 8 + quad;
                int kk = ks + ql * 2;
                bh[nt][0] = *reinterpret_cast<const unsigned*>(&bh_base[nn * BKP + kk]);
                bh[nt][1] = *reinterpret_cast<const unsigned*>(&bh_base[nn * BKP + kk + 8]);
                bl[nt][0] = *reinterpret_cast<const unsigned*>(&bl_base[nn * BKP + kk]);
                bl[nt][1] = *reinterpret_cast<const unsigned*>(&bl_base[nn * BKP + kk + 8]);
            }
#pragma unroll
            for (int mt = 0; mt < 4; mt++) {
                int r = wm * 64 + mt * 16 + quad;
                int kk = ks + ql * 2;
                unsigned ah[4];
                ah[0] = *reinterpret_cast<const unsigned*>(&ah_base[r * BKP + kk]);
                ah[1] = *reinterpret_cast<const unsigned*>(&ah_base[(r + 8) * BKP + kk]);
                ah[2] = *reinterpret_cast<const unsigned*>(&ah_base[r * BKP + kk + 8]);
                ah[3] = *reinterpret_cast<const unsigned*>(&ah_base[(r + 8) * BKP + kk + 8]);
#pragma unroll
                for (int nt = 0; nt < 4; nt++) {
                    mma16816fp(acc[mt][nt], ah, bh[nt]);
                    mma16816fp(acc[mt][nt], ah, bl[nt]);
                }
            }
        }
    };

    loadstage(0, 0);
    __syncthreads();
    for (int ch = 0; ch < nch; ch++) {
        if (ch + 1 < nch) loadstage((ch + 1) * BK, (ch + 1) & 1);
        compute(ch & 1);
        __syncthreads();
    }

#pragma unroll
    for (int mt = 0; mt < 4; mt++) {
        int r0 = m0 + wm * 64 + mt * 16 + quad;
#pragma unroll
        for (int nt = 0; nt < 4; nt++) {
            int cc = wn * 32 + nt * 8 + ql * 2;
            float* p = acc[mt][nt];
            if (r0 < M)
                *reinterpret_cast<float2*>(C + (size_t)r0 * N + cc) = make_float2(p[0], p[1]);
            if (r0 + 8 < M)
                *reinterpret_cast<float2*>(C + (size_t)(r0 + 8) * N + cc) = make_float2(p[2], p[3]);
        }
    }
}

// ---------------------------------------------------------------------------
// Generic split-bf16 3-pass GEMM (layers 2/3): BM=128, BN in {64,128}.
// ---------------------------------------------------------------------------
#define BM 128

template <int AID, int BN, int CID, int T>
__global__ __launch_bounds__(T) void k_gemm_tc(
    const float* __restrict__ W, int M, int N, int K)
{
    const float* A = scratch<AID>();
    float* C = scratch<CID>();

    __shared__ __nv_bfloat16 Ahs[BM][BKP], Als[BM][BKP];
    __shared__ __nv_bfloat16 Bhs[BN][BKP], Bls[BN][BKP];

    const int tid = threadIdx.x;
    const int m0 = blockIdx.y * BM;
    const int n0 = blockIdx.x * BN;

    constexpr int NW_N = BN / 32;
    const int w = tid >> 5, lane = tid & 31;
    const int wm = w / NW_N, wn = w % NW_N;
    const int quad = lane >> 2, ql = lane & 3;

    constexpr int AF4 = (BM * BK / 4) / T;
    constexpr int WF4 = (BK * BN / 4) / T;
    constexpr int WF4PR = BN / 4;

    float4 aReg[AF4], wReg[WF4];
    float acc[4][4][4];
#pragma unroll
    for (int mt = 0; mt < 4; mt++)
#pragma unroll
        for (int nt = 0; nt < 4; nt++)
#pragma unroll
            for (int i = 0; i < 4; i++) acc[mt][nt][i] = 0.0f;

    const int nch = (K + BK - 1) / BK;

    auto loadA = [&](int k0) {
#pragma unroll
        for (int i = 0; i < AF4; i++) {
            int idx = tid + i * T;
            int r = idx >> 3, c4 = (idx & 7) * 4;
            int gm = m0 + r, gk = k0 + c4;
            float4 v = make_float4(0.f, 0.f, 0.f, 0.f);
            if (gm < M && gk + 3 < K)
                v = *reinterpret_cast<const float4*>(A + (size_t)gm * K + gk);
            aReg[i] = v;
        }
    };

    auto loadW = [&](int k0) {
#pragma unroll
        for (int i = 0; i < WF4; i++) {
            int idx = tid + i * T;
            int k = idx / WF4PR, c4 = (idx % WF4PR) * 4;
            int gk = k0 + k;
            float4 v = make_float4(0.f, 0.f, 0.f, 0.f);
            if (gk < K)
                v = *reinterpret_cast<const float4*>(W + (size_t)gk * N + n0 + c4);
            wReg[i] = v;
        }
    };

    auto stage = [&]() {
#pragma unroll
        for (int i = 0; i < AF4; i++) {
            int idx = tid + i * T;
            int r = idx >> 3, c = (idx & 7) * 4;
            float vv[4];
            vv[0] = aReg[i].x; vv[1] = aReg[i].y; vv[2] = aReg[i].z; vv[3] = aReg[i].w;
#pragma unroll
            for (int j = 0; j < 4; j += 2) {
                __nv_bfloat16 h0, l0, h1, l1;
                split_bf16(vv[j], h0, l0);
                split_bf16(vv[j + 1], h1, l1);
                __nv_bfloat162 hp; hp.x = h0; hp.y = h1;
                __nv_bfloat162 lp; lp.x = l0; lp.y = l1;
                *reinterpret_cast<__nv_bfloat162*>(&Ahs[r][c + j]) = hp;
                *reinterpret_cast<__nv_bfloat162*>(&Als[r][c + j]) = lp;
            }
        }
#pragma unroll
        for (int i = 0; i < WF4; i++) {
            int idx = tid + i * T;
            int k = idx / WF4PR, c = (idx % WF4PR) * 4;
            float vv[4];
            vv[0] = wReg[i].x; vv[1] = wReg[i].y; vv[2] = wReg[i].z; vv[3] = wReg[i].w;
#pragma unroll
            for (int j = 0; j < 4; j++) {
                __nv_bfloat16 h, l;
                split_bf16(vv[j], h, l);
                Bhs[c + j][k] = h;
                Bls[c + j][k] = l;
            }
        }
    };

    auto compute = [&]() {
#pragma unroll
        for (int ks = 0; ks < BK; ks += 16) {
            unsigned bh[4][2], bl[4][2];
#pragma unroll
            for (int nt = 0; nt < 4; nt++) {
                int nn = wn * 32 + nt * 8 + quad;
                int kk = ks + ql * 2;
                bh[nt][0] = *reinterpret_cast<const unsigned*>(&Bhs[nn][kk]);
                bh[nt][1] = *reinterpret_cast<const unsigned*>(&Bhs[nn][kk + 8]);
                bl[nt][0] = *reinterpret_cast<const unsigned*>(&Bls[nn][kk]);
                bl[nt][1] = *reinterpret_cast<const unsigned*>(&Bls[nn][kk + 8]);
            }
#pragma unroll
            for (int mt = 0; mt < 4; mt++) {
                int r = wm * 64 + mt * 16 + quad;
                int kk = ks + ql * 2;
                unsigned ah[4], al[4];
                ah[0] = *reinterpret_cast<const unsigned*>(&Ahs[r][kk]);
                ah[1] = *reinterpret_cast<const unsigned*>(&Ahs[r + 8][kk]);
                ah[2] = *reinterpret_cast<const unsigned*>(&Ahs[r][kk + 8]);
                ah[3] = *reinterpret_cast<const unsigned*>(&Ahs[r + 8][kk + 8]);
                al[0] = *reinterpret_cast<const unsigned*>(&Als[r][kk]);
                al[1] = *reinterpret_cast<const unsigned*>(&Als[r + 8][kk]);
                al[2] = *reinterpret_cast<const unsigned*>(&Als[r][kk + 8]);
                al[3] = *reinterpret_cast<const unsigned*>(&Als[r + 8][kk + 8]);
#pragma unroll
                for (int nt = 0; nt < 4; nt++) {
                    mma16816bf(acc[mt][nt], ah, bh[nt]);
                    mma16816bf(acc[mt][nt], ah, bl[nt]);
                    mma16816bf(acc[mt][nt], al, bh[nt]);
                }
            }
        }
    };

    loadA(0); loadW(0);
    for (int ch = 0; ch < nch; ch++) {
        __syncthreads();
        stage();
        __syncthreads();
        if (ch + 1 < nch) { loadA((ch + 1) * BK); loadW((ch + 1) * BK); }
        compute();
    }

#pragma unroll
    for (int mt = 0; mt < 4; mt++) {
        int r0 = m0 + wm * 64 + mt * 16 + quad;
#pragma unroll
        for (int nt = 0; nt < 4; nt++) {
            int cc = n0 + wn * 32 + nt * 8 + ql * 2;
            float* p = acc[mt][nt];
            if (r0 < M)
                *reinterpret_cast<float2*>(C + (size_t)r0 * N + cc) = make_float2(p[0], p[1]);
            if (r0 + 8 < M)
                *reinterpret_cast<float2*>(C + (size_t)(r0 + 8) * N + cc) = make_float2(p[2], p[3]);
        }
    }
}

// ---------------------------------------------------------------------------
// Fused CSR aggregation: one warp per dst node.
// ---------------------------------------------------------------------------
template <int HID, int GID, int F, bool RELU, bool HEAD>
__global__ __launch_bounds__(256) void k_aggregate(
    const float* __restrict__ bias,
    const float* __restrict__ Wl, const float* __restrict__ bl,
    float* __restrict__ out, int n)
{
    const float* h = scratch<HID>();
    constexpr int REP = F / 32;

    int warp_in_block = threadIdx.x >> 5;
    int lane = threadIdx.x & 31;
    int node = blockIdx.x * (blockDim.x >> 5) + warp_in_block;
    if (node >= n) return;

    float d = s_dis[node];
    float dsq = d * d;

    float acc[REP];
#pragma unroll
    for (int r = 0; r < REP; r++)
        acc[r] = h[(size_t)node * F + lane + r * 32] * dsq;

    int beg = s_rowptr[node];
    int end = s_rowptr[node + 1];
    for (int e = beg; e < end; e++) {
        int src = s_csr_src[e];
        float wgt = s_csr_w[e];
        const float* hr = h + (size_t)src * F;
#pragma unroll
        for (int r = 0; r < REP; r++)
            acc[r] = fmaf(hr[lane + r * 32], wgt, acc[r]);
    }

#pragma unroll
    for (int r = 0; r < REP; r++) {
        acc[r] += bias[lane + r * 32];
        if constexpr (RELU) acc[r] = fmaxf(acc[r], 0.0f);
    }

    if constexpr (!HEAD) {
        float* agg = scratch<GID>();
#pragma unroll
        for (int r = 0; r < REP; r++)
            agg[(size_t)node * F + lane + r * 32] = acc[r];
    } else {
        out[(size_t)n + (size_t)node * 64 + lane]      = acc[0];
        out[(size_t)n + (size_t)node * 64 + 32 + lane] = acc[1];
        float ss = acc[0] * Wl[lane] + acc[1] * Wl[32 + lane];
#pragma unroll
        for (int o = 16; o; o >>= 1) ss += __shfl_xor_sync(0xFFFFFFFFu, ss, o);
        if (lane == 0)
            out[node] = 1.0f / (1.0f + expf(-(ss + bl[0])));
    }
}

// ---------------------------------------------------------------------------
static inline int cdiv(long long a, long long b) { return (int)((a + b - 1) / b); }

extern "C" void kernel_launch(void* const* d_in, const int* in_sizes, int n_in,
                              void* d_out, int out_size)
{
    const float* x   = (const float*)d_in[0];
    const void*  ei  = d_in[1];
    const float* W1  = (const float*)d_in[2];
    const float* b1  = (const float*)d_in[3];
    const float* W2  = (const float*)d_in[4];
    const float* b2  = (const float*)d_in[5];
    const float* W3  = (const float*)d_in[6];
    const float* b3  = (const float*)d_in[7];
    const float* Wl  = (const float*)d_in[8];
    const float* bl  = (const float*)d_in[9];
    float* out = (float*)d_out;

    const int n = in_sizes[0] / D0;    // 50000
    const int E = in_sizes[1] / 2;     // 1600000

    cudaFuncSetAttribute(k_gemm_l1, cudaFuncAttributeMaxDynamicSharedMemorySize,
                         L1_SMEM_BYTES);

    int scan_words = (2 * E < 4096) ? 2 * E : 4096;
    const int MT = cdiv(n, BM);           // 391
    const int AGG_BLOCKS = cdiv(n, 8);

    // k_gemm_l1 placed at stream launch index 3 (ncu sampling window).
    k_detect_dtype<<<1, 256>>>((const int*)ei, scan_words);                   // 0
    k_deg_zero<<<cdiv(n, 256), 256>>>(n);                                     // 1
    k_deg_count<<<cdiv(E, 256), 256>>>(ei, E);                                // 2
    k_gemm_l1<<<dim3(1, MT), 512, L1_SMEM_BYTES>>>(x, W1, n);                 // 3
    k_dis<<<cdiv(n, 256), 256>>>(n);                                          // 4
    k_scan<<<1, 1024>>>(n);                                                   // 5
    k_csr_fill<<<cdiv(E, 256), 256>>>(ei, E);                                 // 6

    // ---- Layer 1 agg: s_bufA -> s_bufB (+b1, relu) ----
    k_aggregate<0, 1, D1, true, false><<<AGG_BLOCKS, 256>>>(b1, nullptr, nullptr, nullptr, n);

    // ---- Layer 2: gemm B@W2 -> A ; agg -> B ----
    k_gemm_tc<1, 128, 0, 256><<<dim3(1, MT), 256>>>(W2, n, D2, D1);
    k_aggregate<0, 1, D2, false, false><<<AGG_BLOCKS, 256>>>(b2, nullptr, nullptr, nullptr, n);

    // ---- Layer 3: gemm B@W3 -> A ; agg -> out (head fused) ----
    k_gemm_tc<1, 64, 0, 128><<<dim3(1, MT), 128>>>(W3, n, D3, D2);
    k_aggregate<0, 1, D3, false, true><<<AGG_BLOCKS, 256>>>(b3, Wl, bl, out, n);
}

// round 12
// speedup vs baseline: 3.3364x; 1.2096x over previous
#include <cuda_runtime.h>
#include <cuda_bf16.h>
#include <cuda_fp16.h>
#include <math.h>

// Fixed problem shapes
#define NNODES 50000
#define D0 3000
#define D1 256
#define D2 128
#define D3 64
#define ECAP 1600000

#define L1_KP 3008   // W1 table K padded to multiple of 64

// Static scratch (allocation-free rule). Device-code access only.
__device__ __align__(16) float  s_bufA[NNODES * D1];     // 51.2 MB (g buffers, fp32)
__device__ __align__(16) float  s_bufB[NNODES * D1];     // 51.2 MB
__device__ __align__(16) __half s_h16[NNODES * D1];      // 25.6 MB (GEMM outputs, fp16)
__device__ __align__(16) __half s_w1h[D1 * L1_KP];       // 1.5 MB  W1^T hi [n][k]
__device__ __align__(16) __half s_w1l[D1 * L1_KP];       // 1.5 MB  W1^T lo
__device__ int   s_deg[NNODES];
__device__ float s_dis[NNODES];
__device__ int   s_rowptr[NNODES + 1];
__device__ int   s_cnt[NNODES];
__device__ int   s_csr_src[ECAP];
__device__ float s_csr_w[ECAP];
__device__ int   s_is64;

template <int ID>
__device__ __forceinline__ float* scratch() {
    if constexpr (ID == 0) return s_bufA;
    else return s_bufB;
}

__device__ __forceinline__ int edge_at(const void* ei, long long idx, int is64) {
    if (is64) return (int)((const long long*)ei)[idx];
    return ((const int*)ei)[idx];
}

__device__ __forceinline__ void split_bf16(float v, __nv_bfloat16& h, __nv_bfloat16& l) {
    h = __float2bfloat16(v);
    l = __float2bfloat16(v - __bfloat162float(h));
}

__device__ __forceinline__ void split_fp16(float v, __half& h, __half& l) {
    h = __float2half_rn(v);
    l = __float2half_rn(v - __half2float(h));
}

// ---------------------------------------------------------------------------
// Edge dtype detection
// ---------------------------------------------------------------------------
__global__ void k_detect_dtype(const int* __restrict__ ei_words, int nwords)
{
    __shared__ int found_nonzero;
    if (threadIdx.x == 0) found_nonzero = 0;
    __syncthreads();
    for (int w = 1 + 2 * threadIdx.x; w < nwords; w += 2 * blockDim.x) {
        if (ei_words[w] != 0) { found_nonzero = 1; break; }
    }
    __syncthreads();
    if (threadIdx.x == 0) s_is64 = found_nonzero ? 0 : 1;
}

// ---------------------------------------------------------------------------
// W1 pre-transpose + fp16 hi/lo split: tables [n][k], zero-padded to L1_KP
// ---------------------------------------------------------------------------
__global__ void k_w1t(const float* __restrict__ W1)
{
    int idx = blockIdx.x * blockDim.x + threadIdx.x;
    if (idx >= D1 * L1_KP) return;
    int k = idx >> 8;          // 0..3007  (coalesced gmem reads along n)
    int n = idx & 255;
    float v = (k < D0) ? W1[(size_t)k * D1 + n] : 0.0f;
    __half h, l;
    split_fp16(v, h, l);
    s_w1h[(size_t)n * L1_KP + k] = h;
    s_w1l[(size_t)n * L1_KP + k] = l;
}

// ---------------------------------------------------------------------------
// Degree / normalization / CSR build
// ---------------------------------------------------------------------------
__global__ void k_deg_zero(int n) {
    int i = blockIdx.x * blockDim.x + threadIdx.x;
    if (i < n) s_deg[i] = 0;
}

__global__ void k_deg_count(const void* __restrict__ ei, int E) {
    int e = blockIdx.x * blockDim.x + threadIdx.x;
    if (e < E) {
        int is64 = s_is64;
        int d = edge_at(ei, (long long)E + e, is64);
        if ((unsigned)d < (unsigned)NNODES) atomicAdd(&s_deg[d], 1);
    }
}

__global__ void k_dis(int n) {
    int i = blockIdx.x * blockDim.x + threadIdx.x;
    if (i < n) s_dis[i] = rsqrtf((float)s_deg[i] + 1.0f);
}

__global__ __launch_bounds__(1024) void k_scan(int n)
{
    __shared__ int sh[1024];
    __shared__ int carry_sh;
    if (threadIdx.x == 0) carry_sh = 0;
    __syncthreads();
    for (int base = 0; base < n; base += 1024) {
        int i = base + (int)threadIdx.x;
        int v = (i < n) ? s_deg[i] : 0;
        sh[threadIdx.x] = v;
        __syncthreads();
#pragma unroll
        for (int off = 1; off < 1024; off <<= 1) {
            int t = (threadIdx.x >= off) ? sh[threadIdx.x - off] : 0;
            __syncthreads();
            sh[threadIdx.x] += t;
            __syncthreads();
        }
        int incl = sh[threadIdx.x];
        int excl = incl - v;
        int carry = carry_sh;
        if (i < n) {
            s_rowptr[i] = carry + excl;
            s_cnt[i]    = carry + excl;
        }
        __syncthreads();
        if (threadIdx.x == 1023) carry_sh = carry + incl;
        __syncthreads();
    }
    if (threadIdx.x == 0) s_rowptr[n] = carry_sh;
}

__global__ void k_csr_fill(const void* __restrict__ ei, int E)
{
    int e = blockIdx.x * blockDim.x + threadIdx.x;
    if (e >= E) return;
    int is64 = s_is64;
    int s = edge_at(ei, e, is64);
    int d = edge_at(ei, (long long)E + e, is64);
    if ((unsigned)s >= (unsigned)NNODES || (unsigned)d >= (unsigned)NNODES) return;
    int pos = atomicAdd(&s_cnt[d], 1);
    if (pos < ECAP) {
        s_csr_src[pos] = s;
        s_csr_w[pos]   = s_dis[s] * s_dis[d];
    }
}

// ---------------------------------------------------------------------------
// mma helpers
// ---------------------------------------------------------------------------
__device__ __forceinline__ void mma16816bf(float* c, const unsigned* a, const unsigned* b) {
    asm volatile(
        "mma.sync.aligned.m16n8k16.row.col.f32.bf16.bf16.f32 "
        "{%0,%1,%2,%3}, {%4,%5,%6,%7}, {%8,%9}, {%0,%1,%2,%3};\n"
        : "+f"(c[0]), "+f"(c[1]), "+f"(c[2]), "+f"(c[3])
        : "r"(a[0]), "r"(a[1]), "r"(a[2]), "r"(a[3]), "r"(b[0]), "r"(b[1]));
}

__device__ __forceinline__ void mma16816fp(float* c, const unsigned* a, const unsigned* b) {
    asm volatile(
        "mma.sync.aligned.m16n8k16.row.col.f32.f16.f16.f32 "
        "{%0,%1,%2,%3}, {%4,%5,%6,%7}, {%8,%9}, {%0,%1,%2,%3};\n"
        : "+f"(c[0]), "+f"(c[1]), "+f"(c[2]), "+f"(c[3])
        : "r"(a[0]), "r"(a[1]), "r"(a[2]), "r"(a[3]), "r"(b[0]), "r"(b[1]));
}

// ---------------------------------------------------------------------------
// Layer-1 GEMM: h1[M,256] (fp16) = A[M,3000] @ W1.  fp16 two-pass split.
// BM=128, BN=256, BK=32, T=512 (16 warps 2x8), warp tile 64x32,
// double-buffered SMEM, BKP=40 (conflict-free 8x4 quad fragment loads).
// B comes pre-transposed/pre-split from s_w1h/s_w1l (uint4 staging copies).
// ---------------------------------------------------------------------------
#define BK 32
#define BKP 40   // padded SMEM row stride in halfs: 20 words -> all-32-bank quad map
#define L1_ASZ (128 * BKP)
#define L1_BSZ (256 * BKP)
#define L1_SMEM_BYTES ((2 * L1_ASZ + 2 * L1_BSZ + 2 * L1_BSZ) * 2)  // 102400

__global__ __launch_bounds__(512) void k_gemm_l1(
    const float* __restrict__ A, int M)
{
    const int N = 256, K = 3000;

    extern __shared__ __half dsm_l1[];
    __half* Ah = dsm_l1;                  // [2][128][BKP]   (hi only)
    __half* Bh = Ah + 2 * L1_ASZ;         // [2][256][BKP]   ([n][k])
    __half* Bl = Bh + 2 * L1_BSZ;

    const int tid = threadIdx.x;
    const int m0 = blockIdx.y * 128;
    const int w = tid >> 5, lane = tid & 31;
    const int wm = w >> 3, wn = w & 7;    // 2 x 8 warp grid
    const int quad = lane >> 2, ql = lane & 3;

    float acc[4][4][4];
#pragma unroll
    for (int mt = 0; mt < 4; mt++)
#pragma unroll
        for (int nt = 0; nt < 4; nt++)
#pragma unroll
            for (int i = 0; i < 4; i++) acc[mt][nt][i] = 0.0f;

    const int nch = (K + BK - 1) / BK;   // 94

    auto loadstage = [&](int k0, int buf) {
        // A: 128x32 fp32 = 1024 float4, 2 per thread -> fp16 hi only
#pragma unroll
        for (int i = 0; i < 2; i++) {
            int idx = tid + i * 512;
            int r = idx >> 3, c4 = (idx & 7) * 4;
            int gm = m0 + r, gk = k0 + c4;
            float4 v = make_float4(0.f, 0.f, 0.f, 0.f);
            if (gm < M) {
                const float* base = A + (size_t)gm * K;
                if (gk + 3 < K) {
                    v = *reinterpret_cast<const float4*>(base + gk);
                } else {
                    if (gk + 0 < K) v.x = base[gk + 0];
                    if (gk + 1 < K) v.y = base[gk + 1];
                    if (gk + 2 < K) v.z = base[gk + 2];
                    if (gk + 3 < K) v.w = base[gk + 3];
                }
            }
            float vv[4];
            vv[0] = v.x; vv[1] = v.y; vv[2] = v.z; vv[3] = v.w;
            __half* arow = Ah + buf * L1_ASZ + r * BKP + c4;
#pragma unroll
            for (int j = 0; j < 4; j += 2) {
                __half2 hp;
                hp.x = __float2half_rn(vv[j]);
                hp.y = __float2half_rn(vv[j + 1]);
                *reinterpret_cast<__half2*>(arow + j) = hp;
            }
        }
        // B: copy pre-split tables, [hl][256 n][4 uint4] = 2048 uint4, 4/thread
#pragma unroll
        for (int i = 0; i < 4; i++) {
            int idx = tid + i * 512;
            int hl = idx >> 10;            // 0 = hi, 1 = lo
            int rem = idx & 1023;
            int nn = rem >> 2;
            int uu = rem & 3;              // 4 uint4 (=32 halfs) per row
            const __half* srcp = (hl ? s_w1l : s_w1h) + (size_t)nn * L1_KP + k0 + uu * 8;
            uint4 v = *reinterpret_cast<const uint4*>(srcp);
            __half* dstp = (hl ? Bl : Bh) + buf * L1_BSZ + nn * BKP + uu * 8;
            *reinterpret_cast<uint4*>(dstp) = v;
        }
    };

    auto compute = [&](int buf) {
        const __half* ah_base = Ah + buf * L1_ASZ;
        const __half* bh_base = Bh + buf * L1_BSZ;
        const __half* bl_base = Bl + buf * L1_BSZ;
#pragma unroll
        for (int ks = 0; ks < BK; ks += 16) {
            unsigned bh[4][2], bl[4][2];
#pragma unroll
            for (int nt = 0; nt < 4; nt++) {
                int nn = wn * 32 + nt * 8 + quad;
                int kk = ks + ql * 2;
                bh[nt][0] = *reinterpret_cast<const unsigned*>(&bh_base[nn * BKP + kk]);
                bh[nt][1] = *reinterpret_cast<const unsigned*>(&bh_base[nn * BKP + kk + 8]);
                bl[nt][0] = *reinterpret_cast<const unsigned*>(&bl_base[nn * BKP + kk]);
                bl[nt][1] = *reinterpret_cast<const unsigned*>(&bl_base[nn * BKP + kk + 8]);
            }
#pragma unroll
            for (int mt = 0; mt < 4; mt++) {
                int r = wm * 64 + mt * 16 + quad;
                int kk = ks + ql * 2;
                unsigned ah[4];
                ah[0] = *reinterpret_cast<const unsigned*>(&ah_base[r * BKP + kk]);
                ah[1] = *reinterpret_cast<const unsigned*>(&ah_base[(r + 8) * BKP + kk]);
                ah[2] = *reinterpret_cast<const unsigned*>(&ah_base[r * BKP + kk + 8]);
                ah[3] = *reinterpret_cast<const unsigned*>(&ah_base[(r + 8) * BKP + kk + 8]);
#pragma unroll
                for (int nt = 0; nt < 4; nt++) {
                    mma16816fp(acc[mt][nt], ah, bh[nt]);
                    mma16816fp(acc[mt][nt], ah, bl[nt]);
                }
            }
        }
    };

    loadstage(0, 0);
    __syncthreads();
    for (int ch = 0; ch < nch; ch++) {
        if (ch + 1 < nch) loadstage((ch + 1) * BK, (ch + 1) & 1);
        compute(ch & 1);
        __syncthreads();
    }

    // Epilogue: write fp16 h1
#pragma unroll
    for (int mt = 0; mt < 4; mt++) {
        int r0 = m0 + wm * 64 + mt * 16 + quad;
#pragma unroll
        for (int nt = 0; nt < 4; nt++) {
            int cc = wn * 32 + nt * 8 + ql * 2;
            float* p = acc[mt][nt];
            if (r0 < M)
                *reinterpret_cast<__half2*>(s_h16 + (size_t)r0 * N + cc) =
                    __floats2half2_rn(p[0], p[1]);
            if (r0 + 8 < M)
                *reinterpret_cast<__half2*>(s_h16 + (size_t)(r0 + 8) * N + cc) =
                    __floats2half2_rn(p[2], p[3]);
        }
    }
}

// ---------------------------------------------------------------------------
// Generic split-bf16 3-pass GEMM (layers 2/3): A fp32 scratch, C -> fp16 h16.
// ---------------------------------------------------------------------------
#define BM 128

template <int AID, int BN, int T>
__global__ __launch_bounds__(T) void k_gemm_tc(
    const float* __restrict__ W, int M, int N, int K)
{
    const float* A = scratch<AID>();

    __shared__ __nv_bfloat16 Ahs[BM][BKP], Als[BM][BKP];
    __shared__ __nv_bfloat16 Bhs[BN][BKP], Bls[BN][BKP];

    const int tid = threadIdx.x;
    const int m0 = blockIdx.y * BM;
    const int n0 = blockIdx.x * BN;

    constexpr int NW_N = BN / 32;
    const int w = tid >> 5, lane = tid & 31;
    const int wm = w / NW_N, wn = w % NW_N;
    const int quad = lane >> 2, ql = lane & 3;

    constexpr int AF4 = (BM * BK / 4) / T;
    constexpr int WF4 = (BK * BN / 4) / T;
    constexpr int WF4PR = BN / 4;

    float4 aReg[AF4], wReg[WF4];
    float acc[4][4][4];
#pragma unroll
    for (int mt = 0; mt < 4; mt++)
#pragma unroll
        for (int nt = 0; nt < 4; nt++)
#pragma unroll
            for (int i = 0; i < 4; i++) acc[mt][nt][i] = 0.0f;

    const int nch = (K + BK - 1) / BK;

    auto loadA = [&](int k0) {
#pragma unroll
        for (int i = 0; i < AF4; i++) {
            int idx = tid + i * T;
            int r = idx >> 3, c4 = (idx & 7) * 4;
            int gm = m0 + r, gk = k0 + c4;
            float4 v = make_float4(0.f, 0.f, 0.f, 0.f);
            if (gm < M && gk + 3 < K)
                v = *reinterpret_cast<const float4*>(A + (size_t)gm * K + gk);
            aReg[i] = v;
        }
    };

    auto loadW = [&](int k0) {
#pragma unroll
        for (int i = 0; i < WF4; i++) {
            int idx = tid + i * T;
            int k = idx / WF4PR, c4 = (idx % WF4PR) * 4;
            int gk = k0 + k;
            float4 v = make_float4(0.f, 0.f, 0.f, 0.f);
            if (gk < K)
                v = *reinterpret_cast<const float4*>(W + (size_t)gk * N + n0 + c4);
            wReg[i] = v;
        }
    };

    auto stage = [&]() {
#pragma unroll
        for (int i = 0; i < AF4; i++) {
            int idx = tid + i * T;
            int r = idx >> 3, c = (idx & 7) * 4;
            float vv[4];
            vv[0] = aReg[i].x; vv[1] = aReg[i].y; vv[2] = aReg[i].z; vv[3] = aReg[i].w;
#pragma unroll
            for (int j = 0; j < 4; j += 2) {
                __nv_bfloat16 h0, l0, h1, l1;
                split_bf16(vv[j], h0, l0);
                split_bf16(vv[j + 1], h1, l1);
                __nv_bfloat162 hp; hp.x = h0; hp.y = h1;
                __nv_bfloat162 lp; lp.x = l0; lp.y = l1;
                *reinterpret_cast<__nv_bfloat162*>(&Ahs[r][c + j]) = hp;
                *reinterpret_cast<__nv_bfloat162*>(&Als[r][c + j]) = lp;
            }
        }
#pragma unroll
        for (int i = 0; i < WF4; i++) {
            int idx = tid + i * T;
            int k = idx / WF4PR, c = (idx % WF4PR) * 4;
            float vv[4];
            vv[0] = wReg[i].x; vv[1] = wReg[i].y; vv[2] = wReg[i].z; vv[3] = wReg[i].w;
#pragma unroll
            for (int j = 0; j < 4; j++) {
                __nv_bfloat16 h, l;
                split_bf16(vv[j], h, l);
                Bhs[c + j][k] = h;
                Bls[c + j][k] = l;
            }
        }
    };

    auto compute = [&]() {
#pragma unroll
        for (int ks = 0; ks < BK; ks += 16) {
            unsigned bh[4][2], bl[4][2];
#pragma unroll
            for (int nt = 0; nt < 4; nt++) {
                int nn = wn * 32 + nt * 8 + quad;
                int kk = ks + ql * 2;
                bh[nt][0] = *reinterpret_cast<const unsigned*>(&Bhs[nn][kk]);
                bh[nt][1] = *reinterpret_cast<const unsigned*>(&Bhs[nn][kk + 8]);
                bl[nt][0] = *reinterpret_cast<const unsigned*>(&Bls[nn][kk]);
                bl[nt][1] = *reinterpret_cast<const unsigned*>(&Bls[nn][kk + 8]);
            }
#pragma unroll
            for (int mt = 0; mt < 4; mt++) {
                int r = wm * 64 + mt * 16 + quad;
                int kk = ks + ql * 2;
                unsigned ah[4], al[4];
                ah[0] = *reinterpret_cast<const unsigned*>(&Ahs[r][kk]);
                ah[1] = *reinterpret_cast<const unsigned*>(&Ahs[r + 8][kk]);
                ah[2] = *reinterpret_cast<const unsigned*>(&Ahs[r][kk + 8]);
                ah[3] = *reinterpret_cast<const unsigned*>(&Ahs[r + 8][kk + 8]);
                al[0] = *reinterpret_cast<const unsigned*>(&Als[r][kk]);
                al[1] = *reinterpret_cast<const unsigned*>(&Als[r + 8][kk]);
                al[2] = *reinterpret_cast<const unsigned*>(&Als[r][kk + 8]);
                al[3] = *reinterpret_cast<const unsigned*>(&Als[r + 8][kk + 8]);
#pragma unroll
                for (int nt = 0; nt < 4; nt++) {
                    mma16816bf(acc[mt][nt], ah, bh[nt]);
                    mma16816bf(acc[mt][nt], ah, bl[nt]);
                    mma16816bf(acc[mt][nt], al, bh[nt]);
                }
            }
        }
    };

    loadA(0); loadW(0);
    for (int ch = 0; ch < nch; ch++) {
        __syncthreads();
        stage();
        __syncthreads();
        if (ch + 1 < nch) { loadA((ch + 1) * BK); loadW((ch + 1) * BK); }
        compute();
    }

    // Epilogue: write fp16 h
#pragma unroll
    for (int mt = 0; mt < 4; mt++) {
        int r0 = m0 + wm * 64 + mt * 16 + quad;
#pragma unroll
        for (int nt = 0; nt < 4; nt++) {
            int cc = n0 + wn * 32 + nt * 8 + ql * 2;
            float* p = acc[mt][nt];
            if (r0 < M)
                *reinterpret_cast<__half2*>(s_h16 + (size_t)r0 * N + cc) =
                    __floats2half2_rn(p[0], p[1]);
            if (r0 + 8 < M)
                *reinterpret_cast<__half2*>(s_h16 + (size_t)(r0 + 8) * N + cc) =
                    __floats2half2_rn(p[2], p[3]);
        }
    }
}

// ---------------------------------------------------------------------------
// Fused CSR aggregation (fp16 h -> fp32 g): one warp per dst node.
// Each lane handles element pairs e = lane*2 + r*64 via __half2 gathers.
// ---------------------------------------------------------------------------
template <int GID, int F, bool RELU, bool HEAD>
__global__ __launch_bounds__(256) void k_aggregate(
    const float* __restrict__ bias,
    const float* __restrict__ Wl, const float* __restrict__ bl,
    float* __restrict__ out, int n)
{
    constexpr int RP = F / 64;   // half2 chunks per lane

    int warp_in_block = threadIdx.x >> 5;
    int lane = threadIdx.x & 31;
    int node = blockIdx.x * (blockDim.x >> 5) + warp_in_block;
    if (node >= n) return;

    float d = s_dis[node];
    float dsq = d * d;

    float2 acc[RP];
    {
        const __half2* hrow = reinterpret_cast<const __half2*>(s_h16 + (size_t)node * F);
#pragma unroll
        for (int r = 0; r < RP; r++) {
            float2 f = __half22float2(hrow[lane + r * 32]);
            acc[r].x = f.x * dsq;
            acc[r].y = f.y * dsq;
        }
    }

    int beg = s_rowptr[node];
    int end = s_rowptr[node + 1];
    for (int e = beg; e < end; e++) {
        int src = s_csr_src[e];
        float wgt = s_csr_w[e];
        const __half2* hr = reinterpret_cast<const __half2*>(s_h16 + (size_t)src * F);
#pragma unroll
        for (int r = 0; r < RP; r++) {
            float2 f = __half22float2(hr[lane + r * 32]);
            acc[r].x = fmaf(f.x, wgt, acc[r].x);
            acc[r].y = fmaf(f.y, wgt, acc[r].y);
        }
    }

    const float2* b2 = reinterpret_cast<const float2*>(bias);
#pragma unroll
    for (int r = 0; r < RP; r++) {
        float2 bv = b2[lane + r * 32];
        acc[r].x += bv.x;
        acc[r].y += bv.y;
        if constexpr (RELU) {
            acc[r].x = fmaxf(acc[r].x, 0.0f);
            acc[r].y = fmaxf(acc[r].y, 0.0f);
        }
    }

    if constexpr (!HEAD) {
        float2* g2 = reinterpret_cast<float2*>(scratch<GID>() + (size_t)node * F);
#pragma unroll
        for (int r = 0; r < RP; r++)
            g2[lane + r * 32] = acc[r];
    } else {
        // F == 64, RP == 1: lane holds x3 elements (2*lane, 2*lane+1)
        *reinterpret_cast<float2*>(out + (size_t)n + (size_t)node * 64 + lane * 2) = acc[0];
        float2 wv = reinterpret_cast<const float2*>(Wl)[lane];
        float ss = acc[0].x * wv.x + acc[0].y * wv.y;
#pragma unroll
        for (int o = 16; o; o >>= 1) ss += __shfl_xor_sync(0xFFFFFFFFu, ss, o);
        if (lane == 0)
            out[node] = 1.0f / (1.0f + expf(-(ss + bl[0])));
    }
}

// ---------------------------------------------------------------------------
static inline int cdiv(long long a, long long b) { return (int)((a + b - 1) / b); }

extern "C" void kernel_launch(void* const* d_in, const int* in_sizes, int n_in,
                              void* d_out, int out_size)
{
    const float* x   = (const float*)d_in[0];
    const void*  ei  = d_in[1];
    const float* W1  = (const float*)d_in[2];
    const float* b1  = (const float*)d_in[3];
    const float* W2  = (const float*)d_in[4];
    const float* b2  = (const float*)d_in[5];
    const float* W3  = (const float*)d_in[6];
    const float* b3  = (const float*)d_in[7];
    const float* Wl  = (const float*)d_in[8];
    const float* bl  = (const float*)d_in[9];
    float* out = (float*)d_out;

    const int n = in_sizes[0] / D0;    // 50000
    const int E = in_sizes[1] / 2;     // 1600000

    cudaFuncSetAttribute(k_gemm_l1, cudaFuncAttributeMaxDynamicSharedMemorySize,
                         L1_SMEM_BYTES);

    int scan_words = (2 * E < 4096) ? 2 * E : 4096;
    const int MT = cdiv(n, BM);           // 391
    const int AGG_BLOCKS = cdiv(n, 8);

    // k_gemm_l1 kept at stream launch index 3 (ncu sampling window).
    k_detect_dtype<<<1, 256>>>((const int*)ei, scan_words);                   // 0
    k_w1t<<<cdiv((long long)D1 * L1_KP, 256), 256>>>(W1);                     // 1
    k_deg_zero<<<cdiv(n, 256), 256>>>(n);                                     // 2
    k_gemm_l1<<<dim3(1, MT), 512, L1_SMEM_BYTES>>>(x, n);                     // 3
    k_deg_count<<<cdiv(E, 256), 256>>>(ei, E);                                // 4
    k_dis<<<cdiv(n, 256), 256>>>(n);                                          // 5
    k_scan<<<1, 1024>>>(n);                                                   // 6
    k_csr_fill<<<cdiv(E, 256), 256>>>(ei, E);                                 // 7

    // ---- Layer 1 agg: h16 -> g1 (bufA) (+b1, relu) ----
    k_aggregate<0, D1, true, false><<<AGG_BLOCKS, 256>>>(b1, nullptr, nullptr, nullptr, n);

    // ---- Layer 2: gemm g1(bufA)@W2 -> h16 ; agg -> g2 (bufB) ----
    k_gemm_tc<0, 128, 256><<<dim3(1, MT), 256>>>(W2, n, D2, D1);
    k_aggregate<1, D2, false, false><<<AGG_BLOCKS, 256>>>(b2, nullptr, nullptr, nullptr, n);

    // ---- Layer 3: gemm g2(bufB)@W3 -> h16 ; agg -> out (head fused) ----
    k_gemm_tc<1, 64, 128><<<dim3(1, MT), 128>>>(W3, n, D3, D2);
    k_aggregate<0, D3, false, true><<<AGG_BLOCKS, 256>>>(b3, Wl, bl, out, n);
}

// round 13
// speedup vs baseline: 3.4605x; 1.0372x over previous
#include <cuda_runtime.h>
#include <cuda_bf16.h>
#include <cuda_fp16.h>
#include <math.h>

typedef unsigned int u32;

// Fixed problem shapes
#define NNODES 50000
#define D0 3000
#define D1 256
#define D2 128
#define D3 64
#define ECAP 1600000

#define L1_KP 3008   // W1 table K padded to multiple of 64

// Static scratch (allocation-free rule). Device-code access only.
__device__ __align__(16) float  s_bufA[NNODES * D1];     // 51.2 MB (g buffers, fp32)
__device__ __align__(16) float  s_bufB[NNODES * D1];     // 51.2 MB
__device__ __align__(16) __half s_h16[NNODES * D1];      // 25.6 MB (GEMM outputs, fp16)
__device__ __align__(16) __half s_w1h[D1 * L1_KP];       // 1.5 MB  W1^T hi [n][k]
__device__ __align__(16) __half s_w1l[D1 * L1_KP];       // 1.5 MB  W1^T lo
__device__ int   s_deg[NNODES];
__device__ float s_dis[NNODES];
__device__ int   s_rowptr[NNODES + 1];
__device__ int   s_cnt[NNODES];
__device__ int   s_csr_src[ECAP];
__device__ float s_csr_w[ECAP];
__device__ int   s_is64;

template <int ID>
__device__ __forceinline__ float* scratch() {
    if constexpr (ID == 0) return s_bufA;
    else return s_bufB;
}

__device__ __forceinline__ int edge_at(const void* ei, long long idx, int is64) {
    if (is64) return (int)((const long long*)ei)[idx];
    return ((const int*)ei)[idx];
}

__device__ __forceinline__ void split_bf16(float v, __nv_bfloat16& h, __nv_bfloat16& l) {
    h = __float2bfloat16(v);
    l = __float2bfloat16(v - __bfloat162float(h));
}

__device__ __forceinline__ void split_fp16(float v, __half& h, __half& l) {
    h = __float2half_rn(v);
    l = __float2half_rn(v - __half2float(h));
}

__device__ __forceinline__ u32 smem_u32(const void* p) {
    u32 a;
    asm("{ .reg .u64 t; cvta.to.shared.u64 t, %1; cvt.u32.u64 %0, t; }"
        : "=r"(a) : "l"(p));
    return a;
}

__device__ __forceinline__ void ldsm_x4(unsigned* r, u32 addr) {
    asm volatile("ldmatrix.sync.aligned.m8n8.x4.shared.b16 {%0,%1,%2,%3}, [%4];"
                 : "=r"(r[0]), "=r"(r[1]), "=r"(r[2]), "=r"(r[3]) : "r"(addr));
}

__device__ __forceinline__ void ldsm_x2(unsigned* r, u32 addr) {
    asm volatile("ldmatrix.sync.aligned.m8n8.x2.shared.b16 {%0,%1}, [%2];"
                 : "=r"(r[0]), "=r"(r[1]) : "r"(addr));
}

// ---------------------------------------------------------------------------
// Edge dtype detection
// ---------------------------------------------------------------------------
__global__ void k_detect_dtype(const int* __restrict__ ei_words, int nwords)
{
    __shared__ int found_nonzero;
    if (threadIdx.x == 0) found_nonzero = 0;
    __syncthreads();
    for (int w = 1 + 2 * threadIdx.x; w < nwords; w += 2 * blockDim.x) {
        if (ei_words[w] != 0) { found_nonzero = 1; break; }
    }
    __syncthreads();
    if (threadIdx.x == 0) s_is64 = found_nonzero ? 0 : 1;
}

// ---------------------------------------------------------------------------
// W1 pre-transpose + fp16 hi/lo split: tables [n][k], zero-padded to L1_KP
// ---------------------------------------------------------------------------
__global__ void k_w1t(const float* __restrict__ W1)
{
    int idx = blockIdx.x * blockDim.x + threadIdx.x;
    if (idx >= D1 * L1_KP) return;
    int k = idx >> 8;
    int n = idx & 255;
    float v = (k < D0) ? W1[(size_t)k * D1 + n] : 0.0f;
    __half h, l;
    split_fp16(v, h, l);
    s_w1h[(size_t)n * L1_KP + k] = h;
    s_w1l[(size_t)n * L1_KP + k] = l;
}

// ---------------------------------------------------------------------------
// Degree / normalization / CSR build
// ---------------------------------------------------------------------------
__global__ void k_deg_zero(int n) {
    int i = blockIdx.x * blockDim.x + threadIdx.x;
    if (i < n) s_deg[i] = 0;
}

__global__ void k_deg_count(const void* __restrict__ ei, int E) {
    int e = blockIdx.x * blockDim.x + threadIdx.x;
    if (e < E) {
        int is64 = s_is64;
        int d = edge_at(ei, (long long)E + e, is64);
        if ((unsigned)d < (unsigned)NNODES) atomicAdd(&s_deg[d], 1);
    }
}

__global__ void k_dis(int n) {
    int i = blockIdx.x * blockDim.x + threadIdx.x;
    if (i < n) s_dis[i] = rsqrtf((float)s_deg[i] + 1.0f);
}

__global__ __launch_bounds__(1024) void k_scan(int n)
{
    __shared__ int sh[1024];
    __shared__ int carry_sh;
    if (threadIdx.x == 0) carry_sh = 0;
    __syncthreads();
    for (int base = 0; base < n; base += 1024) {
        int i = base + (int)threadIdx.x;
        int v = (i < n) ? s_deg[i] : 0;
        sh[threadIdx.x] = v;
        __syncthreads();
#pragma unroll
        for (int off = 1; off < 1024; off <<= 1) {
            int t = (threadIdx.x >= off) ? sh[threadIdx.x - off] : 0;
            __syncthreads();
            sh[threadIdx.x] += t;
            __syncthreads();
        }
        int incl = sh[threadIdx.x];
        int excl = incl - v;
        int carry = carry_sh;
        if (i < n) {
            s_rowptr[i] = carry + excl;
            s_cnt[i]    = carry + excl;
        }
        __syncthreads();
        if (threadIdx.x == 1023) carry_sh = carry + incl;
        __syncthreads();
    }
    if (threadIdx.x == 0) s_rowptr[n] = carry_sh;
}

__global__ void k_csr_fill(const void* __restrict__ ei, int E)
{
    int e = blockIdx.x * blockDim.x + threadIdx.x;
    if (e >= E) return;
    int is64 = s_is64;
    int s = edge_at(ei, e, is64);
    int d = edge_at(ei, (long long)E + e, is64);
    if ((unsigned)s >= (unsigned)NNODES || (unsigned)d >= (unsigned)NNODES) return;
    int pos = atomicAdd(&s_cnt[d], 1);
    if (pos < ECAP) {
        s_csr_src[pos] = s;
        s_csr_w[pos]   = s_dis[s] * s_dis[d];
    }
}

// ---------------------------------------------------------------------------
// mma helpers
// ---------------------------------------------------------------------------
__device__ __forceinline__ void mma16816bf(float* c, const unsigned* a, const unsigned* b) {
    asm volatile(
        "mma.sync.aligned.m16n8k16.row.col.f32.bf16.bf16.f32 "
        "{%0,%1,%2,%3}, {%4,%5,%6,%7}, {%8,%9}, {%0,%1,%2,%3};\n"
        : "+f"(c[0]), "+f"(c[1]), "+f"(c[2]), "+f"(c[3])
        : "r"(a[0]), "r"(a[1]), "r"(a[2]), "r"(a[3]), "r"(b[0]), "r"(b[1]));
}

__device__ __forceinline__ void mma16816fp(float* c, const unsigned* a, const unsigned* b) {
    asm volatile(
        "mma.sync.aligned.m16n8k16.row.col.f32.f16.f16.f32 "
        "{%0,%1,%2,%3}, {%4,%5,%6,%7}, {%8,%9}, {%0,%1,%2,%3};\n"
        : "+f"(c[0]), "+f"(c[1]), "+f"(c[2]), "+f"(c[3])
        : "r"(a[0]), "r"(a[1]), "r"(a[2]), "r"(a[3]), "r"(b[0]), "r"(b[1]));
}

// ---------------------------------------------------------------------------
// Layer-1 GEMM: h1[M,256] (fp16) = A[M,3000] @ W1.  fp16 two-pass split.
// BM=128, BN=256, BK=32, T=512 (16 warps 2x8), warp tile 64x32,
// double-buffered SMEM, BKP=40 (all-32-bank quad map, ldmatrix-conflict-free).
// Fragment loads via ldmatrix (x4 for A, x2 for B hi/lo).
// ---------------------------------------------------------------------------
#define BK 32
#define BKP 40
#define L1_ASZ (128 * BKP)
#define L1_BSZ (256 * BKP)
#define L1_SMEM_BYTES ((2 * L1_ASZ + 2 * L1_BSZ + 2 * L1_BSZ) * 2)  // 102400

__global__ __launch_bounds__(512) void k_gemm_l1(
    const float* __restrict__ A, int M)
{
    const int N = 256, K = 3000;

    extern __shared__ __half dsm_l1[];
    __half* Ah = dsm_l1;                  // [2][128][BKP]   (hi only)
    __half* Bh = Ah + 2 * L1_ASZ;         // [2][256][BKP]   ([n][k])
    __half* Bl = Bh + 2 * L1_BSZ;

    const int tid = threadIdx.x;
    const int m0 = blockIdx.y * 128;
    const int w = tid >> 5, lane = tid & 31;
    const int wm = w >> 3, wn = w & 7;    // 2 x 8 warp grid
    const int quad = lane >> 2, ql = lane & 3;

    // ldmatrix per-lane byte offsets
    const u32 aS0  = smem_u32(Ah);
    const u32 bhS0 = smem_u32(Bh);
    const u32 blS0 = smem_u32(Bl);
    const u32 a_lane_off = (u32)(((lane & 15) * BKP + (lane >> 4) * 8) * 2);
    const u32 b_lane_off = (u32)(((lane & 7) * BKP + ((lane >> 3) & 1) * 8) * 2);

    float acc[4][4][4];
#pragma unroll
    for (int mt = 0; mt < 4; mt++)
#pragma unroll
        for (int nt = 0; nt < 4; nt++)
#pragma unroll
            for (int i = 0; i < 4; i++) acc[mt][nt][i] = 0.0f;

    const int nch = (K + BK - 1) / BK;   // 94

    auto loadstage = [&](int k0, int buf) {
        // A: 128x32 fp32 = 1024 float4, 2 per thread -> fp16 hi only
#pragma unroll
        for (int i = 0; i < 2; i++) {
            int idx = tid + i * 512;
            int r = idx >> 3, c4 = (idx & 7) * 4;
            int gm = m0 + r, gk = k0 + c4;
            float4 v = make_float4(0.f, 0.f, 0.f, 0.f);
            if (gm < M) {
                const float* base = A + (size_t)gm * K;
                if (gk + 3 < K) {
                    v = *reinterpret_cast<const float4*>(base + gk);
                } else {
                    if (gk + 0 < K) v.x = base[gk + 0];
                    if (gk + 1 < K) v.y = base[gk + 1];
                    if (gk + 2 < K) v.z = base[gk + 2];
                    if (gk + 3 < K) v.w = base[gk + 3];
                }
            }
            float vv[4];
            vv[0] = v.x; vv[1] = v.y; vv[2] = v.z; vv[3] = v.w;
            __half* arow = Ah + buf * L1_ASZ + r * BKP + c4;
#pragma unroll
            for (int j = 0; j < 4; j += 2) {
                __half2 hp;
                hp.x = __float2half_rn(vv[j]);
                hp.y = __float2half_rn(vv[j + 1]);
                *reinterpret_cast<__half2*>(arow + j) = hp;
            }
        }
        // B: copy pre-split tables, [hl][256 n][4 uint4] = 2048 uint4, 4/thread
#pragma unroll
        for (int i = 0; i < 4; i++) {
            int idx = tid + i * 512;
            int hl = idx >> 10;
            int rem = idx & 1023;
            int nn = rem >> 2;
            int uu = rem & 3;
            const __half* srcp = (hl ? s_w1l : s_w1h) + (size_t)nn * L1_KP + k0 + uu * 8;
            uint4 v = *reinterpret_cast<const uint4*>(srcp);
            __half* dstp = (hl ? Bl : Bh) + buf * L1_BSZ + nn * BKP + uu * 8;
            *reinterpret_cast<uint4*>(dstp) = v;
        }
    };

    auto compute = [&](int buf) {
        const u32 aS  = aS0  + (u32)(buf * L1_ASZ * 2);
        const u32 bhS = bhS0 + (u32)(buf * L1_BSZ * 2);
        const u32 blS = blS0 + (u32)(buf * L1_BSZ * 2);
#pragma unroll
        for (int ks = 0; ks < BK; ks += 16) {
            unsigned bh[4][2], bl[4][2];
#pragma unroll
            for (int nt = 0; nt < 4; nt++) {
                u32 off = (u32)(((wn * 32 + nt * 8) * BKP + ks) * 2) + b_lane_off;
                ldsm_x2(bh[nt], bhS + off);
                ldsm_x2(bl[nt], blS + off);
            }
#pragma unroll
            for (int mt = 0; mt < 4; mt++) {
                unsigned ah[4];
                u32 off = (u32)(((wm * 64 + mt * 16) * BKP + ks) * 2) + a_lane_off;
                ldsm_x4(ah, aS + off);
#pragma unroll
                for (int nt = 0; nt < 4; nt++) {
                    mma16816fp(acc[mt][nt], ah, bh[nt]);
                    mma16816fp(acc[mt][nt], ah, bl[nt]);
                }
            }
        }
    };

    loadstage(0, 0);
    __syncthreads();
    for (int ch = 0; ch < nch; ch++) {
        if (ch + 1 < nch) loadstage((ch + 1) * BK, (ch + 1) & 1);
        compute(ch & 1);
        __syncthreads();
    }

    // Epilogue: write fp16 h1
#pragma unroll
    for (int mt = 0; mt < 4; mt++) {
        int r0 = m0 + wm * 64 + mt * 16 + quad;
#pragma unroll
        for (int nt = 0; nt < 4; nt++) {
            int cc = wn * 32 + nt * 8 + ql * 2;
            float* p = acc[mt][nt];
            if (r0 < M)
                *reinterpret_cast<__half2*>(s_h16 + (size_t)r0 * N + cc) =
                    __floats2half2_rn(p[0], p[1]);
            if (r0 + 8 < M)
                *reinterpret_cast<__half2*>(s_h16 + (size_t)(r0 + 8) * N + cc) =
                    __floats2half2_rn(p[2], p[3]);
        }
    }
}

// ---------------------------------------------------------------------------
// Generic split-bf16 3-pass GEMM (layers 2/3): A fp32 scratch, C -> fp16 h16.
// ---------------------------------------------------------------------------
#define BM 128

template <int AID, int BN, int T>
__global__ __launch_bounds__(T) void k_gemm_tc(
    const float* __restrict__ W, int M, int N, int K)
{
    const float* A = scratch<AID>();

    __shared__ __nv_bfloat16 Ahs[BM][BKP], Als[BM][BKP];
    __shared__ __nv_bfloat16 Bhs[BN][BKP], Bls[BN][BKP];

    const int tid = threadIdx.x;
    const int m0 = blockIdx.y * BM;
    const int n0 = blockIdx.x * BN;

    constexpr int NW_N = BN / 32;
    const int w = tid >> 5, lane = tid & 31;
    const int wm = w / NW_N, wn = w % NW_N;
    const int quad = lane >> 2, ql = lane & 3;

    constexpr int AF4 = (BM * BK / 4) / T;
    constexpr int WF4 = (BK * BN / 4) / T;
    constexpr int WF4PR = BN / 4;

    float4 aReg[AF4], wReg[WF4];
    float acc[4][4][4];
#pragma unroll
    for (int mt = 0; mt < 4; mt++)
#pragma unroll
        for (int nt = 0; nt < 4; nt++)
#pragma unroll
            for (int i = 0; i < 4; i++) acc[mt][nt][i] = 0.0f;

    const int nch = (K + BK - 1) / BK;

    auto loadA = [&](int k0) {
#pragma unroll
        for (int i = 0; i < AF4; i++) {
            int idx = tid + i * T;
            int r = idx >> 3, c4 = (idx & 7) * 4;
            int gm = m0 + r, gk = k0 + c4;
            float4 v = make_float4(0.f, 0.f, 0.f, 0.f);
            if (gm < M && gk + 3 < K)
                v = *reinterpret_cast<const float4*>(A + (size_t)gm * K + gk);
            aReg[i] = v;
        }
    };

    auto loadW = [&](int k0) {
#pragma unroll
        for (int i = 0; i < WF4; i++) {
            int idx = tid + i * T;
            int k = idx / WF4PR, c4 = (idx % WF4PR) * 4;
            int gk = k0 + k;
            float4 v = make_float4(0.f, 0.f, 0.f, 0.f);
            if (gk < K)
                v = *reinterpret_cast<const float4*>(W + (size_t)gk * N + n0 + c4);
            wReg[i] = v;
        }
    };

    auto stage = [&]() {
#pragma unroll
        for (int i = 0; i < AF4; i++) {
            int idx = tid + i * T;
            int r = idx >> 3, c = (idx & 7) * 4;
            float vv[4];
            vv[0] = aReg[i].x; vv[1] = aReg[i].y; vv[2] = aReg[i].z; vv[3] = aReg[i].w;
#pragma unroll
            for (int j = 0; j < 4; j += 2) {
                __nv_bfloat16 h0, l0, h1, l1;
                split_bf16(vv[j], h0, l0);
                split_bf16(vv[j + 1], h1, l1);
                __nv_bfloat162 hp; hp.x = h0; hp.y = h1;
                __nv_bfloat162 lp; lp.x = l0; lp.y = l1;
                *reinterpret_cast<__nv_bfloat162*>(&Ahs[r][c + j]) = hp;
                *reinterpret_cast<__nv_bfloat162*>(&Als[r][c + j]) = lp;
            }
        }
#pragma unroll
        for (int i = 0; i < WF4; i++) {
            int idx = tid + i * T;
            int k = idx / WF4PR, c = (idx % WF4PR) * 4;
            float vv[4];
            vv[0] = wReg[i].x; vv[1] = wReg[i].y; vv[2] = wReg[i].z; vv[3] = wReg[i].w;
#pragma unroll
            for (int j = 0; j < 4; j++) {
                __nv_bfloat16 h, l;
                split_bf16(vv[j], h, l);
                Bhs[c + j][k] = h;
                Bls[c + j][k] = l;
            }
        }
    };

    auto compute = [&]() {
#pragma unroll
        for (int ks = 0; ks < BK; ks += 16) {
            unsigned bh[4][2], bl[4][2];
#pragma unroll
            for (int nt = 0; nt < 4; nt++) {
                int nn = wn * 32 + nt * 8 + quad;
                int kk = ks + ql * 2;
                bh[nt][0] = *reinterpret_cast<const unsigned*>(&Bhs[nn][kk]);
                bh[nt][1] = *reinterpret_cast<const unsigned*>(&Bhs[nn][kk + 8]);
                bl[nt][0] = *reinterpret_cast<const unsigned*>(&Bls[nn][kk]);
                bl[nt][1] = *reinterpret_cast<const unsigned*>(&Bls[nn][kk + 8]);
            }
#pragma unroll
            for (int mt = 0; mt < 4; mt++) {
                int r = wm * 64 + mt * 16 + quad;
                int kk = ks + ql * 2;
                unsigned ah[4], al[4];
                ah[0] = *reinterpret_cast<const unsigned*>(&Ahs[r][kk]);
                ah[1] = *reinterpret_cast<const unsigned*>(&Ahs[r + 8][kk]);
                ah[2] = *reinterpret_cast<const unsigned*>(&Ahs[r][kk + 8]);
                ah[3] = *reinterpret_cast<const unsigned*>(&Ahs[r + 8][kk + 8]);
                al[0] = *reinterpret_cast<const unsigned*>(&Als[r][kk]);
                al[1] = *reinterpret_cast<const unsigned*>(&Als[r + 8][kk]);
                al[2] = *reinterpret_cast<const unsigned*>(&Als[r][kk + 8]);
                al[3] = *reinterpret_cast<const unsigned*>(&Als[r + 8][kk + 8]);
#pragma unroll
                for (int nt = 0; nt < 4; nt++) {
                    mma16816bf(acc[mt][nt], ah, bh[nt]);
                    mma16816bf(acc[mt][nt], ah, bl[nt]);
                    mma16816bf(acc[mt][nt], al, bh[nt]);
                }
            }
        }
    };

    loadA(0); loadW(0);
    for (int ch = 0; ch < nch; ch++) {
        __syncthreads();
        stage();
        __syncthreads();
        if (ch + 1 < nch) { loadA((ch + 1) * BK); loadW((ch + 1) * BK); }
        compute();
    }

    // Epilogue: write fp16 h
#pragma unroll
    for (int mt = 0; mt < 4; mt++) {
        int r0 = m0 + wm * 64 + mt * 16 + quad;
#pragma unroll
        for (int nt = 0; nt < 4; nt++) {
            int cc = n0 + wn * 32 + nt * 8 + ql * 2;
            float* p = acc[mt][nt];
            if (r0 < M)
                *reinterpret_cast<__half2*>(s_h16 + (size_t)r0 * N + cc) =
                    __floats2half2_rn(p[0], p[1]);
            if (r0 + 8 < M)
                *reinterpret_cast<__half2*>(s_h16 + (size_t)(r0 + 8) * N + cc) =
                    __floats2half2_rn(p[2], p[3]);
        }
    }
}

// ---------------------------------------------------------------------------
// Fused CSR aggregation (fp16 h -> fp32 g): one warp per dst node.
// ---------------------------------------------------------------------------
template <int GID, int F, bool RELU, bool HEAD>
__global__ __launch_bounds__(256) void k_aggregate(
    const float* __restrict__ bias,
    const float* __restrict__ Wl, const float* __restrict__ bl,
    float* __restrict__ out, int n)
{
    constexpr int RP = F / 64;

    int warp_in_block = threadIdx.x >> 5;
    int lane = threadIdx.x & 31;
    int node = blockIdx.x * (blockDim.x >> 5) + warp_in_block;
    if (node >= n) return;

    float d = s_dis[node];
    float dsq = d * d;

    float2 acc[RP];
    {
        const __half2* hrow = reinterpret_cast<const __half2*>(s_h16 + (size_t)node * F);
#pragma unroll
        for (int r = 0; r < RP; r++) {
            float2 f = __half22float2(hrow[lane + r * 32]);
            acc[r].x = f.x * dsq;
            acc[r].y = f.y * dsq;
        }
    }

    int beg = s_rowptr[node];
    int end = s_rowptr[node + 1];
    for (int e = beg; e < end; e++) {
        int src = s_csr_src[e];
        float wgt = s_csr_w[e];
        const __half2* hr = reinterpret_cast<const __half2*>(s_h16 + (size_t)src * F);
#pragma unroll
        for (int r = 0; r < RP; r++) {
            float2 f = __half22float2(hr[lane + r * 32]);
            acc[r].x = fmaf(f.x, wgt, acc[r].x);
            acc[r].y = fmaf(f.y, wgt, acc[r].y);
        }
    }

    const float2* b2 = reinterpret_cast<const float2*>(bias);
#pragma unroll
    for (int r = 0; r < RP; r++) {
        float2 bv = b2[lane + r * 32];
        acc[r].x += bv.x;
        acc[r].y += bv.y;
        if constexpr (RELU) {
            acc[r].x = fmaxf(acc[r].x, 0.0f);
            acc[r].y = fmaxf(acc[r].y, 0.0f);
        }
    }

    if constexpr (!HEAD) {
        float2* g2 = reinterpret_cast<float2*>(scratch<GID>() + (size_t)node * F);
#pragma unroll
        for (int r = 0; r < RP; r++)
            g2[lane + r * 32] = acc[r];
    } else {
        *reinterpret_cast<float2*>(out + (size_t)n + (size_t)node * 64 + lane * 2) = acc[0];
        float2 wv = reinterpret_cast<const float2*>(Wl)[lane];
        float ss = acc[0].x * wv.x + acc[0].y * wv.y;
#pragma unroll
        for (int o = 16; o; o >>= 1) ss += __shfl_xor_sync(0xFFFFFFFFu, ss, o);
        if (lane == 0)
            out[node] = 1.0f / (1.0f + expf(-(ss + bl[0])));
    }
}

// ---------------------------------------------------------------------------
static inline int cdiv(long long a, long long b) { return (int)((a + b - 1) / b); }

extern "C" void kernel_launch(void* const* d_in, const int* in_sizes, int n_in,
                              void* d_out, int out_size)
{
    const float* x   = (const float*)d_in[0];
    const void*  ei  = d_in[1];
    const float* W1  = (const float*)d_in[2];
    const float* b1  = (const float*)d_in[3];
    const float* W2  = (const float*)d_in[4];
    const float* b2  = (const float*)d_in[5];
    const float* W3  = (const float*)d_in[6];
    const float* b3  = (const float*)d_in[7];
    const float* Wl  = (const float*)d_in[8];
    const float* bl  = (const float*)d_in[9];
    float* out = (float*)d_out;

    const int n = in_sizes[0] / D0;    // 50000
    const int E = in_sizes[1] / 2;     // 1600000

    cudaFuncSetAttribute(k_gemm_l1, cudaFuncAttributeMaxDynamicSharedMemorySize,
                         L1_SMEM_BYTES);

    int scan_words = (2 * E < 4096) ? 2 * E : 4096;
    const int MT = cdiv(n, BM);           // 391
    const int AGG_BLOCKS = cdiv(n, 8);

    // k_gemm_l1 kept at stream launch index 3 (ncu sampling window).
    k_detect_dtype<<<1, 256>>>((const int*)ei, scan_words);                   // 0
    k_w1t<<<cdiv((long long)D1 * L1_KP, 256), 256>>>(W1);                     // 1
    k_deg_zero<<<cdiv(n, 256), 256>>>(n);                                     // 2
    k_gemm_l1<<<dim3(1, MT), 512, L1_SMEM_BYTES>>>(x, n);                     // 3
    k_deg_count<<<cdiv(E, 256), 256>>>(ei, E);                                // 4
    k_dis<<<cdiv(n, 256), 256>>>(n);                                          // 5
    k_scan<<<1, 1024>>>(n);                                                   // 6
    k_csr_fill<<<cdiv(E, 256), 256>>>(ei, E);                                 // 7

    // ---- Layer 1 agg: h16 -> g1 (bufA) (+b1, relu) ----
    k_aggregate<0, D1, true, false><<<AGG_BLOCKS, 256>>>(b1, nullptr, nullptr, nullptr, n);

    // ---- Layer 2: gemm g1(bufA)@W2 -> h16 ; agg -> g2 (bufB) ----
    k_gemm_tc<0, 128, 256><<<dim3(1, MT), 256>>>(W2, n, D2, D1);
    k_aggregate<1, D2, false, false><<<AGG_BLOCKS, 256>>>(b2, nullptr, nullptr, nullptr, n);

    // ---- Layer 3: gemm g2(bufB)@W3 -> h16 ; agg -> out (head fused) ----
    k_gemm_tc<1, 64, 128><<<dim3(1, MT), 128>>>(W3, n, D3, D2);
    k_aggregate<0, D3, false, true><<<AGG_BLOCKS, 256>>>(b3, Wl, bl, out, n);
}

// round 14
// speedup vs baseline: 4.1754x; 1.2066x over previous
#include <cuda_runtime.h>
#include <cuda_bf16.h>
#include <cuda_fp16.h>
#include <math.h>

typedef unsigned int u32;

// Fixed problem shapes
#define NNODES 50000
#define D0 3000
#define D1 256
#define D2 128
#define D3 64
#define ECAP 1600000

#define L1_KP 3008   // W1 table K padded to multiple of 64

// Static scratch (allocation-free rule). Device-code access only.
__device__ __align__(16) float  s_bufA[NNODES * D1];     // 51.2 MB (g buffers, fp32)
__device__ __align__(16) float  s_bufB[NNODES * D1];     // 51.2 MB
__device__ __align__(16) __half s_h16[NNODES * D1];      // 25.6 MB (GEMM outputs, fp16)
__device__ __align__(16) __half s_w1h[D1 * L1_KP];       // 1.5 MB  W1^T fp16 [n][k]
__device__ int   s_deg[NNODES];
__device__ float s_dis[NNODES];
__device__ int   s_rowptr[NNODES + 1];
__device__ int   s_cnt[NNODES];
__device__ int   s_csr_src[ECAP];
__device__ float s_csr_w[ECAP];
__device__ int   s_is64;

template <int ID>
__device__ __forceinline__ float* scratch() {
    if constexpr (ID == 0) return s_bufA;
    else return s_bufB;
}

__device__ __forceinline__ int edge_at(const void* ei, long long idx, int is64) {
    if (is64) return (int)((const long long*)ei)[idx];
    return ((const int*)ei)[idx];
}

__device__ __forceinline__ void split_bf16(float v, __nv_bfloat16& h, __nv_bfloat16& l) {
    h = __float2bfloat16(v);
    l = __float2bfloat16(v - __bfloat162float(h));
}

__device__ __forceinline__ u32 smem_u32(const void* p) {
    u32 a;
    asm("{ .reg .u64 t; cvta.to.shared.u64 t, %1; cvt.u32.u64 %0, t; }"
        : "=r"(a) : "l"(p));
    return a;
}

__device__ __forceinline__ void ldsm_x4(unsigned* r, u32 addr) {
    asm volatile("ldmatrix.sync.aligned.m8n8.x4.shared.b16 {%0,%1,%2,%3}, [%4];"
                 : "=r"(r[0]), "=r"(r[1]), "=r"(r[2]), "=r"(r[3]) : "r"(addr));
}

__device__ __forceinline__ void ldsm_x2(unsigned* r, u32 addr) {
    asm volatile("ldmatrix.sync.aligned.m8n8.x2.shared.b16 {%0,%1}, [%2];"
                 : "=r"(r[0]), "=r"(r[1]) : "r"(addr));
}

// ---------------------------------------------------------------------------
// Edge dtype detection
// ---------------------------------------------------------------------------
__global__ void k_detect_dtype(const int* __restrict__ ei_words, int nwords)
{
    __shared__ int found_nonzero;
    if (threadIdx.x == 0) found_nonzero = 0;
    __syncthreads();
    for (int w = 1 + 2 * threadIdx.x; w < nwords; w += 2 * blockDim.x) {
        if (ei_words[w] != 0) { found_nonzero = 1; break; }
    }
    __syncthreads();
    if (threadIdx.x == 0) s_is64 = found_nonzero ? 0 : 1;
}

// ---------------------------------------------------------------------------
// W1 pre-transpose to fp16 [n][k], zero-padded to L1_KP
// ---------------------------------------------------------------------------
__global__ void k_w1t(const float* __restrict__ W1)
{
    int idx = blockIdx.x * blockDim.x + threadIdx.x;
    if (idx >= D1 * L1_KP) return;
    int k = idx >> 8;
    int n = idx & 255;
    float v = (k < D0) ? W1[(size_t)k * D1 + n] : 0.0f;
    s_w1h[(size_t)n * L1_KP + k] = __float2half_rn(v);
}

// ---------------------------------------------------------------------------
// Degree / normalization / CSR build
// ---------------------------------------------------------------------------
__global__ void k_deg_zero(int n) {
    int i = blockIdx.x * blockDim.x + threadIdx.x;
    if (i < n) s_deg[i] = 0;
}

__global__ void k_deg_count(const void* __restrict__ ei, int E) {
    int e = blockIdx.x * blockDim.x + threadIdx.x;
    if (e < E) {
        int is64 = s_is64;
        int d = edge_at(ei, (long long)E + e, is64);
        if ((unsigned)d < (unsigned)NNODES) atomicAdd(&s_deg[d], 1);
    }
}

__global__ void k_dis(int n) {
    int i = blockIdx.x * blockDim.x + threadIdx.x;
    if (i < n) s_dis[i] = rsqrtf((float)s_deg[i] + 1.0f);
}

__global__ __launch_bounds__(1024) void k_scan(int n)
{
    __shared__ int sh[1024];
    __shared__ int carry_sh;
    if (threadIdx.x == 0) carry_sh = 0;
    __syncthreads();
    for (int base = 0; base < n; base += 1024) {
        int i = base + (int)threadIdx.x;
        int v = (i < n) ? s_deg[i] : 0;
        sh[threadIdx.x] = v;
        __syncthreads();
#pragma unroll
        for (int off = 1; off < 1024; off <<= 1) {
            int t = (threadIdx.x >= off) ? sh[threadIdx.x - off] : 0;
            __syncthreads();
            sh[threadIdx.x] += t;
            __syncthreads();
        }
        int incl = sh[threadIdx.x];
        int excl = incl - v;
        int carry = carry_sh;
        if (i < n) {
            s_rowptr[i] = carry + excl;
            s_cnt[i]    = carry + excl;
        }
        __syncthreads();
        if (threadIdx.x == 1023) carry_sh = carry + incl;
        __syncthreads();
    }
    if (threadIdx.x == 0) s_rowptr[n] = carry_sh;
}

__global__ void k_csr_fill(const void* __restrict__ ei, int E)
{
    int e = blockIdx.x * blockDim.x + threadIdx.x;
    if (e >= E) return;
    int is64 = s_is64;
    int s = edge_at(ei, e, is64);
    int d = edge_at(ei, (long long)E + e, is64);
    if ((unsigned)s >= (unsigned)NNODES || (unsigned)d >= (unsigned)NNODES) return;
    int pos = atomicAdd(&s_cnt[d], 1);
    if (pos < ECAP) {
        s_csr_src[pos] = s;
        s_csr_w[pos]   = s_dis[s] * s_dis[d];
    }
}

// ---------------------------------------------------------------------------
// mma helpers
// ---------------------------------------------------------------------------
__device__ __forceinline__ void mma16816bf(float* c, const unsigned* a, const unsigned* b) {
    asm volatile(
        "mma.sync.aligned.m16n8k16.row.col.f32.bf16.bf16.f32 "
        "{%0,%1,%2,%3}, {%4,%5,%6,%7}, {%8,%9}, {%0,%1,%2,%3};\n"
        : "+f"(c[0]), "+f"(c[1]), "+f"(c[2]), "+f"(c[3])
        : "r"(a[0]), "r"(a[1]), "r"(a[2]), "r"(a[3]), "r"(b[0]), "r"(b[1]));
}

__device__ __forceinline__ void mma16816fp(float* c, const unsigned* a, const unsigned* b) {
    asm volatile(
        "mma.sync.aligned.m16n8k16.row.col.f32.f16.f16.f32 "
        "{%0,%1,%2,%3}, {%4,%5,%6,%7}, {%8,%9}, {%0,%1,%2,%3};\n"
        : "+f"(c[0]), "+f"(c[1]), "+f"(c[2]), "+f"(c[3])
        : "r"(a[0]), "r"(a[1]), "r"(a[2]), "r"(a[3]), "r"(b[0]), "r"(b[1]));
}

// ---------------------------------------------------------------------------
// Layer-1 GEMM: h1[M,256] (fp16) = A[M,3000] @ W1.  SINGLE-pass fp16.
// BM=128, BN=256, BK=32, T=512 (16 warps 2x8), warp tile 64x32,
// double-buffered SMEM (60 KB), BKP=40, ldmatrix fragment loads.
// ---------------------------------------------------------------------------
#define BK 32
#define BKP 40
#define L1_ASZ (128 * BKP)
#define L1_BSZ (256 * BKP)
#define L1_SMEM_BYTES ((2 * L1_ASZ + 2 * L1_BSZ) * 2)   // 61440

__global__ __launch_bounds__(512) void k_gemm_l1(
    const float* __restrict__ A, int M)
{
    const int N = 256, K = 3000;

    extern __shared__ __half dsm_l1[];
    __half* Ah = dsm_l1;                  // [2][128][BKP]
    __half* Bh = Ah + 2 * L1_ASZ;         // [2][256][BKP]   ([n][k])

    const int tid = threadIdx.x;
    const int m0 = blockIdx.y * 128;
    const int w = tid >> 5, lane = tid & 31;
    const int wm = w >> 3, wn = w & 7;    // 2 x 8 warp grid
    const int quad = lane >> 2, ql = lane & 3;

    const u32 aS0  = smem_u32(Ah);
    const u32 bhS0 = smem_u32(Bh);
    const u32 a_lane_off = (u32)(((lane & 15) * BKP + (lane >> 4) * 8) * 2);
    const u32 b_lane_off = (u32)(((lane & 7) * BKP + ((lane >> 3) & 1) * 8) * 2);

    float acc[4][4][4];
#pragma unroll
    for (int mt = 0; mt < 4; mt++)
#pragma unroll
        for (int nt = 0; nt < 4; nt++)
#pragma unroll
            for (int i = 0; i < 4; i++) acc[mt][nt][i] = 0.0f;

    const int nch = (K + BK - 1) / BK;   // 94

    auto loadstage = [&](int k0, int buf) {
        // A: 128x32 fp32 = 1024 float4, 2 per thread -> fp16
#pragma unroll
        for (int i = 0; i < 2; i++) {
            int idx = tid + i * 512;
            int r = idx >> 3, c4 = (idx & 7) * 4;
            int gm = m0 + r, gk = k0 + c4;
            float4 v = make_float4(0.f, 0.f, 0.f, 0.f);
            if (gm < M) {
                const float* base = A + (size_t)gm * K;
                if (gk + 3 < K) {
                    v = *reinterpret_cast<const float4*>(base + gk);
                } else {
                    if (gk + 0 < K) v.x = base[gk + 0];
                    if (gk + 1 < K) v.y = base[gk + 1];
                    if (gk + 2 < K) v.z = base[gk + 2];
                    if (gk + 3 < K) v.w = base[gk + 3];
                }
            }
            __half* arow = Ah + buf * L1_ASZ + r * BKP + c4;
            *reinterpret_cast<__half2*>(arow)     = __floats2half2_rn(v.x, v.y);
            *reinterpret_cast<__half2*>(arow + 2) = __floats2half2_rn(v.z, v.w);
        }
        // B: copy pre-converted table, [256 n][4 uint4] = 1024 uint4, 2/thread
#pragma unroll
        for (int i = 0; i < 2; i++) {
            int idx = tid + i * 512;
            int nn = idx >> 2;
            int uu = idx & 3;
            const __half* srcp = s_w1h + (size_t)nn * L1_KP + k0 + uu * 8;
            uint4 v = *reinterpret_cast<const uint4*>(srcp);
            __half* dstp = Bh + buf * L1_BSZ + nn * BKP + uu * 8;
            *reinterpret_cast<uint4*>(dstp) = v;
        }
    };

    auto compute = [&](int buf) {
        const u32 aS  = aS0  + (u32)(buf * L1_ASZ * 2);
        const u32 bhS = bhS0 + (u32)(buf * L1_BSZ * 2);
#pragma unroll
        for (int ks = 0; ks < BK; ks += 16) {
            unsigned bh[4][2];
#pragma unroll
            for (int nt = 0; nt < 4; nt++) {
                u32 off = (u32)(((wn * 32 + nt * 8) * BKP + ks) * 2) + b_lane_off;
                ldsm_x2(bh[nt], bhS + off);
            }
#pragma unroll
            for (int mt = 0; mt < 4; mt++) {
                unsigned ah[4];
                u32 off = (u32)(((wm * 64 + mt * 16) * BKP + ks) * 2) + a_lane_off;
                ldsm_x4(ah, aS + off);
#pragma unroll
                for (int nt = 0; nt < 4; nt++)
                    mma16816fp(acc[mt][nt], ah, bh[nt]);
            }
        }
    };

    loadstage(0, 0);
    __syncthreads();
    for (int ch = 0; ch < nch; ch++) {
        if (ch + 1 < nch) loadstage((ch + 1) * BK, (ch + 1) & 1);
        compute(ch & 1);
        __syncthreads();
    }

    // Epilogue: write fp16 h1
#pragma unroll
    for (int mt = 0; mt < 4; mt++) {
        int r0 = m0 + wm * 64 + mt * 16 + quad;
#pragma unroll
        for (int nt = 0; nt < 4; nt++) {
            int cc = wn * 32 + nt * 8 + ql * 2;
            float* p = acc[mt][nt];
            if (r0 < M)
                *reinterpret_cast<__half2*>(s_h16 + (size_t)r0 * N + cc) =
                    __floats2half2_rn(p[0], p[1]);
            if (r0 + 8 < M)
                *reinterpret_cast<__half2*>(s_h16 + (size_t)(r0 + 8) * N + cc) =
                    __floats2half2_rn(p[2], p[3]);
        }
    }
}

// ---------------------------------------------------------------------------
// Generic split-bf16 3-pass GEMM (layers 2/3): A fp32 scratch, C -> fp16 h16.
// ---------------------------------------------------------------------------
#define BM 128

template <int AID, int BN, int T>
__global__ __launch_bounds__(T) void k_gemm_tc(
    const float* __restrict__ W, int M, int N, int K)
{
    const float* A = scratch<AID>();

    __shared__ __nv_bfloat16 Ahs[BM][BKP], Als[BM][BKP];
    __shared__ __nv_bfloat16 Bhs[BN][BKP], Bls[BN][BKP];

    const int tid = threadIdx.x;
    const int m0 = blockIdx.y * BM;
    const int n0 = blockIdx.x * BN;

    constexpr int NW_N = BN / 32;
    const int w = tid >> 5, lane = tid & 31;
    const int wm = w / NW_N, wn = w % NW_N;
    const int quad = lane >> 2, ql = lane & 3;

    constexpr int AF4 = (BM * BK / 4) / T;
    constexpr int WF4 = (BK * BN / 4) / T;
    constexpr int WF4PR = BN / 4;

    float4 aReg[AF4], wReg[WF4];
    float acc[4][4][4];
#pragma unroll
    for (int mt = 0; mt < 4; mt++)
#pragma unroll
        for (int nt = 0; nt < 4; nt++)
#pragma unroll
            for (int i = 0; i < 4; i++) acc[mt][nt][i] = 0.0f;

    const int nch = (K + BK - 1) / BK;

    auto loadA = [&](int k0) {
#pragma unroll
        for (int i = 0; i < AF4; i++) {
            int idx = tid + i * T;
            int r = idx >> 3, c4 = (idx & 7) * 4;
            int gm = m0 + r, gk = k0 + c4;
            float4 v = make_float4(0.f, 0.f, 0.f, 0.f);
            if (gm < M && gk + 3 < K)
                v = *reinterpret_cast<const float4*>(A + (size_t)gm * K + gk);
            aReg[i] = v;
        }
    };

    auto loadW = [&](int k0) {
#pragma unroll
        for (int i = 0; i < WF4; i++) {
            int idx = tid + i * T;
            int k = idx / WF4PR, c4 = (idx % WF4PR) * 4;
            int gk = k0 + k;
            float4 v = make_float4(0.f, 0.f, 0.f, 0.f);
            if (gk < K)
                v = *reinterpret_cast<const float4*>(W + (size_t)gk * N + n0 + c4);
            wReg[i] = v;
        }
    };

    auto stage = [&]() {
#pragma unroll
        for (int i = 0; i < AF4; i++) {
            int idx = tid + i * T;
            int r = idx >> 3, c = (idx & 7) * 4;
            float vv[4];
            vv[0] = aReg[i].x; vv[1] = aReg[i].y; vv[2] = aReg[i].z; vv[3] = aReg[i].w;
#pragma unroll
            for (int j = 0; j < 4; j += 2) {
                __nv_bfloat16 h0, l0, h1, l1;
                split_bf16(vv[j], h0, l0);
                split_bf16(vv[j + 1], h1, l1);
                __nv_bfloat162 hp; hp.x = h0; hp.y = h1;
                __nv_bfloat162 lp; lp.x = l0; lp.y = l1;
                *reinterpret_cast<__nv_bfloat162*>(&Ahs[r][c + j]) = hp;
                *reinterpret_cast<__nv_bfloat162*>(&Als[r][c + j]) = lp;
            }
        }
#pragma unroll
        for (int i = 0; i < WF4; i++) {
            int idx = tid + i * T;
            int k = idx / WF4PR, c = (idx % WF4PR) * 4;
            float vv[4];
            vv[0] = wReg[i].x; vv[1] = wReg[i].y; vv[2] = wReg[i].z; vv[3] = wReg[i].w;
#pragma unroll
            for (int j = 0; j < 4; j++) {
                __nv_bfloat16 h, l;
                split_bf16(vv[j], h, l);
                Bhs[c + j][k] = h;
                Bls[c + j][k] = l;
            }
        }
    };

    auto compute = [&]() {
#pragma unroll
        for (int ks = 0; ks < BK; ks += 16) {
            unsigned bh[4][2], bl[4][2];
#pragma unroll
            for (int nt = 0; nt < 4; nt++) {
                int nn = wn * 32 + nt * 8 + quad;
                int kk = ks + ql * 2;
                bh[nt][0] = *reinterpret_cast<const unsigned*>(&Bhs[nn][kk]);
                bh[nt][1] = *reinterpret_cast<const unsigned*>(&Bhs[nn][kk + 8]);
                bl[nt][0] = *reinterpret_cast<const unsigned*>(&Bls[nn][kk]);
                bl[nt][1] = *reinterpret_cast<const unsigned*>(&Bls[nn][kk + 8]);
            }
#pragma unroll
            for (int mt = 0; mt < 4; mt++) {
                int r = wm * 64 + mt * 16 + quad;
                int kk = ks + ql * 2;
                unsigned ah[4], al[4];
                ah[0] = *reinterpret_cast<const unsigned*>(&Ahs[r][kk]);
                ah[1] = *reinterpret_cast<const unsigned*>(&Ahs[r + 8][kk]);
                ah[2] = *reinterpret_cast<const unsigned*>(&Ahs[r][kk + 8]);
                ah[3] = *reinterpret_cast<const unsigned*>(&Ahs[r + 8][kk + 8]);
                al[0] = *reinterpret_cast<const unsigned*>(&Als[r][kk]);
                al[1] = *reinterpret_cast<const unsigned*>(&Als[r + 8][kk]);
                al[2] = *reinterpret_cast<const unsigned*>(&Als[r][kk + 8]);
                al[3] = *reinterpret_cast<const unsigned*>(&Als[r + 8][kk + 8]);
#pragma unroll
                for (int nt = 0; nt < 4; nt++) {
                    mma16816bf(acc[mt][nt], ah, bh[nt]);
                    mma16816bf(acc[mt][nt], ah, bl[nt]);
                    mma16816bf(acc[mt][nt], al, bh[nt]);
                }
            }
        }
    };

    loadA(0); loadW(0);
    for (int ch = 0; ch < nch; ch++) {
        __syncthreads();
        stage();
        __syncthreads();
        if (ch + 1 < nch) { loadA((ch + 1) * BK); loadW((ch + 1) * BK); }
        compute();
    }

    // Epilogue: write fp16 h
#pragma unroll
    for (int mt = 0; mt < 4; mt++) {
        int r0 = m0 + wm * 64 + mt * 16 + quad;
#pragma unroll
        for (int nt = 0; nt < 4; nt++) {
            int cc = n0 + wn * 32 + nt * 8 + ql * 2;
            float* p = acc[mt][nt];
            if (r0 < M)
                *reinterpret_cast<__half2*>(s_h16 + (size_t)r0 * N + cc) =
                    __floats2half2_rn(p[0], p[1]);
            if (r0 + 8 < M)
                *reinterpret_cast<__half2*>(s_h16 + (size_t)(r0 + 8) * N + cc) =
                    __floats2half2_rn(p[2], p[3]);
        }
    }
}

// ---------------------------------------------------------------------------
// Fused CSR aggregation (fp16 h -> fp32 g): one warp per dst node.
// ---------------------------------------------------------------------------
template <int GID, int F, bool RELU, bool HEAD>
__global__ __launch_bounds__(256) void k_aggregate(
    const float* __restrict__ bias,
    const float* __restrict__ Wl, const float* __restrict__ bl,
    float* __restrict__ out, int n)
{
    constexpr int RP = F / 64;

    int warp_in_block = threadIdx.x >> 5;
    int lane = threadIdx.x & 31;
    int node = blockIdx.x * (blockDim.x >> 5) + warp_in_block;
    if (node >= n) return;

    float d = s_dis[node];
    float dsq = d * d;

    float2 acc[RP];
    {
        const __half2* hrow = reinterpret_cast<const __half2*>(s_h16 + (size_t)node * F);
#pragma unroll
        for (int r = 0; r < RP; r++) {
            float2 f = __half22float2(hrow[lane + r * 32]);
            acc[r].x = f.x * dsq;
            acc[r].y = f.y * dsq;
        }
    }

    int beg = s_rowptr[node];
    int end = s_rowptr[node + 1];
    for (int e = beg; e < end; e++) {
        int src = s_csr_src[e];
        float wgt = s_csr_w[e];
        const __half2* hr = reinterpret_cast<const __half2*>(s_h16 + (size_t)src * F);
#pragma unroll
        for (int r = 0; r < RP; r++) {
            float2 f = __half22float2(hr[lane + r * 32]);
            acc[r].x = fmaf(f.x, wgt, acc[r].x);
            acc[r].y = fmaf(f.y, wgt, acc[r].y);
        }
    }

    const float2* b2 = reinterpret_cast<const float2*>(bias);
#pragma unroll
    for (int r = 0; r < RP; r++) {
        float2 bv = b2[lane + r * 32];
        acc[r].x += bv.x;
        acc[r].y += bv.y;
        if constexpr (RELU) {
            acc[r].x = fmaxf(acc[r].x, 0.0f);
            acc[r].y = fmaxf(acc[r].y, 0.0f);
        }
    }

    if constexpr (!HEAD) {
        float2* g2 = reinterpret_cast<float2*>(scratch<GID>() + (size_t)node * F);
#pragma unroll
        for (int r = 0; r < RP; r++)
            g2[lane + r * 32] = acc[r];
    } else {
        *reinterpret_cast<float2*>(out + (size_t)n + (size_t)node * 64 + lane * 2) = acc[0];
        float2 wv = reinterpret_cast<const float2*>(Wl)[lane];
        float ss = acc[0].x * wv.x + acc[0].y * wv.y;
#pragma unroll
        for (int o = 16; o; o >>= 1) ss += __shfl_xor_sync(0xFFFFFFFFu, ss, o);
        if (lane == 0)
            out[node] = 1.0f / (1.0f + expf(-(ss + bl[0])));
    }
}

// ---------------------------------------------------------------------------
static inline int cdiv(long long a, long long b) { return (int)((a + b - 1) / b); }

extern "C" void kernel_launch(void* const* d_in, const int* in_sizes, int n_in,
                              void* d_out, int out_size)
{
    const float* x   = (const float*)d_in[0];
    const void*  ei  = d_in[1];
    const float* W1  = (const float*)d_in[2];
    const float* b1  = (const float*)d_in[3];
    const float* W2  = (const float*)d_in[4];
    const float* b2  = (const float*)d_in[5];
    const float* W3  = (const float*)d_in[6];
    const float* b3  = (const float*)d_in[7];
    const float* Wl  = (const float*)d_in[8];
    const float* bl  = (const float*)d_in[9];
    float* out = (float*)d_out;

    const int n = in_sizes[0] / D0;    // 50000
    const int E = in_sizes[1] / 2;     // 1600000

    cudaFuncSetAttribute(k_gemm_l1, cudaFuncAttributeMaxDynamicSharedMemorySize,
                         L1_SMEM_BYTES);

    int scan_words = (2 * E < 4096) ? 2 * E : 4096;
    const int MT = cdiv(n, BM);           // 391
    const int AGG_BLOCKS = cdiv(n, 8);

    // k_gemm_l1 kept at stream launch index 3 (ncu sampling window).
    k_detect_dtype<<<1, 256>>>((const int*)ei, scan_words);                   // 0
    k_w1t<<<cdiv((long long)D1 * L1_KP, 256), 256>>>(W1);                     // 1
    k_deg_zero<<<cdiv(n, 256), 256>>>(n);                                     // 2
    k_gemm_l1<<<dim3(1, MT), 512, L1_SMEM_BYTES>>>(x, n);                     // 3
    k_deg_count<<<cdiv(E, 256), 256>>>(ei, E);                                // 4
    k_dis<<<cdiv(n, 256), 256>>>(n);                                          // 5
    k_scan<<<1, 1024>>>(n);                                                   // 6
    k_csr_fill<<<cdiv(E, 256), 256>>>(ei, E);                                 // 7

    // ---- Layer 1 agg: h16 -> g1 (bufA) (+b1, relu) ----
    k_aggregate<0, D1, true, false><<<AGG_BLOCKS, 256>>>(b1, nullptr, nullptr, nullptr, n);

    // ---- Layer 2: gemm g1(bufA)@W2 -> h16 ; agg -> g2 (bufB) ----
    k_gemm_tc<0, 128, 256><<<dim3(1, MT), 256>>>(W2, n, D2, D1);
    k_aggregate<1, D2, false, false><<<AGG_BLOCKS, 256>>>(b2, nullptr, nullptr, nullptr, n);

    // ---- Layer 3: gemm g2(bufB)@W3 -> h16 ; agg -> out (head fused) ----
    k_gemm_tc<1, 64, 128><<<dim3(1, MT), 128>>>(W3, n, D3, D2);
    k_aggregate<0, D3, false, true><<<AGG_BLOCKS, 256>>>(b3, Wl, bl, out, n);
}

// round 15
// speedup vs baseline: 5.2876x; 1.2664x over previous
#include <cuda_runtime.h>
#include <cuda_bf16.h>
#include <cuda_fp16.h>
#include <math.h>

typedef unsigned int u32;

// Fixed problem shapes
#define NNODES 50000
#define D0 3000
#define D1 256
#define D2 128
#define D3 64
#define ECAP 1600000

#define L1_KP 3008   // W1 table K padded to multiple of 64

// Static scratch (allocation-free rule). Device-code access only.
__device__ __align__(16) float  s_bufA[NNODES * D1];     // 51.2 MB (g buffers, fp32)
__device__ __align__(16) float  s_bufB[NNODES * D1];     // 51.2 MB
__device__ __align__(16) __half s_h16[NNODES * D1];      // 25.6 MB (GEMM outputs, fp16)
__device__ __align__(16) __half s_w1h[D1 * L1_KP];       // 1.5 MB  W1^T fp16 [n][k]
__device__ int   s_deg[NNODES];
__device__ float s_dis[NNODES];
__device__ int   s_rowptr[NNODES + 1];
__device__ int   s_cnt[NNODES];
__device__ int   s_csr_src[ECAP];
__device__ float s_csr_w[ECAP];
__device__ int   s_is64;

template <int ID>
__device__ __forceinline__ float* scratch() {
    if constexpr (ID == 0) return s_bufA;
    else return s_bufB;
}

__device__ __forceinline__ int edge_at(const void* ei, long long idx, int is64) {
    if (is64) return (int)((const long long*)ei)[idx];
    return ((const int*)ei)[idx];
}

__device__ __forceinline__ void split_bf16(float v, __nv_bfloat16& h, __nv_bfloat16& l) {
    h = __float2bfloat16(v);
    l = __float2bfloat16(v - __bfloat162float(h));
}

__device__ __forceinline__ u32 smem_u32(const void* p) {
    u32 a;
    asm("{ .reg .u64 t; cvta.to.shared.u64 t, %1; cvt.u32.u64 %0, t; }"
        : "=r"(a) : "l"(p));
    return a;
}

__device__ __forceinline__ void ldsm_x4(unsigned* r, u32 addr) {
    asm volatile("ldmatrix.sync.aligned.m8n8.x4.shared.b16 {%0,%1,%2,%3}, [%4];"
                 : "=r"(r[0]), "=r"(r[1]), "=r"(r[2]), "=r"(r[3]) : "r"(addr));
}

__device__ __forceinline__ void ldsm_x2(unsigned* r, u32 addr) {
    asm volatile("ldmatrix.sync.aligned.m8n8.x2.shared.b16 {%0,%1}, [%2];"
                 : "=r"(r[0]), "=r"(r[1]) : "r"(addr));
}

__device__ __forceinline__ void cp_async16(u32 smem_addr, const void* gptr) {
    asm volatile("cp.async.cg.shared.global [%0], [%1], 16;"
                 :: "r"(smem_addr), "l"(gptr) : "memory");
}
__device__ __forceinline__ void cp_async_commit() {
    asm volatile("cp.async.commit_group;" ::: "memory");
}
__device__ __forceinline__ void cp_async_wait0() {
    asm volatile("cp.async.wait_group 0;" ::: "memory");
}

// ---------------------------------------------------------------------------
// Edge dtype detection
// ---------------------------------------------------------------------------
__global__ void k_detect_dtype(const int* __restrict__ ei_words, int nwords)
{
    __shared__ int found_nonzero;
    if (threadIdx.x == 0) found_nonzero = 0;
    __syncthreads();
    for (int w = 1 + 2 * threadIdx.x; w < nwords; w += 2 * blockDim.x) {
        if (ei_words[w] != 0) { found_nonzero = 1; break; }
    }
    __syncthreads();
    if (threadIdx.x == 0) s_is64 = found_nonzero ? 0 : 1;
}

// ---------------------------------------------------------------------------
// W1 pre-transpose to fp16 [n][k], zero-padded to L1_KP
// ---------------------------------------------------------------------------
__global__ void k_w1t(const float* __restrict__ W1)
{
    int idx = blockIdx.x * blockDim.x + threadIdx.x;
    if (idx >= D1 * L1_KP) return;
    int k = idx >> 8;
    int n = idx & 255;
    float v = (k < D0) ? W1[(size_t)k * D1 + n] : 0.0f;
    s_w1h[(size_t)n * L1_KP + k] = __float2half_rn(v);
}

// ---------------------------------------------------------------------------
// Degree / normalization / CSR build
// ---------------------------------------------------------------------------
__global__ void k_deg_zero(int n) {
    int i = blockIdx.x * blockDim.x + threadIdx.x;
    if (i < n) s_deg[i] = 0;
}

__global__ void k_deg_count(const void* __restrict__ ei, int E) {
    int e = blockIdx.x * blockDim.x + threadIdx.x;
    if (e < E) {
        int is64 = s_is64;
        int d = edge_at(ei, (long long)E + e, is64);
        if ((unsigned)d < (unsigned)NNODES) atomicAdd(&s_deg[d], 1);
    }
}

__global__ void k_dis(int n) {
    int i = blockIdx.x * blockDim.x + threadIdx.x;
    if (i < n) s_dis[i] = rsqrtf((float)s_deg[i] + 1.0f);
}

__global__ __launch_bounds__(1024) void k_scan(int n)
{
    __shared__ int sh[1024];
    __shared__ int carry_sh;
    if (threadIdx.x == 0) carry_sh = 0;
    __syncthreads();
    for (int base = 0; base < n; base += 1024) {
        int i = base + (int)threadIdx.x;
        int v = (i < n) ? s_deg[i] : 0;
        sh[threadIdx.x] = v;
        __syncthreads();
#pragma unroll
        for (int off = 1; off < 1024; off <<= 1) {
            int t = (threadIdx.x >= off) ? sh[threadIdx.x - off] : 0;
            __syncthreads();
            sh[threadIdx.x] += t;
            __syncthreads();
        }
        int incl = sh[threadIdx.x];
        int excl = incl - v;
        int carry = carry_sh;
        if (i < n) {
            s_rowptr[i] = carry + excl;
            s_cnt[i]    = carry + excl;
        }
        __syncthreads();
        if (threadIdx.x == 1023) carry_sh = carry + incl;
        __syncthreads();
    }
    if (threadIdx.x == 0) s_rowptr[n] = carry_sh;
}

__global__ void k_csr_fill(const void* __restrict__ ei, int E)
{
    int e = blockIdx.x * blockDim.x + threadIdx.x;
    if (e >= E) return;
    int is64 = s_is64;
    int s = edge_at(ei, e, is64);
    int d = edge_at(ei, (long long)E + e, is64);
    if ((unsigned)s >= (unsigned)NNODES || (unsigned)d >= (unsigned)NNODES) return;
    int pos = atomicAdd(&s_cnt[d], 1);
    if (pos < ECAP) {
        s_csr_src[pos] = s;
        s_csr_w[pos]   = s_dis[s] * s_dis[d];
    }
}

// ---------------------------------------------------------------------------
// mma helpers
// ---------------------------------------------------------------------------
__device__ __forceinline__ void mma16816bf(float* c, const unsigned* a, const unsigned* b) {
    asm volatile(
        "mma.sync.aligned.m16n8k16.row.col.f32.bf16.bf16.f32 "
        "{%0,%1,%2,%3}, {%4,%5,%6,%7}, {%8,%9}, {%0,%1,%2,%3};\n"
        : "+f"(c[0]), "+f"(c[1]), "+f"(c[2]), "+f"(c[3])
        : "r"(a[0]), "r"(a[1]), "r"(a[2]), "r"(a[3]), "r"(b[0]), "r"(b[1]));
}

__device__ __forceinline__ void mma16816fp(float* c, const unsigned* a, const unsigned* b) {
    asm volatile(
        "mma.sync.aligned.m16n8k16.row.col.f32.f16.f16.f32 "
        "{%0,%1,%2,%3}, {%4,%5,%6,%7}, {%8,%9}, {%0,%1,%2,%3};\n"
        : "+f"(c[0]), "+f"(c[1]), "+f"(c[2]), "+f"(c[3])
        : "r"(a[0]), "r"(a[1]), "r"(a[2]), "r"(a[3]), "r"(b[0]), "r"(b[1]));
}

// ---------------------------------------------------------------------------
// Layer-1 GEMM: h1[M,256] (fp16) = A[M,3000] @ W1.  Single-pass fp16.
// BM=128, BN=256, BK=32, T=512 (16 warps 2x8), warp tile 64x32,
// double-buffered SMEM (60 KB), BKP=40, ldmatrix fragment loads.
// Pipeline: A LDG->regs issued before compute (STS deferred to next iter top),
// B staged via cp.async (no register round-trip).
// ---------------------------------------------------------------------------
#define BK 32
#define BKP 40
#define L1_ASZ (128 * BKP)
#define L1_BSZ (256 * BKP)
#define L1_SMEM_BYTES ((2 * L1_ASZ + 2 * L1_BSZ) * 2)   // 61440

__global__ __launch_bounds__(512) void k_gemm_l1(
    const float* __restrict__ A, int M)
{
    const int N = 256, K = 3000;

    extern __shared__ __half dsm_l1[];
    __half* Ah = dsm_l1;                  // [2][128][BKP]
    __half* Bh = Ah + 2 * L1_ASZ;         // [2][256][BKP]   ([n][k])

    const int tid = threadIdx.x;
    const int m0 = blockIdx.y * 128;
    const int w = tid >> 5, lane = tid & 31;
    const int wm = w >> 3, wn = w & 7;    // 2 x 8 warp grid
    const int quad = lane >> 2, ql = lane & 3;

    const u32 aS0  = smem_u32(Ah);
    const u32 bhS0 = smem_u32(Bh);
    const u32 a_lane_off = (u32)(((lane & 15) * BKP + (lane >> 4) * 8) * 2);
    const u32 b_lane_off = (u32)(((lane & 7) * BKP + ((lane >> 3) & 1) * 8) * 2);

    // Per-thread staging coordinates
    const int ar  = tid >> 3;             // A row (thread 0..511 -> rows 0..63 x2)
    const int ac4 = (tid & 7) * 4;        // A col group
    const int bnn = tid >> 1;             // B row (two threads per row)
    const int buu = (tid & 1) * 2;        // B uint4 index (2 per thread)

    float4 aReg[2];
    float acc[4][4][4];
#pragma unroll
    for (int mt = 0; mt < 4; mt++)
#pragma unroll
        for (int nt = 0; nt < 4; nt++)
#pragma unroll
            for (int i = 0; i < 4; i++) acc[mt][nt][i] = 0.0f;

    const int nch = (K + BK - 1) / BK;   // 94

    auto loadA = [&](int k0) {
#pragma unroll
        for (int i = 0; i < 2; i++) {
            int r = ar + i * 64;
            int gm = m0 + r, gk = k0 + ac4;
            float4 v = make_float4(0.f, 0.f, 0.f, 0.f);
            if (gm < M) {
                const float* base = A + (size_t)gm * K;
                if (gk + 3 < K) {
                    v = *reinterpret_cast<const float4*>(base + gk);
                } else {
                    if (gk + 0 < K) v.x = base[gk + 0];
                    if (gk + 1 < K) v.y = base[gk + 1];
                    if (gk + 2 < K) v.z = base[gk + 2];
                    if (gk + 3 < K) v.w = base[gk + 3];
                }
            }
            aReg[i] = v;
        }
    };

    auto stageA = [&](int buf) {
#pragma unroll
        for (int i = 0; i < 2; i++) {
            int r = ar + i * 64;
            __half* arow = Ah + buf * L1_ASZ + r * BKP + ac4;
            *reinterpret_cast<__half2*>(arow)     = __floats2half2_rn(aReg[i].x, aReg[i].y);
            *reinterpret_cast<__half2*>(arow + 2) = __floats2half2_rn(aReg[i].z, aReg[i].w);
        }
    };

    auto cpB = [&](int k0, int buf) {
        // 1024 uint4 total; 2 per thread (same B row, adjacent uint4s)
        const __half* srcp = s_w1h + (size_t)bnn * L1_KP + k0 + buu * 8;
        u32 dst = bhS0 + (u32)((buf * L1_BSZ + bnn * BKP + buu * 8) * 2);
        cp_async16(dst, srcp);
        cp_async16(dst + 16, srcp + 8);
        cp_async_commit();
    };

    auto compute = [&](int buf) {
        const u32 aS  = aS0  + (u32)(buf * L1_ASZ * 2);
        const u32 bhS = bhS0 + (u32)(buf * L1_BSZ * 2);
#pragma unroll
        for (int ks = 0; ks < BK; ks += 16) {
            unsigned bh[4][2];
#pragma unroll
            for (int nt = 0; nt < 4; nt++) {
                u32 off = (u32)(((wn * 32 + nt * 8) * BKP + ks) * 2) + b_lane_off;
                ldsm_x2(bh[nt], bhS + off);
            }
#pragma unroll
            for (int mt = 0; mt < 4; mt++) {
                unsigned ah[4];
                u32 off = (u32)(((wm * 64 + mt * 16) * BKP + ks) * 2) + a_lane_off;
                ldsm_x4(ah, aS + off);
#pragma unroll
                for (int nt = 0; nt < 4; nt++)
                    mma16816fp(acc[mt][nt], ah, bh[nt]);
            }
        }
    };

    loadA(0);
    cpB(0, 0);
    for (int ch = 0; ch < nch; ch++) {
        cp_async_wait0();       // B(ch) landed (this thread's)
        stageA(ch & 1);         // A(ch): regs -> smem
        __syncthreads();        // all staging for buf(ch&1) visible
        if (ch + 1 < nch) {
            loadA((ch + 1) * BK);          // LDGs in flight during compute
            cpB((ch + 1) * BK, (ch + 1) & 1);
        }
        compute(ch & 1);
    }

    // Epilogue: write fp16 h1
#pragma unroll
    for (int mt = 0; mt < 4; mt++) {
        int r0 = m0 + wm * 64 + mt * 16 + quad;
#pragma unroll
        for (int nt = 0; nt < 4; nt++) {
            int cc = wn * 32 + nt * 8 + ql * 2;
            float* p = acc[mt][nt];
            if (r0 < M)
                *reinterpret_cast<__half2*>(s_h16 + (size_t)r0 * N + cc) =
                    __floats2half2_rn(p[0], p[1]);
            if (r0 + 8 < M)
                *reinterpret_cast<__half2*>(s_h16 + (size_t)(r0 + 8) * N + cc) =
                    __floats2half2_rn(p[2], p[3]);
        }
    }
}

// ---------------------------------------------------------------------------
// Generic split-bf16 3-pass GEMM (layers 2/3): A fp32 scratch, C -> fp16 h16.
// ---------------------------------------------------------------------------
#define BM 128

template <int AID, int BN, int T>
__global__ __launch_bounds__(T) void k_gemm_tc(
    const float* __restrict__ W, int M, int N, int K)
{
    const float* A = scratch<AID>();

    __shared__ __nv_bfloat16 Ahs[BM][BKP], Als[BM][BKP];
    __shared__ __nv_bfloat16 Bhs[BN][BKP], Bls[BN][BKP];

    const int tid = threadIdx.x;
    const int m0 = blockIdx.y * BM;
    const int n0 = blockIdx.x * BN;

    constexpr int NW_N = BN / 32;
    const int w = tid >> 5, lane = tid & 31;
    const int wm = w / NW_N, wn = w % NW_N;
    const int quad = lane >> 2, ql = lane & 3;

    constexpr int AF4 = (BM * BK / 4) / T;
    constexpr int WF4 = (BK * BN / 4) / T;
    constexpr int WF4PR = BN / 4;

    float4 aReg[AF4], wReg[WF4];
    float acc[4][4][4];
#pragma unroll
    for (int mt = 0; mt < 4; mt++)
#pragma unroll
        for (int nt = 0; nt < 4; nt++)
#pragma unroll
            for (int i = 0; i < 4; i++) acc[mt][nt][i] = 0.0f;

    const int nch = (K + BK - 1) / BK;

    auto loadA = [&](int k0) {
#pragma unroll
        for (int i = 0; i < AF4; i++) {
            int idx = tid + i * T;
            int r = idx >> 3, c4 = (idx & 7) * 4;
            int gm = m0 + r, gk = k0 + c4;
            float4 v = make_float4(0.f, 0.f, 0.f, 0.f);
            if (gm < M && gk + 3 < K)
                v = *reinterpret_cast<const float4*>(A + (size_t)gm * K + gk);
            aReg[i] = v;
        }
    };

    auto loadW = [&](int k0) {
#pragma unroll
        for (int i = 0; i < WF4; i++) {
            int idx = tid + i * T;
            int k = idx / WF4PR, c4 = (idx % WF4PR) * 4;
            int gk = k0 + k;
            float4 v = make_float4(0.f, 0.f, 0.f, 0.f);
            if (gk < K)
                v = *reinterpret_cast<const float4*>(W + (size_t)gk * N + n0 + c4);
            wReg[i] = v;
        }
    };

    auto stage = [&]() {
#pragma unroll
        for (int i = 0; i < AF4; i++) {
            int idx = tid + i * T;
            int r = idx >> 3, c = (idx & 7) * 4;
            float vv[4];
            vv[0] = aReg[i].x; vv[1] = aReg[i].y; vv[2] = aReg[i].z; vv[3] = aReg[i].w;
#pragma unroll
            for (int j = 0; j < 4; j += 2) {
                __nv_bfloat16 h0, l0, h1, l1;
                split_bf16(vv[j], h0, l0);
                split_bf16(vv[j + 1], h1, l1);
                __nv_bfloat162 hp; hp.x = h0; hp.y = h1;
                __nv_bfloat162 lp; lp.x = l0; lp.y = l1;
                *reinterpret_cast<__nv_bfloat162*>(&Ahs[r][c + j]) = hp;
                *reinterpret_cast<__nv_bfloat162*>(&Als[r][c + j]) = lp;
            }
        }
#pragma unroll
        for (int i = 0; i < WF4; i++) {
            int idx = tid + i * T;
            int k = idx / WF4PR, c = (idx % WF4PR) * 4;
            float vv[4];
            vv[0] = wReg[i].x; vv[1] = wReg[i].y; vv[2] = wReg[i].z; vv[3] = wReg[i].w;
#pragma unroll
            for (int j = 0; j < 4; j++) {
                __nv_bfloat16 h, l;
                split_bf16(vv[j], h, l);
                Bhs[c + j][k] = h;
                Bls[c + j][k] = l;
            }
        }
    };

    auto compute = [&]() {
#pragma unroll
        for (int ks = 0; ks < BK; ks += 16) {
            unsigned bh[4][2], bl[4][2];
#pragma unroll
            for (int nt = 0; nt < 4; nt++) {
                int nn = wn * 32 + nt * 8 + quad;
                int kk = ks + ql * 2;
                bh[nt][0] = *reinterpret_cast<const unsigned*>(&Bhs[nn][kk]);
                bh[nt][1] = *reinterpret_cast<const unsigned*>(&Bhs[nn][kk + 8]);
                bl[nt][0] = *reinterpret_cast<const unsigned*>(&Bls[nn][kk]);
                bl[nt][1] = *reinterpret_cast<const unsigned*>(&Bls[nn][kk + 8]);
            }
#pragma unroll
            for (int mt = 0; mt < 4; mt++) {
                int r = wm * 64 + mt * 16 + quad;
                int kk = ks + ql * 2;
                unsigned ah[4], al[4];
                ah[0] = *reinterpret_cast<const unsigned*>(&Ahs[r][kk]);
                ah[1] = *reinterpret_cast<const unsigned*>(&Ahs[r + 8][kk]);
                ah[2] = *reinterpret_cast<const unsigned*>(&Ahs[r][kk + 8]);
                ah[3] = *reinterpret_cast<const unsigned*>(&Ahs[r + 8][kk + 8]);
                al[0] = *reinterpret_cast<const unsigned*>(&Als[r][kk]);
                al[1] = *reinterpret_cast<const unsigned*>(&Als[r + 8][kk]);
                al[2] = *reinterpret_cast<const unsigned*>(&Als[r][kk + 8]);
                al[3] = *reinterpret_cast<const unsigned*>(&Als[r + 8][kk + 8]);
#pragma unroll
                for (int nt = 0; nt < 4; nt++) {
                    mma16816bf(acc[mt][nt], ah, bh[nt]);
                    mma16816bf(acc[mt][nt], ah, bl[nt]);
                    mma16816bf(acc[mt][nt], al, bh[nt]);
                }
            }
        }
    };

    loadA(0); loadW(0);
    for (int ch = 0; ch < nch; ch++) {
        __syncthreads();
        stage();
        __syncthreads();
        if (ch + 1 < nch) { loadA((ch + 1) * BK); loadW((ch + 1) * BK); }
        compute();
    }

    // Epilogue: write fp16 h
#pragma unroll
    for (int mt = 0; mt < 4; mt++) {
        int r0 = m0 + wm * 64 + mt * 16 + quad;
#pragma unroll
        for (int nt = 0; nt < 4; nt++) {
            int cc = n0 + wn * 32 + nt * 8 + ql * 2;
            float* p = acc[mt][nt];
            if (r0 < M)
                *reinterpret_cast<__half2*>(s_h16 + (size_t)r0 * N + cc) =
                    __floats2half2_rn(p[0], p[1]);
            if (r0 + 8 < M)
                *reinterpret_cast<__half2*>(s_h16 + (size_t)(r0 + 8) * N + cc) =
                    __floats2half2_rn(p[2], p[3]);
        }
    }
}

// ---------------------------------------------------------------------------
// Fused CSR aggregation (fp16 h -> fp32 g): one warp per dst node.
// ---------------------------------------------------------------------------
template <int GID, int F, bool RELU, bool HEAD>
__global__ __launch_bounds__(256) void k_aggregate(
    const float* __restrict__ bias,
    const float* __restrict__ Wl, const float* __restrict__ bl,
    float* __restrict__ out, int n)
{
    constexpr int RP = F / 64;

    int warp_in_block = threadIdx.x >> 5;
    int lane = threadIdx.x & 31;
    int node = blockIdx.x * (blockDim.x >> 5) + warp_in_block;
    if (node >= n) return;

    float d = s_dis[node];
    float dsq = d * d;

    float2 acc[RP];
    {
        const __half2* hrow = reinterpret_cast<const __half2*>(s_h16 + (size_t)node * F);
#pragma unroll
        for (int r = 0; r < RP; r++) {
            float2 f = __half22float2(hrow[lane + r * 32]);
            acc[r].x = f.x * dsq;
            acc[r].y = f.y * dsq;
        }
    }

    int beg = s_rowptr[node];
    int end = s_rowptr[node + 1];
    for (int e = beg; e < end; e++) {
        int src = s_csr_src[e];
        float wgt = s_csr_w[e];
        const __half2* hr = reinterpret_cast<const __half2*>(s_h16 + (size_t)src * F);
#pragma unroll
        for (int r = 0; r < RP; r++) {
            float2 f = __half22float2(hr[lane + r * 32]);
            acc[r].x = fmaf(f.x, wgt, acc[r].x);
            acc[r].y = fmaf(f.y, wgt, acc[r].y);
        }
    }

    const float2* b2 = reinterpret_cast<const float2*>(bias);
#pragma unroll
    for (int r = 0; r < RP; r++) {
        float2 bv = b2[lane + r * 32];
        acc[r].x += bv.x;
        acc[r].y += bv.y;
        if constexpr (RELU) {
            acc[r].x = fmaxf(acc[r].x, 0.0f);
            acc[r].y = fmaxf(acc[r].y, 0.0f);
        }
    }

    if constexpr (!HEAD) {
        float2* g2 = reinterpret_cast<float2*>(scratch<GID>() + (size_t)node * F);
#pragma unroll
        for (int r = 0; r < RP; r++)
            g2[lane + r * 32] = acc[r];
    } else {
        *reinterpret_cast<float2*>(out + (size_t)n + (size_t)node * 64 + lane * 2) = acc[0];
        float2 wv = reinterpret_cast<const float2*>(Wl)[lane];
        float ss = acc[0].x * wv.x + acc[0].y * wv.y;
#pragma unroll
        for (int o = 16; o; o >>= 1) ss += __shfl_xor_sync(0xFFFFFFFFu, ss, o);
        if (lane == 0)
            out[node] = 1.0f / (1.0f + expf(-(ss + bl[0])));
    }
}

// ---------------------------------------------------------------------------
static inline int cdiv(long long a, long long b) { return (int)((a + b - 1) / b); }

extern "C" void kernel_launch(void* const* d_in, const int* in_sizes, int n_in,
                              void* d_out, int out_size)
{
    const float* x   = (const float*)d_in[0];
    const void*  ei  = d_in[1];
    const float* W1  = (const float*)d_in[2];
    const float* b1  = (const float*)d_in[3];
    const float* W2  = (const float*)d_in[4];
    const float* b2  = (const float*)d_in[5];
    const float* W3  = (const float*)d_in[6];
    const float* b3  = (const float*)d_in[7];
    const float* Wl  = (const float*)d_in[8];
    const float* bl  = (const float*)d_in[9];
    float* out = (float*)d_out;

    const int n = in_sizes[0] / D0;    // 50000
    const int E = in_sizes[1] / 2;     // 1600000

    cudaFuncSetAttribute(k_gemm_l1, cudaFuncAttributeMaxDynamicSharedMemorySize,
                         L1_SMEM_BYTES);

    int scan_words = (2 * E < 4096) ? 2 * E : 4096;
    const int MT = cdiv(n, BM);           // 391
    const int AGG_BLOCKS = cdiv(n, 8);

    // k_gemm_l1 kept at stream launch index 3 (ncu sampling window).
    k_detect_dtype<<<1, 256>>>((const int*)ei, scan_words);                   // 0
    k_w1t<<<cdiv((long long)D1 * L1_KP, 256), 256>>>(W1);                     // 1
    k_deg_zero<<<cdiv(n, 256), 256>>>(n);                                     // 2
    k_gemm_l1<<<dim3(1, MT), 512, L1_SMEM_BYTES>>>(x, n);                     // 3
    k_deg_count<<<cdiv(E, 256), 256>>>(ei, E);                                // 4
    k_dis<<<cdiv(n, 256), 256>>>(n);                                          // 5
    k_scan<<<1, 1024>>>(n);                                                   // 6
    k_csr_fill<<<cdiv(E, 256), 256>>>(ei, E);                                 // 7

    // ---- Layer 1 agg: h16 -> g1 (bufA) (+b1, relu) ----
    k_aggregate<0, D1, true, false><<<AGG_BLOCKS, 256>>>(b1, nullptr, nullptr, nullptr, n);

    // ---- Layer 2: gemm g1(bufA)@W2 -> h16 ; agg -> g2 (bufB) ----
    k_gemm_tc<0, 128, 256><<<dim3(1, MT), 256>>>(W2, n, D2, D1);
    k_aggregate<1, D2, false, false><<<AGG_BLOCKS, 256>>>(b2, nullptr, nullptr, nullptr, n);

    // ---- Layer 3: gemm g2(bufB)@W3 -> h16 ; agg -> out (head fused) ----
    k_gemm_tc<1, 64, 128><<<dim3(1, MT), 128>>>(W3, n, D3, D2);
    k_aggregate<0, D3, false, true><<<AGG_BLOCKS, 256>>>(b3, Wl, bl, out, n);
}